// round 2
// baseline (speedup 1.0000x reference)
#include <cuda_runtime.h>
#include <cstdint>

// Problem constants (fixed instance)
#define BB   4
#define NN   8192
#define KK   16
#define CG   10
#define CIN  128
#define CN   128
#define CC   256
#define COUT 256
#define PP   (BB * NN)        // 32768 points
#define RR   (PP * KK)        // 524288 neighbor rows

// ---------------------------------------------------------------------------
// Scratch (static device memory; no runtime allocation)
// ---------------------------------------------------------------------------
__device__ float d_F1[(size_t)PP * CC];        // feature @ w_attn[:128,:]      (32 MB)
__device__ float d_FS[(size_t)PP * COUT];      // BN_s(feature @ w_s)           (32 MB)
__device__ float d_NB[(size_t)RR * CN];        // neigh = lrelu(BN(raw@w_n))    (256 MB)
__device__ float d_LB[(size_t)RR * CC];        // NB @ w_attn[128:,:]           (512 MB)
__device__ float d_PL[(size_t)PP * CC];        // attention-pooled features     (32 MB)
__device__ int   d_GI[RR];                     // batch-absolute gather indices  (2 MB)
__device__ int   d_idx64;                      // 1 if neighbors_idx is int64
// folded BN params: rows 0=s_n 1=t_n 2=s_o 3=t_o 4=s_s 5=t_s
__device__ float d_fold[6][256];

__device__ __forceinline__ float lrelu(float x) { return fmaxf(x, 0.2f * x); }

// ---------------------------------------------------------------------------
// Index dtype detection + conversion (robust to int32 vs int64 metadata)
// If the buffer holds little-endian int64 values < 2^31, every odd 32-bit
// word is 0. Random int32 indices in [0,8192) fail that test w.p. ~1.
// ---------------------------------------------------------------------------
__global__ void detect_idx_kernel(const int* __restrict__ w)
{
    __shared__ int ok;
    if (threadIdx.x == 0) ok = 1;
    __syncthreads();
    for (int i = threadIdx.x; i < 2048; i += blockDim.x)
        if (w[2 * i + 1] != 0) ok = 0;
    __syncthreads();
    if (threadIdx.x == 0) d_idx64 = ok;
}

__global__ void convert_idx_kernel(const void* __restrict__ nidx)
{
    int r = blockIdx.x * blockDim.x + threadIdx.x;
    if (r >= RR) return;
    long long v;
    if (d_idx64) v = ((const long long*)nidx)[r];
    else         v = (long long)((const int*)nidx)[r];
    int vi = (int)v;
    vi = min(max(vi, 0), NN - 1);               // clamp: never OOB
    int batch = r / (NN * KK);
    d_GI[r] = batch * NN + vi;
}

// ---------------------------------------------------------------------------
// Fold BN (+bias) into per-channel scale/shift:  bn(y+b) = y*s + t
// ---------------------------------------------------------------------------
__global__ void fold_kernel(
    const float* __restrict__ bn_, const float* __restrict__ gn,
    const float* __restrict__ betan, const float* __restrict__ rmn, const float* __restrict__ rvn,
    const float* __restrict__ bo, const float* __restrict__ go,
    const float* __restrict__ betao, const float* __restrict__ rmo, const float* __restrict__ rvo,
    const float* __restrict__ bs, const float* __restrict__ gs,
    const float* __restrict__ betas, const float* __restrict__ rms, const float* __restrict__ rvs)
{
    int i = threadIdx.x;
    if (i < CN) {
        float s = gn[i] * rsqrtf(rvn[i] + 1e-5f);
        d_fold[0][i] = s;
        d_fold[1][i] = (bn_[i] - rmn[i]) * s + betan[i];
    }
    if (i < COUT) {
        float s = go[i] * rsqrtf(rvo[i] + 1e-5f);
        d_fold[2][i] = s;
        d_fold[3][i] = (bo[i] - rmo[i]) * s + betao[i];
        float s2 = gs[i] * rsqrtf(rvs[i] + 1e-5f);
        d_fold[4][i] = s2;
        d_fold[5][i] = (bs[i] - rms[i]) * s2 + betas[i];
    }
}

// ---------------------------------------------------------------------------
// neigh: NB[r, c] = lrelu( (raw[r,:] @ w_n[:,c]) * s_n[c] + t_n[c] )
// ---------------------------------------------------------------------------
__global__ void neigh_kernel(const float* __restrict__ raw, const float* __restrict__ wn)
{
    int r = blockIdx.x * 2 + (threadIdx.x >> 7);
    int c = threadIdx.x & 127;
    const float* rr = raw + (size_t)r * CG;
    float acc = 0.f;
#pragma unroll
    for (int g = 0; g < CG; g++) acc += rr[g] * wn[g * CN + c];
    float v = acc * d_fold[0][c] + d_fold[1][c];
    d_NB[(size_t)r * CN + c] = lrelu(v);
}

// ---------------------------------------------------------------------------
// Tiled SGEMM: C[M,256] = A[M,Kd] @ Bm[Kd,256]   (all row-major)
// BM=128, BN=128, BK=8, 256 threads, 8x8 per thread, f32x2 packed FMAs.
// mode 0: C=acc   mode 1: C=acc*s+t   mode 2: C=lrelu(addend + acc*s+t)
// ---------------------------------------------------------------------------
__global__ __launch_bounds__(256, 2)
void gemm_kernel(const float* __restrict__ A, const float* __restrict__ Bm,
                 float* __restrict__ C, int M, int Kd,
                 const float* __restrict__ sv, const float* __restrict__ tv,
                 const float* __restrict__ addend, int mode)
{
    __shared__ __align__(16) float As[8][128];
    __shared__ __align__(16) float Bs[8][128];

    const int tid = threadIdx.x;
    const int tx = tid & 15;         // 16 threads across N
    const int ty = tid >> 4;         // 16 threads across M
    const int m0 = blockIdx.x * 128;
    const int n0 = blockIdx.y * 128;

    unsigned long long acc[8][4];
#pragma unroll
    for (int i = 0; i < 8; i++)
#pragma unroll
        for (int j = 0; j < 4; j++) acc[i][j] = 0ULL;

    const int aRow = tid >> 1;            // 0..127
    const int aK   = (tid & 1) * 4;       // 0 or 4
    const int bRow = tid >> 5;            // 0..7
    const int bC   = (tid & 31) * 4;      // 0..124

    for (int kt = 0; kt < Kd; kt += 8) {
        float4 av = *(const float4*)(A + (size_t)(m0 + aRow) * Kd + kt + aK);
        float4 bv = *(const float4*)(Bm + (size_t)(kt + bRow) * 256 + n0 + bC);
        As[aK + 0][aRow] = av.x;
        As[aK + 1][aRow] = av.y;
        As[aK + 2][aRow] = av.z;
        As[aK + 3][aRow] = av.w;
        *(float4*)&Bs[bRow][bC] = bv;
        __syncthreads();

#pragma unroll
        for (int kk = 0; kk < 8; kk++) {
            float4 a0 = *(const float4*)&As[kk][ty * 8];
            float4 a1 = *(const float4*)&As[kk][ty * 8 + 4];
            ulonglong2 b0 = *(const ulonglong2*)&Bs[kk][tx * 8];
            ulonglong2 b1 = *(const ulonglong2*)&Bs[kk][tx * 8 + 4];
            float af[8] = {a0.x, a0.y, a0.z, a0.w, a1.x, a1.y, a1.z, a1.w};
            unsigned long long bp[4] = {b0.x, b0.y, b1.x, b1.y};
#pragma unroll
            for (int i = 0; i < 8; i++) {
                unsigned long long ap;
                unsigned int au = __float_as_uint(af[i]);
                asm("mov.b64 %0, {%1,%2};" : "=l"(ap) : "r"(au), "r"(au));
#pragma unroll
                for (int j = 0; j < 4; j++)
                    asm("fma.rn.f32x2 %0, %1, %2, %0;"
                        : "+l"(acc[i][j]) : "l"(ap), "l"(bp[j]));
            }
        }
        __syncthreads();
    }

    // Epilogue
    float svr[8], tvr[8];
    if (mode != 0) {
#pragma unroll
        for (int j = 0; j < 8; j++) {
            svr[j] = sv[n0 + tx * 8 + j];
            tvr[j] = tv[n0 + tx * 8 + j];
        }
    }
#pragma unroll
    for (int i = 0; i < 8; i++) {
        int row = m0 + ty * 8 + i;
        float* crow = C + (size_t)row * 256 + n0 + tx * 8;
        float out[8];
#pragma unroll
        for (int j = 0; j < 4; j++) {
            float2 v = *reinterpret_cast<float2*>(&acc[i][j]);
            out[2 * j + 0] = v.x;
            out[2 * j + 1] = v.y;
        }
        if (mode == 1) {
#pragma unroll
            for (int j = 0; j < 8; j++) out[j] = out[j] * svr[j] + tvr[j];
        } else if (mode == 2) {
            const float* arow = addend + (size_t)row * 256 + n0 + tx * 8;
            float4 ad0 = *(const float4*)arow;
            float4 ad1 = *(const float4*)(arow + 4);
            float adf[8] = {ad0.x, ad0.y, ad0.z, ad0.w, ad1.x, ad1.y, ad1.z, ad1.w};
#pragma unroll
            for (int j = 0; j < 8; j++)
                out[j] = lrelu(adf[j] + out[j] * svr[j] + tvr[j]);
        }
        *(float4*)crow       = make_float4(out[0], out[1], out[2], out[3]);
        *(float4*)(crow + 4) = make_float4(out[4], out[5], out[6], out[7]);
    }
}

// ---------------------------------------------------------------------------
// Per-point: logits = LB + gather(F1), softmax over K per channel,
// attention-pool cat = [gathered_feature | NB]  ->  PL[p, 0:256]
// One CTA per point, thread j = channel.
// ---------------------------------------------------------------------------
__global__ void pool_kernel(const float* __restrict__ feat)
{
    const int p = blockIdx.x;
    const int j = threadIdx.x;
    const int* gi = d_GI + (size_t)p * KK;

    float l[KK];
    const float* lbp = d_LB + (size_t)p * KK * 256 + j;
#pragma unroll
    for (int k = 0; k < KK; k++)
        l[k] = lbp[(size_t)k * 256] + d_F1[(size_t)gi[k] * 256 + j];

    float m = l[0];
#pragma unroll
    for (int k = 1; k < KK; k++) m = fmaxf(m, l[k]);
    float s = 0.f;
#pragma unroll
    for (int k = 0; k < KK; k++) { l[k] = __expf(l[k] - m); s += l[k]; }
    float inv = __frcp_rn(s);

    float pooled = 0.f;
    if (j < 128) {
#pragma unroll
        for (int k = 0; k < KK; k++)
            pooled += l[k] * feat[(size_t)gi[k] * CIN + j];
    } else {
        const float* nbp = d_NB + (size_t)p * KK * CN + (j - 128);
#pragma unroll
        for (int k = 0; k < KK; k++)
            pooled += l[k] * nbp[(size_t)k * CN];
    }
    d_PL[(size_t)p * 256 + j] = pooled * inv;
}

// ---------------------------------------------------------------------------
// Launch
// ---------------------------------------------------------------------------
extern "C" void kernel_launch(void* const* d_in, const int* in_sizes, int n_in,
                              void* d_out, int out_size)
{
    const float* feature = (const float*)d_in[0];
    const float* raw     = (const float*)d_in[1];
    const void*  nidx    = d_in[2];
    const float* w_n     = (const float*)d_in[3];
    const float* b_n     = (const float*)d_in[4];
    const float* g_n     = (const float*)d_in[5];
    const float* beta_n  = (const float*)d_in[6];
    const float* rm_n    = (const float*)d_in[7];
    const float* rv_n    = (const float*)d_in[8];
    const float* w_attn  = (const float*)d_in[9];
    const float* w_o     = (const float*)d_in[10];
    const float* b_o     = (const float*)d_in[11];
    const float* g_o     = (const float*)d_in[12];
    const float* beta_o  = (const float*)d_in[13];
    const float* rm_o    = (const float*)d_in[14];
    const float* rv_o    = (const float*)d_in[15];
    const float* w_s     = (const float*)d_in[16];
    const float* b_s     = (const float*)d_in[17];
    const float* g_s     = (const float*)d_in[18];
    const float* beta_s  = (const float*)d_in[19];
    const float* rm_s    = (const float*)d_in[20];
    const float* rv_s    = (const float*)d_in[21];
    float* out = (float*)d_out;

    float *pF1, *pFS, *pNB, *pLB, *pPL, *pFold;
    cudaGetSymbolAddress((void**)&pF1, d_F1);
    cudaGetSymbolAddress((void**)&pFS, d_FS);
    cudaGetSymbolAddress((void**)&pNB, d_NB);
    cudaGetSymbolAddress((void**)&pLB, d_LB);
    cudaGetSymbolAddress((void**)&pPL, d_PL);
    cudaGetSymbolAddress((void**)&pFold, d_fold);

    fold_kernel<<<1, 256>>>(b_n, g_n, beta_n, rm_n, rv_n,
                            b_o, g_o, beta_o, rm_o, rv_o,
                            b_s, g_s, beta_s, rm_s, rv_s);
    detect_idx_kernel<<<1, 256>>>((const int*)nidx);
    convert_idx_kernel<<<(RR + 255) / 256, 256>>>(nidx);

    // F1 = feature @ w_attn_top   [32768,128]@[128,256]
    gemm_kernel<<<dim3(PP / 128, 2), 256>>>(feature, w_attn, pF1, PP, CIN,
                                            nullptr, nullptr, nullptr, 0);
    // FS = BN_s(feature @ w_s)
    gemm_kernel<<<dim3(PP / 128, 2), 256>>>(feature, w_s, pFS, PP, CIN,
                                            pFold + 4 * 256, pFold + 5 * 256, nullptr, 1);
    // NB = lrelu(BN_n(raw @ w_n))
    neigh_kernel<<<RR / 2, 256>>>(raw, w_n);
    // LB = NB @ w_attn_bot        [524288,128]@[128,256]  (dominant GEMM)
    gemm_kernel<<<dim3(RR / 128, 2), 256>>>(pNB, w_attn + 128 * 256, pLB, RR, CN,
                                            nullptr, nullptr, nullptr, 0);
    // gather + softmax + attention pooling -> PL
    pool_kernel<<<PP, 256>>>(feature);
    // out = lrelu(FS + BN_o(PL @ w_o))
    gemm_kernel<<<dim3(PP / 128, 2), 256>>>(pPL, w_o, out, PP, CC,
                                            pFold + 2 * 256, pFold + 3 * 256, pFS, 2);
}

// round 5
// speedup vs baseline: 1.3672x; 1.3672x over previous
#include <cuda_runtime.h>
#include <cuda_bf16.h>
#include <cstdint>

// Problem constants (fixed instance)
#define BB   4
#define NN   8192
#define KK   16
#define CG   10
#define CIN  128
#define CN   128
#define CC   256
#define COUT 256
#define PP   (BB * NN)        // 32768 points
#define RR   (PP * KK)        // 524288 neighbor rows
#define NTILES (RR / 128)     // 4096 M-tiles for the tensor GEMM

// ---------------------------------------------------------------------------
// Scratch (static device memory; no runtime allocation)
// ---------------------------------------------------------------------------
__device__ float d_F1[(size_t)PP * CC];            // feature @ w_attn[:128,:]
__device__ float d_FS[(size_t)PP * COUT];          // BN_s(feature @ w_s)
__device__ __nv_bfloat16 d_NBh[(size_t)RR * CN];   // neigh hi (bf16)
__device__ __nv_bfloat16 d_NBl[(size_t)RR * CN];   // neigh lo (bf16)
__device__ float d_LB[(size_t)RR * CC];            // NB @ w_attn[128:,:]
__device__ float d_PL[(size_t)PP * CC];            // attention-pooled features
__device__ __nv_bfloat16 d_Wth[256 * 128];         // w_attn_bot^T hi, [N=256][K=128]
__device__ __nv_bfloat16 d_Wtl[256 * 128];         // w_attn_bot^T lo
__device__ int   d_GI[RR];                         // batch-absolute gather indices
__device__ int   d_idx64;                          // 1 if neighbors_idx is int64
__device__ float d_fold[6][256];                   // folded BN: s_n t_n s_o t_o s_s t_s

__device__ __forceinline__ float lrelu(float x) { return fmaxf(x, 0.2f * x); }

// ---------------------------------------------------------------------------
// Index dtype detection + conversion (int32 vs int64 robust)
// ---------------------------------------------------------------------------
__global__ void detect_idx_kernel(const int* __restrict__ w)
{
    __shared__ int ok;
    if (threadIdx.x == 0) ok = 1;
    __syncthreads();
    for (int i = threadIdx.x; i < 2048; i += blockDim.x)
        if (w[2 * i + 1] != 0) ok = 0;
    __syncthreads();
    if (threadIdx.x == 0) d_idx64 = ok;
}

__global__ void convert_idx_kernel(const void* __restrict__ nidx)
{
    int r = blockIdx.x * blockDim.x + threadIdx.x;
    if (r >= RR) return;
    long long v;
    if (d_idx64) v = ((const long long*)nidx)[r];
    else         v = (long long)((const int*)nidx)[r];
    int vi = (int)v;
    vi = min(max(vi, 0), NN - 1);
    int batch = r / (NN * KK);
    d_GI[r] = batch * NN + vi;
}

// ---------------------------------------------------------------------------
// Fold BN (+bias) into per-channel scale/shift
// ---------------------------------------------------------------------------
__global__ void fold_kernel(
    const float* __restrict__ bn_, const float* __restrict__ gn,
    const float* __restrict__ betan, const float* __restrict__ rmn, const float* __restrict__ rvn,
    const float* __restrict__ bo, const float* __restrict__ go,
    const float* __restrict__ betao, const float* __restrict__ rmo, const float* __restrict__ rvo,
    const float* __restrict__ bs, const float* __restrict__ gs,
    const float* __restrict__ betas, const float* __restrict__ rms, const float* __restrict__ rvs)
{
    int i = threadIdx.x;
    if (i < CN) {
        float s = gn[i] * rsqrtf(rvn[i] + 1e-5f);
        d_fold[0][i] = s;
        d_fold[1][i] = (bn_[i] - rmn[i]) * s + betan[i];
    }
    if (i < COUT) {
        float s = go[i] * rsqrtf(rvo[i] + 1e-5f);
        d_fold[2][i] = s;
        d_fold[3][i] = (bo[i] - rmo[i]) * s + betao[i];
        float s2 = gs[i] * rsqrtf(rvs[i] + 1e-5f);
        d_fold[4][i] = s2;
        d_fold[5][i] = (bs[i] - rms[i]) * s2 + betas[i];
    }
}

// ---------------------------------------------------------------------------
// Wt prep: transpose + bf16 hi/lo split of w_attn[128:256, :]
// Wt[n][k] = w_attn[(128+k)*256 + n]
// ---------------------------------------------------------------------------
__global__ void prep_w_kernel(const float* __restrict__ w_attn)
{
    int i = blockIdx.x * blockDim.x + threadIdx.x;   // i = n*128 + k
    if (i >= 256 * 128) return;
    int n = i >> 7, k = i & 127;
    float v = w_attn[(size_t)(128 + k) * 256 + n];
    __nv_bfloat16 hi = __float2bfloat16(v);
    __nv_bfloat16 lo = __float2bfloat16(v - __bfloat162float(hi));
    d_Wth[i] = hi;
    d_Wtl[i] = lo;
}

// ---------------------------------------------------------------------------
// neigh: NB = lrelu(BN(raw @ w_n)) stored as bf16 hi/lo pair
// ---------------------------------------------------------------------------
__global__ void neigh_kernel(const float* __restrict__ raw, const float* __restrict__ wn)
{
    int r = blockIdx.x * 2 + (threadIdx.x >> 7);
    int c = threadIdx.x & 127;
    const float* rr = raw + (size_t)r * CG;
    float acc = 0.f;
#pragma unroll
    for (int g = 0; g < CG; g++) acc += rr[g] * wn[g * CN + c];
    float v = lrelu(acc * d_fold[0][c] + d_fold[1][c]);
    __nv_bfloat16 hi = __float2bfloat16(v);
    __nv_bfloat16 lo = __float2bfloat16(v - __bfloat162float(hi));
    size_t o = (size_t)r * CN + c;
    d_NBh[o] = hi;
    d_NBl[o] = lo;
}

// ---------------------------------------------------------------------------
// HMMA GEMM: LB[RR,256] = (NBh+NBl)[RR,128] @ W^T  (3-pass bf16 split)
// Persistent: grid = 296 (148 tiles-stride x 2 N-halves), 256 threads (8 warps).
// Each CTA: its 128-col half of W (hi+lo) resident in smem; loops M-tiles.
// Warp tile 32x64; mma.sync.m16n8k16 row.col bf16->fp32.
// Smem layout (pad stride 136 bf16 = 272B -> conflict-free frags).
// ---------------------------------------------------------------------------
#define SA 136
#define OFF_WH 0
#define OFF_WL (128 * 272)
#define OFF_AH (2 * 128 * 272)
#define OFF_AL (3 * 128 * 272)
#define LB_SMEM (4 * 128 * 272)            // 139264 bytes

__global__ __launch_bounds__(256, 1) void lb_hmma_kernel()
{
    extern __shared__ __align__(16) char sm[];
    __nv_bfloat16* WH = (__nv_bfloat16*)(sm + OFF_WH);
    __nv_bfloat16* WL = (__nv_bfloat16*)(sm + OFF_WL);
    __nv_bfloat16* AH = (__nv_bfloat16*)(sm + OFF_AH);
    __nv_bfloat16* AL = (__nv_bfloat16*)(sm + OFF_AL);

    const int tid  = threadIdx.x;
    const int wid  = tid >> 5, lane = tid & 31;
    const int wm   = wid >> 1, wn = wid & 1;     // warp grid 4(M) x 2(N)
    const int g    = lane >> 2, tg = lane & 3;
    const int half = blockIdx.x & 1;             // which 128-col half of N=256

    // Load W half (hi+lo) once: 128 rows x 128 bf16 = 2048 uint4 each
    for (int lin = tid; lin < 2048; lin += 256) {
        int row = lin >> 4, ch = lin & 15;
        uint4 vh = ((const uint4*)d_Wth)[(size_t)(half * 128 + row) * 16 + ch];
        uint4 vl = ((const uint4*)d_Wtl)[(size_t)(half * 128 + row) * 16 + ch];
        *(uint4*)((char*)WH + row * 272 + ch * 16) = vh;
        *(uint4*)((char*)WL + row * 272 + ch * 16) = vl;
    }
    __syncthreads();

    for (int tile = blockIdx.x >> 1; tile < NTILES; tile += 148) {
        // Load A tile (128 rows x 128 bf16 = 2048 uint4, hi + lo)
        const size_t abase = (size_t)tile * 2048;   // uint4 index
        for (int lin = tid; lin < 2048; lin += 256) {
            int row = lin >> 4, ch = lin & 15;
            uint4 vh = ((const uint4*)d_NBh)[abase + lin];
            uint4 vl = ((const uint4*)d_NBl)[abase + lin];
            *(uint4*)((char*)AH + row * 272 + ch * 16) = vh;
            *(uint4*)((char*)AL + row * 272 + ch * 16) = vl;
        }
        __syncthreads();

        float acc[2][8][4];
#pragma unroll
        for (int i = 0; i < 2; i++)
#pragma unroll
            for (int j = 0; j < 8; j++)
#pragma unroll
                for (int c = 0; c < 4; c++) acc[i][j][c] = 0.f;

#pragma unroll
        for (int p = 0; p < 3; p++) {               // hh, hl, lh
            const __nv_bfloat16* Ab = (p == 2) ? AL : AH;
            const __nv_bfloat16* Bb = (p == 1) ? WL : WH;
#pragma unroll
            for (int ks = 0; ks < 8; ks++) {
                const int k0 = ks * 16;
                uint32_t a[2][4], b[8][2];
#pragma unroll
                for (int i = 0; i < 2; i++) {
                    const __nv_bfloat16* ar = Ab + (wm * 32 + i * 16 + g) * SA + k0 + 2 * tg;
                    a[i][0] = *(const uint32_t*)(ar);
                    a[i][1] = *(const uint32_t*)(ar + 8 * SA);
                    a[i][2] = *(const uint32_t*)(ar + 8);
                    a[i][3] = *(const uint32_t*)(ar + 8 * SA + 8);
                }
#pragma unroll
                for (int j = 0; j < 8; j++) {
                    const __nv_bfloat16* br = Bb + (wn * 64 + j * 8 + g) * SA + k0 + 2 * tg;
                    b[j][0] = *(const uint32_t*)(br);
                    b[j][1] = *(const uint32_t*)(br + 8);
                }
#pragma unroll
                for (int i = 0; i < 2; i++)
#pragma unroll
                    for (int j = 0; j < 8; j++)
                        asm volatile(
                            "mma.sync.aligned.m16n8k16.row.col.f32.bf16.bf16.f32 "
                            "{%0,%1,%2,%3}, {%4,%5,%6,%7}, {%8,%9}, {%0,%1,%2,%3};"
                            : "+f"(acc[i][j][0]), "+f"(acc[i][j][1]),
                              "+f"(acc[i][j][2]), "+f"(acc[i][j][3])
                            : "r"(a[i][0]), "r"(a[i][1]), "r"(a[i][2]), "r"(a[i][3]),
                              "r"(b[j][0]), "r"(b[j][1]));
            }
        }

        // Epilogue: write 128x128 fp32 block
#pragma unroll
        for (int i = 0; i < 2; i++) {
            const int row0 = tile * 128 + wm * 32 + i * 16 + g;
#pragma unroll
            for (int j = 0; j < 8; j++) {
                const int col = half * 128 + wn * 64 + j * 8 + 2 * tg;
                *(float2*)(d_LB + (size_t)row0 * 256 + col) =
                    make_float2(acc[i][j][0], acc[i][j][1]);
                *(float2*)(d_LB + (size_t)(row0 + 8) * 256 + col) =
                    make_float2(acc[i][j][2], acc[i][j][3]);
            }
        }
        __syncthreads();
    }
}

// ---------------------------------------------------------------------------
// Scalar tiled SGEMM (small GEMMs): C[M,256] = A[M,Kd] @ Bm[Kd,256]
// mode 0: C=acc   mode 1: C=acc*s+t   mode 2: C=lrelu(addend + acc*s+t)
// ---------------------------------------------------------------------------
__global__ __launch_bounds__(256, 2)
void gemm_kernel(const float* __restrict__ A, const float* __restrict__ Bm,
                 float* __restrict__ C, int M, int Kd,
                 const float* __restrict__ sv, const float* __restrict__ tv,
                 const float* __restrict__ addend, int mode)
{
    __shared__ __align__(16) float As[8][128];
    __shared__ __align__(16) float Bs[8][128];

    const int tid = threadIdx.x;
    const int tx = tid & 15;
    const int ty = tid >> 4;
    const int m0 = blockIdx.x * 128;
    const int n0 = blockIdx.y * 128;

    unsigned long long acc[8][4];
#pragma unroll
    for (int i = 0; i < 8; i++)
#pragma unroll
        for (int j = 0; j < 4; j++) acc[i][j] = 0ULL;

    const int aRow = tid >> 1;
    const int aK   = (tid & 1) * 4;
    const int bRow = tid >> 5;
    const int bC   = (tid & 31) * 4;

    for (int kt = 0; kt < Kd; kt += 8) {
        float4 av = *(const float4*)(A + (size_t)(m0 + aRow) * Kd + kt + aK);
        float4 bv = *(const float4*)(Bm + (size_t)(kt + bRow) * 256 + n0 + bC);
        As[aK + 0][aRow] = av.x;
        As[aK + 1][aRow] = av.y;
        As[aK + 2][aRow] = av.z;
        As[aK + 3][aRow] = av.w;
        *(float4*)&Bs[bRow][bC] = bv;
        __syncthreads();

#pragma unroll
        for (int kk = 0; kk < 8; kk++) {
            float4 a0 = *(const float4*)&As[kk][ty * 8];
            float4 a1 = *(const float4*)&As[kk][ty * 8 + 4];
            ulonglong2 b0 = *(const ulonglong2*)&Bs[kk][tx * 8];
            ulonglong2 b1 = *(const ulonglong2*)&Bs[kk][tx * 8 + 4];
            float af[8] = {a0.x, a0.y, a0.z, a0.w, a1.x, a1.y, a1.z, a1.w};
            unsigned long long bp[4] = {b0.x, b0.y, b1.x, b1.y};
#pragma unroll
            for (int i = 0; i < 8; i++) {
                unsigned long long ap;
                unsigned int au = __float_as_uint(af[i]);
                asm("mov.b64 %0, {%1,%2};" : "=l"(ap) : "r"(au), "r"(au));
#pragma unroll
                for (int j = 0; j < 4; j++)
                    asm("fma.rn.f32x2 %0, %1, %2, %0;"
                        : "+l"(acc[i][j]) : "l"(ap), "l"(bp[j]));
            }
        }
        __syncthreads();
    }

    float svr[8], tvr[8];
    if (mode != 0) {
#pragma unroll
        for (int j = 0; j < 8; j++) {
            svr[j] = sv[n0 + tx * 8 + j];
            tvr[j] = tv[n0 + tx * 8 + j];
        }
    }
#pragma unroll
    for (int i = 0; i < 8; i++) {
        int row = m0 + ty * 8 + i;
        float* crow = C + (size_t)row * 256 + n0 + tx * 8;
        float out[8];
#pragma unroll
        for (int j = 0; j < 4; j++) {
            float2 v = *reinterpret_cast<float2*>(&acc[i][j]);
            out[2 * j + 0] = v.x;
            out[2 * j + 1] = v.y;
        }
        if (mode == 1) {
#pragma unroll
            for (int j = 0; j < 8; j++) out[j] = out[j] * svr[j] + tvr[j];
        } else if (mode == 2) {
            const float* arow = addend + (size_t)row * 256 + n0 + tx * 8;
            float4 ad0 = *(const float4*)arow;
            float4 ad1 = *(const float4*)(arow + 4);
            float adf[8] = {ad0.x, ad0.y, ad0.z, ad0.w, ad1.x, ad1.y, ad1.z, ad1.w};
#pragma unroll
            for (int j = 0; j < 8; j++)
                out[j] = lrelu(adf[j] + out[j] * svr[j] + tvr[j]);
        }
        *(float4*)crow       = make_float4(out[0], out[1], out[2], out[3]);
        *(float4*)(crow + 4) = make_float4(out[4], out[5], out[6], out[7]);
    }
}

// ---------------------------------------------------------------------------
// Per-point pooling: logits = LB + gather(F1); channelwise softmax over K;
// pooled = sum_k attn * cat  where cat = [gathered feature | NB(hi+lo)]
// ---------------------------------------------------------------------------
__global__ void pool_kernel(const float* __restrict__ feat)
{
    const int p = blockIdx.x;
    const int j = threadIdx.x;
    const int* gi = d_GI + (size_t)p * KK;

    float l[KK];
    const float* lbp = d_LB + (size_t)p * KK * 256 + j;
#pragma unroll
    for (int k = 0; k < KK; k++)
        l[k] = lbp[(size_t)k * 256] + d_F1[(size_t)gi[k] * 256 + j];

    float m = l[0];
#pragma unroll
    for (int k = 1; k < KK; k++) m = fmaxf(m, l[k]);
    float s = 0.f;
#pragma unroll
    for (int k = 0; k < KK; k++) { l[k] = __expf(l[k] - m); s += l[k]; }
    float inv = __frcp_rn(s);

    float pooled = 0.f;
    if (j < 128) {
#pragma unroll
        for (int k = 0; k < KK; k++)
            pooled += l[k] * feat[(size_t)gi[k] * CIN + j];
    } else {
        const size_t nbo = (size_t)p * KK * CN + (j - 128);
#pragma unroll
        for (int k = 0; k < KK; k++) {
            float nb = __bfloat162float(d_NBh[nbo + (size_t)k * CN]) +
                       __bfloat162float(d_NBl[nbo + (size_t)k * CN]);
            pooled += l[k] * nb;
        }
    }
    d_PL[(size_t)p * 256 + j] = pooled * inv;
}

// ---------------------------------------------------------------------------
// Launch
// ---------------------------------------------------------------------------
extern "C" void kernel_launch(void* const* d_in, const int* in_sizes, int n_in,
                              void* d_out, int out_size)
{
    const float* feature = (const float*)d_in[0];
    const float* raw     = (const float*)d_in[1];
    const void*  nidx    = d_in[2];
    const float* w_n     = (const float*)d_in[3];
    const float* b_n     = (const float*)d_in[4];
    const float* g_n     = (const float*)d_in[5];
    const float* beta_n  = (const float*)d_in[6];
    const float* rm_n    = (const float*)d_in[7];
    const float* rv_n    = (const float*)d_in[8];
    const float* w_attn  = (const float*)d_in[9];
    const float* w_o     = (const float*)d_in[10];
    const float* b_o     = (const float*)d_in[11];
    const float* g_o     = (const float*)d_in[12];
    const float* beta_o  = (const float*)d_in[13];
    const float* rm_o    = (const float*)d_in[14];
    const float* rv_o    = (const float*)d_in[15];
    const float* w_s     = (const float*)d_in[16];
    const float* b_s     = (const float*)d_in[17];
    const float* g_s     = (const float*)d_in[18];
    const float* beta_s  = (const float*)d_in[19];
    const float* rm_s    = (const float*)d_in[20];
    const float* rv_s    = (const float*)d_in[21];
    float* out = (float*)d_out;

    float *pF1, *pFS, *pPL, *pFold;
    cudaGetSymbolAddress((void**)&pF1, d_F1);
    cudaGetSymbolAddress((void**)&pFS, d_FS);
    cudaGetSymbolAddress((void**)&pPL, d_PL);
    cudaGetSymbolAddress((void**)&pFold, d_fold);

    cudaFuncSetAttribute(lb_hmma_kernel,
                         cudaFuncAttributeMaxDynamicSharedMemorySize, LB_SMEM);

    fold_kernel<<<1, 256>>>(b_n, g_n, beta_n, rm_n, rv_n,
                            b_o, g_o, beta_o, rm_o, rv_o,
                            b_s, g_s, beta_s, rm_s, rv_s);
    detect_idx_kernel<<<1, 256>>>((const int*)nidx);
    convert_idx_kernel<<<(RR + 255) / 256, 256>>>(nidx);
    prep_w_kernel<<<128, 256>>>(w_attn);

    // F1 = feature @ w_attn_top
    gemm_kernel<<<dim3(PP / 128, 2), 256>>>(feature, w_attn, pF1, PP, CIN,
                                            nullptr, nullptr, nullptr, 0);
    // FS = BN_s(feature @ w_s)
    gemm_kernel<<<dim3(PP / 128, 2), 256>>>(feature, w_s, pFS, PP, CIN,
                                            pFold + 4 * 256, pFold + 5 * 256, nullptr, 1);
    // NB (bf16 hi/lo) = lrelu(BN_n(raw @ w_n))
    neigh_kernel<<<RR / 2, 256>>>(raw, w_n);
    // LB = NB @ w_attn_bot  — HMMA bf16-split, persistent
    lb_hmma_kernel<<<296, 256, LB_SMEM>>>();
    // gather + softmax + attention pooling -> PL
    pool_kernel<<<PP, 256>>>(feature);
    // out = lrelu(FS + BN_o(PL @ w_o))
    gemm_kernel<<<dim3(PP / 128, 2), 256>>>(pPL, w_o, out, PP, CC,
                                            pFold + 2 * 256, pFold + 3 * 256, pFS, 2);
}

// round 6
// speedup vs baseline: 1.4091x; 1.0307x over previous
#include <cuda_runtime.h>
#include <cuda_bf16.h>
#include <cstdint>

// Problem constants (fixed instance)
#define BB   4
#define NN   8192
#define KK   16
#define CG   10
#define CIN  128
#define PP   (BB * NN)        // 32768 points
#define RR   (PP * KK)        // 524288 neighbor rows
#define NTILES (RR / 128)     // 4096 M-tiles

// ---------------------------------------------------------------------------
// Scratch (static device memory)
// ---------------------------------------------------------------------------
__device__ float d_F1[(size_t)PP * 256];           // feature @ w_attn_top (fp32)
__device__ float d_FS[(size_t)PP * 256];           // BN_s(feature @ w_s)
__device__ __nv_bfloat16 d_NBh[(size_t)RR * 128];  // neigh hi
__device__ __nv_bfloat16 d_NBl[(size_t)RR * 128];  // neigh lo
__device__ __nv_bfloat16 d_Fh[(size_t)PP * 128];   // feature hi
__device__ __nv_bfloat16 d_Fl[(size_t)PP * 128];   // feature lo
__device__ __nv_bfloat16 d_PLh[(size_t)PP * 256];  // pooled hi
__device__ __nv_bfloat16 d_PLl[(size_t)PP * 256];  // pooled lo
__device__ __nv_bfloat16 d_Wth[256 * 128], d_Wtl[256 * 128];  // w_attn_bot^T
__device__ __nv_bfloat16 d_WAh[256 * 128], d_WAl[256 * 128];  // w_attn_top^T
__device__ __nv_bfloat16 d_WSh[256 * 128], d_WSl[256 * 128];  // w_s^T
__device__ __nv_bfloat16 d_WOh[256 * 256], d_WOl[256 * 256];  // w_o^T
__device__ int   d_GI[RR];
__device__ int   d_idx64;
__device__ float d_fold[6][256];   // s_n t_n s_o t_o s_s t_s

__device__ __forceinline__ float lrelu(float x) { return fmaxf(x, 0.2f * x); }

// ---------------------------------------------------------------------------
// Index dtype detection + conversion
// ---------------------------------------------------------------------------
__global__ void detect_idx_kernel(const int* __restrict__ w)
{
    __shared__ int ok;
    if (threadIdx.x == 0) ok = 1;
    __syncthreads();
    for (int i = threadIdx.x; i < 2048; i += blockDim.x)
        if (w[2 * i + 1] != 0) ok = 0;
    __syncthreads();
    if (threadIdx.x == 0) d_idx64 = ok;
}

__global__ void convert_idx_kernel(const void* __restrict__ nidx)
{
    int r = blockIdx.x * blockDim.x + threadIdx.x;
    if (r >= RR) return;
    long long v;
    if (d_idx64) v = ((const long long*)nidx)[r];
    else         v = (long long)((const int*)nidx)[r];
    int vi = (int)v;
    vi = min(max(vi, 0), NN - 1);
    int batch = r / (NN * KK);
    d_GI[r] = batch * NN + vi;
}

// ---------------------------------------------------------------------------
// Fold BN (+bias) into per-channel scale/shift
// ---------------------------------------------------------------------------
__global__ void fold_kernel(
    const float* __restrict__ bn_, const float* __restrict__ gn,
    const float* __restrict__ betan, const float* __restrict__ rmn, const float* __restrict__ rvn,
    const float* __restrict__ bo, const float* __restrict__ go,
    const float* __restrict__ betao, const float* __restrict__ rmo, const float* __restrict__ rvo,
    const float* __restrict__ bs, const float* __restrict__ gs,
    const float* __restrict__ betas, const float* __restrict__ rms, const float* __restrict__ rvs)
{
    int i = threadIdx.x;
    if (i < 128) {
        float s = gn[i] * rsqrtf(rvn[i] + 1e-5f);
        d_fold[0][i] = s;
        d_fold[1][i] = (bn_[i] - rmn[i]) * s + betan[i];
    }
    if (i < 256) {
        float s = go[i] * rsqrtf(rvo[i] + 1e-5f);
        d_fold[2][i] = s;
        d_fold[3][i] = (bo[i] - rmo[i]) * s + betao[i];
        float s2 = gs[i] * rsqrtf(rvs[i] + 1e-5f);
        d_fold[4][i] = s2;
        d_fold[5][i] = (bs[i] - rms[i]) * s2 + betas[i];
    }
}

// ---------------------------------------------------------------------------
// Weight transpose + bf16 hi/lo split: T[n][k] = W[(rowOff+k)*N + n], T is [Nw][Kw]
// ---------------------------------------------------------------------------
__global__ void split_wt_kernel(const float* __restrict__ W,
                                __nv_bfloat16* __restrict__ Th,
                                __nv_bfloat16* __restrict__ Tl,
                                int Kw, int Nw, int rowOff)
{
    int i = blockIdx.x * blockDim.x + threadIdx.x;
    if (i >= Nw * Kw) return;
    int n = i / Kw, k = i % Kw;
    float v = W[(size_t)(rowOff + k) * Nw + n];
    __nv_bfloat16 hi = __float2bfloat16(v);
    Th[i] = hi;
    Tl[i] = __float2bfloat16(v - __bfloat162float(hi));
}

// feature -> bf16 hi/lo
__global__ void split_feat_kernel(const float* __restrict__ f)
{
    int i = blockIdx.x * blockDim.x + threadIdx.x;
    if (i >= PP * CIN) return;
    float v = f[i];
    __nv_bfloat16 hi = __float2bfloat16(v);
    d_Fh[i] = hi;
    d_Fl[i] = __float2bfloat16(v - __bfloat162float(hi));
}

// ---------------------------------------------------------------------------
// neigh: NB = lrelu(BN(raw @ w_n)) stored as bf16 hi/lo
// ---------------------------------------------------------------------------
__global__ void neigh_kernel(const float* __restrict__ raw, const float* __restrict__ wn)
{
    int r = blockIdx.x * 2 + (threadIdx.x >> 7);
    int c = threadIdx.x & 127;
    const float* rr = raw + (size_t)r * CG;
    float acc = 0.f;
#pragma unroll
    for (int g = 0; g < CG; g++) acc += rr[g] * wn[g * 128 + c];
    float v = lrelu(acc * d_fold[0][c] + d_fold[1][c]);
    __nv_bfloat16 hi = __float2bfloat16(v);
    __nv_bfloat16 lo = __float2bfloat16(v - __bfloat162float(hi));
    size_t o = (size_t)r * 128 + c;
    d_NBh[o] = hi;
    d_NBl[o] = lo;
}

// ---------------------------------------------------------------------------
// Shared warp-tile MMA: 3-pass bf16 split over a 128x128(K) tile pair in smem.
// smem rows padded to SA=136 bf16 (272B). acc: warp tile 32(M) x 64(N).
// ---------------------------------------------------------------------------
#define SA 136
__device__ __forceinline__ void mma_tile(
    const __nv_bfloat16* AH, const __nv_bfloat16* AL,
    const __nv_bfloat16* WH, const __nv_bfloat16* WL,
    int wm, int wn, int g, int tg, float (&acc)[2][8][4])
{
#pragma unroll
    for (int p = 0; p < 3; p++) {               // hh, hl, lh
        const __nv_bfloat16* Ab = (p == 2) ? AL : AH;
        const __nv_bfloat16* Bb = (p == 1) ? WL : WH;
#pragma unroll
        for (int ks = 0; ks < 8; ks++) {
            const int k0 = ks * 16;
            uint32_t a[2][4], b[8][2];
#pragma unroll
            for (int i = 0; i < 2; i++) {
                const __nv_bfloat16* ar = Ab + (wm * 32 + i * 16 + g) * SA + k0 + 2 * tg;
                a[i][0] = *(const uint32_t*)(ar);
                a[i][1] = *(const uint32_t*)(ar + 8 * SA);
                a[i][2] = *(const uint32_t*)(ar + 8);
                a[i][3] = *(const uint32_t*)(ar + 8 * SA + 8);
            }
#pragma unroll
            for (int j = 0; j < 8; j++) {
                const __nv_bfloat16* br = Bb + (wn * 64 + j * 8 + g) * SA + k0 + 2 * tg;
                b[j][0] = *(const uint32_t*)(br);
                b[j][1] = *(const uint32_t*)(br + 8);
            }
#pragma unroll
            for (int i = 0; i < 2; i++)
#pragma unroll
                for (int j = 0; j < 8; j++)
                    asm volatile(
                        "mma.sync.aligned.m16n8k16.row.col.f32.bf16.bf16.f32 "
                        "{%0,%1,%2,%3}, {%4,%5,%6,%7}, {%8,%9}, {%0,%1,%2,%3};"
                        : "+f"(acc[i][j][0]), "+f"(acc[i][j][1]),
                          "+f"(acc[i][j][2]), "+f"(acc[i][j][3])
                        : "r"(a[i][0]), "r"(a[i][1]), "r"(a[i][2]), "r"(a[i][3]),
                          "r"(b[j][0]), "r"(b[j][1]));
        }
    }
}

// ---------------------------------------------------------------------------
// Generic HMMA GEMM: C[M,256] = (Ah+Al)[M,Kd] @ (Wh+Wl)^T, W stored [256][Kd].
// grid (M/128, 2), 256 threads. Kd in {128, 256} (K-chunked by 128).
// mode 0: C=acc   mode 1: C=acc*s+t   mode 2: C=lrelu(addend + acc*s+t)
// ---------------------------------------------------------------------------
#define G_SMEM (4 * 128 * 272)   // 139264
__global__ __launch_bounds__(256, 1)
void hmma_gemm(const __nv_bfloat16* __restrict__ Ah, const __nv_bfloat16* __restrict__ Al,
               const __nv_bfloat16* __restrict__ Wh, const __nv_bfloat16* __restrict__ Wl,
               float* __restrict__ C, int Kd, int mode,
               const float* __restrict__ sv, const float* __restrict__ tv,
               const float* __restrict__ addend)
{
    extern __shared__ __align__(16) char sm[];
    __nv_bfloat16* WH = (__nv_bfloat16*)(sm);
    __nv_bfloat16* WL = (__nv_bfloat16*)(sm + 34816);
    __nv_bfloat16* AH = (__nv_bfloat16*)(sm + 69632);
    __nv_bfloat16* AL = (__nv_bfloat16*)(sm + 104448);

    const int tid = threadIdx.x;
    const int wid = tid >> 5, lane = tid & 31;
    const int wm = wid >> 1, wn = wid & 1;
    const int g = lane >> 2, tg = lane & 3;
    const int m0 = blockIdx.x * 128;
    const int half = blockIdx.y;
    const int rowU4 = Kd >> 3;   // uint4 per row

    float acc[2][8][4];
#pragma unroll
    for (int i = 0; i < 2; i++)
#pragma unroll
        for (int j = 0; j < 8; j++)
#pragma unroll
            for (int c = 0; c < 4; c++) acc[i][j][c] = 0.f;

    for (int kt = 0; kt < (Kd >> 7); kt++) {
        if (kt > 0) __syncthreads();
        for (int lin = tid; lin < 2048; lin += 256) {
            int row = lin >> 4, ch = lin & 15;
            size_t wi = (size_t)(half * 128 + row) * rowU4 + kt * 16 + ch;
            size_t ai = (size_t)(m0 + row) * rowU4 + kt * 16 + ch;
            *(uint4*)((char*)WH + row * 272 + ch * 16) = ((const uint4*)Wh)[wi];
            *(uint4*)((char*)WL + row * 272 + ch * 16) = ((const uint4*)Wl)[wi];
            *(uint4*)((char*)AH + row * 272 + ch * 16) = ((const uint4*)Ah)[ai];
            *(uint4*)((char*)AL + row * 272 + ch * 16) = ((const uint4*)Al)[ai];
        }
        __syncthreads();
        mma_tile(AH, AL, WH, WL, wm, wn, g, tg, acc);
    }

    // Epilogue
#pragma unroll
    for (int i = 0; i < 2; i++) {
        const int row0 = m0 + wm * 32 + i * 16 + g;
#pragma unroll
        for (int j = 0; j < 8; j++) {
            const int col = half * 128 + wn * 64 + j * 8 + 2 * tg;
            float2 v0 = make_float2(acc[i][j][0], acc[i][j][1]);
            float2 v1 = make_float2(acc[i][j][2], acc[i][j][3]);
            if (mode >= 1) {
                float s0 = sv[col], s1 = sv[col + 1];
                float t0 = tv[col], t1 = tv[col + 1];
                v0.x = v0.x * s0 + t0; v0.y = v0.y * s1 + t1;
                v1.x = v1.x * s0 + t0; v1.y = v1.y * s1 + t1;
                if (mode == 2) {
                    float2 a0 = *(const float2*)(addend + (size_t)row0 * 256 + col);
                    float2 a1 = *(const float2*)(addend + (size_t)(row0 + 8) * 256 + col);
                    v0.x = lrelu(a0.x + v0.x); v0.y = lrelu(a0.y + v0.y);
                    v1.x = lrelu(a1.x + v1.x); v1.y = lrelu(a1.y + v1.y);
                }
            }
            *(float2*)(C + (size_t)row0 * 256 + col) = v0;
            *(float2*)(C + (size_t)(row0 + 8) * 256 + col) = v1;
        }
    }
}

// ---------------------------------------------------------------------------
// Fused LB GEMM + softmax + attention pooling. Persistent, grid=296.
// Per (tile, half): HMMA 128x128, +F1 gather, softmax over K per channel,
// pool with cat (feat gather for half 0, smem NB for half 1) -> PL (bf16 hi/lo).
// smem: W 69632 | A 69632 (Ftile overlays for half 0) | Ctile 67584 | gi 512
// ---------------------------------------------------------------------------
#define LBF_C   139264
#define LBF_GI  206848
#define LBF_TOT 207360
#define CSA 132   // Ctile/Ftile stride in floats (528B, 16B aligned)

__global__ __launch_bounds__(256, 1) void lb_fused_kernel(const float* __restrict__ feat)
{
    extern __shared__ __align__(16) char sm[];
    __nv_bfloat16* WH = (__nv_bfloat16*)(sm);
    __nv_bfloat16* WL = (__nv_bfloat16*)(sm + 34816);
    __nv_bfloat16* AH = (__nv_bfloat16*)(sm + 69632);
    __nv_bfloat16* AL = (__nv_bfloat16*)(sm + 104448);
    float* Ct = (float*)(sm + LBF_C);
    float* Ft = (float*)(sm + 69632);         // overlays AH/AL (half 0 only)
    int*   sgi = (int*)(sm + LBF_GI);

    const int tid = threadIdx.x;
    const int wid = tid >> 5, lane = tid & 31;
    const int wm = wid >> 1, wn = wid & 1;
    const int g = lane >> 2, tg = lane & 3;
    const int half = blockIdx.x & 1;

    // W half resident
    for (int lin = tid; lin < 2048; lin += 256) {
        int row = lin >> 4, ch = lin & 15;
        size_t wi = (size_t)(half * 128 + row) * 16 + ch;
        *(uint4*)((char*)WH + row * 272 + ch * 16) = ((const uint4*)d_Wth)[wi];
        *(uint4*)((char*)WL + row * 272 + ch * 16) = ((const uint4*)d_Wtl)[wi];
    }
    __syncthreads();

    for (int tile = blockIdx.x >> 1; tile < NTILES; tile += 148) {
        // A tile (NB hi/lo) + gather indices
        const size_t abase = (size_t)tile * 2048;
        for (int lin = tid; lin < 2048; lin += 256) {
            int row = lin >> 4, ch = lin & 15;
            *(uint4*)((char*)AH + row * 272 + ch * 16) = ((const uint4*)d_NBh)[abase + lin];
            *(uint4*)((char*)AL + row * 272 + ch * 16) = ((const uint4*)d_NBl)[abase + lin];
        }
        if (tid < 128) sgi[tid] = d_GI[tile * 128 + tid];
        __syncthreads();

        float acc[2][8][4];
#pragma unroll
        for (int i = 0; i < 2; i++)
#pragma unroll
            for (int j = 0; j < 8; j++)
#pragma unroll
                for (int c = 0; c < 4; c++) acc[i][j][c] = 0.f;

        mma_tile(AH, AL, WH, WL, wm, wn, g, tg, acc);

        // acc -> Ctile (local cols 0..127)
#pragma unroll
        for (int i = 0; i < 2; i++) {
            const int r0 = wm * 32 + i * 16 + g;
#pragma unroll
            for (int j = 0; j < 8; j++) {
                const int c = wn * 64 + j * 8 + 2 * tg;
                *(float2*)(Ct + r0 * CSA + c) = make_float2(acc[i][j][0], acc[i][j][1]);
                *(float2*)(Ct + (r0 + 8) * CSA + c) = make_float2(acc[i][j][2], acc[i][j][3]);
            }
        }
        __syncthreads();

        // += F1 gather; stage feat gather (half 0)
        const float4* F1v = (const float4*)d_F1;
        const float4* ftv = (const float4*)feat;
#pragma unroll
        for (int ii = 0; ii < 16; ii++) {
            int lin = tid + 256 * ii;          // 0..4095
            int r = lin >> 5, c4 = lin & 31;
            int gi = sgi[r];
            float4 f1 = F1v[(size_t)gi * 64 + half * 32 + c4];
            float4* cp = (float4*)(Ct + r * CSA) + c4;
            float4 cv = *cp;
            cv.x += f1.x; cv.y += f1.y; cv.z += f1.z; cv.w += f1.w;
            *cp = cv;
            if (half == 0)
                ((float4*)(Ft + r * CSA))[c4] = ftv[(size_t)gi * 32 + c4];
        }
        __syncthreads();

        // softmax over K per channel + pool
        const int pt = tid >> 5, lt = tid & 31;
        const float* ctp = Ct + pt * 16 * CSA;
#pragma unroll
        for (int c = 0; c < 4; c++) {
            const int ch = lt + 32 * c;
            float l[KK];
#pragma unroll
            for (int k = 0; k < KK; k++) l[k] = ctp[k * CSA + ch];
            float m = l[0];
#pragma unroll
            for (int k = 1; k < KK; k++) m = fmaxf(m, l[k]);
            float s = 0.f;
#pragma unroll
            for (int k = 0; k < KK; k++) { l[k] = __expf(l[k] - m); s += l[k]; }
            float inv = __frcp_rn(s);

            float pooled = 0.f;
            if (half == 0) {
                const float* fp = Ft + pt * 16 * CSA + ch;
#pragma unroll
                for (int k = 0; k < KK; k++) pooled += l[k] * fp[k * CSA];
            } else {
                const __nv_bfloat16* ah = AH + (pt * 16) * SA + ch;
                const __nv_bfloat16* al = AL + (pt * 16) * SA + ch;
#pragma unroll
                for (int k = 0; k < KK; k++)
                    pooled += l[k] * (__bfloat162float(ah[k * SA]) +
                                      __bfloat162float(al[k * SA]));
            }
            pooled *= inv;
            size_t o = (size_t)(tile * 8 + pt) * 256 + half * 128 + ch;
            __nv_bfloat16 hi = __float2bfloat16(pooled);
            d_PLh[o] = hi;
            d_PLl[o] = __float2bfloat16(pooled - __bfloat162float(hi));
        }
        __syncthreads();
    }
}

// ---------------------------------------------------------------------------
// Launch
// ---------------------------------------------------------------------------
extern "C" void kernel_launch(void* const* d_in, const int* in_sizes, int n_in,
                              void* d_out, int out_size)
{
    const float* feature = (const float*)d_in[0];
    const float* raw     = (const float*)d_in[1];
    const void*  nidx    = d_in[2];
    const float* w_n     = (const float*)d_in[3];
    const float* b_n     = (const float*)d_in[4];
    const float* g_n     = (const float*)d_in[5];
    const float* beta_n  = (const float*)d_in[6];
    const float* rm_n    = (const float*)d_in[7];
    const float* rv_n    = (const float*)d_in[8];
    const float* w_attn  = (const float*)d_in[9];
    const float* w_o     = (const float*)d_in[10];
    const float* b_o     = (const float*)d_in[11];
    const float* g_o     = (const float*)d_in[12];
    const float* beta_o  = (const float*)d_in[13];
    const float* rm_o    = (const float*)d_in[14];
    const float* rv_o    = (const float*)d_in[15];
    const float* w_s     = (const float*)d_in[16];
    const float* b_s     = (const float*)d_in[17];
    const float* g_s     = (const float*)d_in[18];
    const float* beta_s  = (const float*)d_in[19];
    const float* rm_s    = (const float*)d_in[20];
    const float* rv_s    = (const float*)d_in[21];
    float* out = (float*)d_out;

    float *pF1, *pFS, *pFold;
    __nv_bfloat16 *pWth, *pWtl, *pWAh, *pWAl, *pWSh, *pWSl, *pWOh, *pWOl;
    __nv_bfloat16 *pFh, *pFl, *pPLh, *pPLl;
    cudaGetSymbolAddress((void**)&pF1, d_F1);
    cudaGetSymbolAddress((void**)&pFS, d_FS);
    cudaGetSymbolAddress((void**)&pFold, d_fold);
    cudaGetSymbolAddress((void**)&pWth, d_Wth);
    cudaGetSymbolAddress((void**)&pWtl, d_Wtl);
    cudaGetSymbolAddress((void**)&pWAh, d_WAh);
    cudaGetSymbolAddress((void**)&pWAl, d_WAl);
    cudaGetSymbolAddress((void**)&pWSh, d_WSh);
    cudaGetSymbolAddress((void**)&pWSl, d_WSl);
    cudaGetSymbolAddress((void**)&pWOh, d_WOh);
    cudaGetSymbolAddress((void**)&pWOl, d_WOl);
    cudaGetSymbolAddress((void**)&pFh, d_Fh);
    cudaGetSymbolAddress((void**)&pFl, d_Fl);
    cudaGetSymbolAddress((void**)&pPLh, d_PLh);
    cudaGetSymbolAddress((void**)&pPLl, d_PLl);

    cudaFuncSetAttribute(hmma_gemm, cudaFuncAttributeMaxDynamicSharedMemorySize, G_SMEM);
    cudaFuncSetAttribute(lb_fused_kernel, cudaFuncAttributeMaxDynamicSharedMemorySize, LBF_TOT);

    fold_kernel<<<1, 256>>>(b_n, g_n, beta_n, rm_n, rv_n,
                            b_o, g_o, beta_o, rm_o, rv_o,
                            b_s, g_s, beta_s, rm_s, rv_s);
    detect_idx_kernel<<<1, 256>>>((const int*)nidx);
    convert_idx_kernel<<<(RR + 255) / 256, 256>>>(nidx);

    split_wt_kernel<<<128, 256>>>(w_attn, pWth, pWtl, 128, 256, 128);  // w_attn_bot^T
    split_wt_kernel<<<128, 256>>>(w_attn, pWAh, pWAl, 128, 256, 0);    // w_attn_top^T
    split_wt_kernel<<<128, 256>>>(w_s,    pWSh, pWSl, 128, 256, 0);    // w_s^T
    split_wt_kernel<<<256, 256>>>(w_o,    pWOh, pWOl, 256, 256, 0);    // w_o^T
    split_feat_kernel<<<(PP * CIN + 255) / 256, 256>>>(feature);

    // NB (bf16 hi/lo) = lrelu(BN_n(raw @ w_n))
    neigh_kernel<<<RR / 2, 256>>>(raw, w_n);

    // F1 = feature @ w_attn_top  (fp32 out)
    hmma_gemm<<<dim3(PP / 128, 2), 256, G_SMEM>>>(pFh, pFl, pWAh, pWAl, pF1,
                                                  128, 0, nullptr, nullptr, nullptr);
    // FS = BN_s(feature @ w_s)
    hmma_gemm<<<dim3(PP / 128, 2), 256, G_SMEM>>>(pFh, pFl, pWSh, pWSl, pFS,
                                                  128, 1, pFold + 4 * 256, pFold + 5 * 256, nullptr);
    // Fused: LB GEMM + gather + softmax + pool -> PL (bf16 hi/lo)
    lb_fused_kernel<<<296, 256, LBF_TOT>>>(feature);

    // out = lrelu(FS + BN_o(PL @ w_o))
    hmma_gemm<<<dim3(PP / 128, 2), 256, G_SMEM>>>(pPLh, pPLl, pWOh, pWOl, out,
                                                  256, 2, pFold + 2 * 256, pFold + 3 * 256, pFS);
}

// round 7
// speedup vs baseline: 1.7408x; 1.2353x over previous
#include <cuda_runtime.h>
#include <cuda_bf16.h>
#include <cstdint>

// Problem constants (fixed instance)
#define BB   4
#define NN   8192
#define KK   16
#define CG   10
#define CIN  128
#define PP   (BB * NN)        // 32768 points
#define RR   (PP * KK)        // 524288 neighbor rows
#define NTILES (RR / 128)     // 4096 M-tiles

// ---------------------------------------------------------------------------
// Scratch (static device memory)
// ---------------------------------------------------------------------------
__device__ float d_F1[(size_t)PP * 256];           // feature @ w_attn_top (fp32)
__device__ float d_FS[(size_t)PP * 256];           // BN_s(feature @ w_s)
__device__ __nv_bfloat16 d_Fh[(size_t)PP * 128];   // feature hi
__device__ __nv_bfloat16 d_Fl[(size_t)PP * 128];   // feature lo
__device__ __nv_bfloat16 d_PLh[(size_t)PP * 256];  // pooled hi
__device__ __nv_bfloat16 d_PLl[(size_t)PP * 256];  // pooled lo
__device__ __nv_bfloat16 d_Wth[256 * 128], d_Wtl[256 * 128];  // w_attn_bot^T
__device__ __nv_bfloat16 d_WAh[256 * 128], d_WAl[256 * 128];  // w_attn_top^T
__device__ __nv_bfloat16 d_WSh[256 * 128], d_WSl[256 * 128];  // w_s^T
__device__ __nv_bfloat16 d_WOh[256 * 256], d_WOl[256 * 256];  // w_o^T
__device__ int   d_GI[RR];
__device__ int   d_idx64;
__device__ float d_fold[6][256];   // s_n t_n s_o t_o s_s t_s

__device__ __forceinline__ float lrelu(float x) { return fmaxf(x, 0.2f * x); }

// ---------------------------------------------------------------------------
// PTX helpers
// ---------------------------------------------------------------------------
__device__ __forceinline__ uint32_t smem_u32(const void* p) {
    uint32_t a;
    asm("{ .reg .u64 t; cvta.to.shared.u64 t, %1; cvt.u32.u64 %0, t; }" : "=r"(a) : "l"(p));
    return a;
}
__device__ __forceinline__ void ldsm_x4(uint32_t& r0, uint32_t& r1, uint32_t& r2,
                                        uint32_t& r3, uint32_t addr) {
    asm volatile("ldmatrix.sync.aligned.m8n8.x4.shared.b16 {%0,%1,%2,%3}, [%4];"
                 : "=r"(r0), "=r"(r1), "=r"(r2), "=r"(r3) : "r"(addr));
}
#define CP16(dst, src)  asm volatile("cp.async.cg.shared.global [%0], [%1], 16;" :: "r"(dst), "l"(src))
#define CP_COMMIT()     asm volatile("cp.async.commit_group;" ::: "memory")
#define CP_WAIT(n)      asm volatile("cp.async.wait_group %0;" :: "n"(n) : "memory")

// ---------------------------------------------------------------------------
// Launch 0: fold BN (block 0) + index dtype detect (block 1)
// ---------------------------------------------------------------------------
__global__ void foldetect_kernel(
    const float* __restrict__ bn_, const float* __restrict__ gn,
    const float* __restrict__ betan, const float* __restrict__ rmn, const float* __restrict__ rvn,
    const float* __restrict__ bo, const float* __restrict__ go,
    const float* __restrict__ betao, const float* __restrict__ rmo, const float* __restrict__ rvo,
    const float* __restrict__ bs, const float* __restrict__ gs,
    const float* __restrict__ betas, const float* __restrict__ rms, const float* __restrict__ rvs,
    const int* __restrict__ widx)
{
    if (blockIdx.x == 1) {
        __shared__ int ok;
        if (threadIdx.x == 0) ok = 1;
        __syncthreads();
        for (int i = threadIdx.x; i < 2048; i += blockDim.x)
            if (widx[2 * i + 1] != 0) ok = 0;
        __syncthreads();
        if (threadIdx.x == 0) d_idx64 = ok;
        return;
    }
    int i = threadIdx.x;
    if (i < 128) {
        float s = gn[i] * rsqrtf(rvn[i] + 1e-5f);
        d_fold[0][i] = s;
        d_fold[1][i] = (bn_[i] - rmn[i]) * s + betan[i];
    }
    if (i < 256) {
        float s = go[i] * rsqrtf(rvo[i] + 1e-5f);
        d_fold[2][i] = s;
        d_fold[3][i] = (bo[i] - rmo[i]) * s + betao[i];
        float s2 = gs[i] * rsqrtf(rvs[i] + 1e-5f);
        d_fold[4][i] = s2;
        d_fold[5][i] = (bs[i] - rms[i]) * s2 + betas[i];
    }
}

// Launch 1: index conversion
__global__ void convert_idx_kernel(const void* __restrict__ nidx)
{
    int r = blockIdx.x * blockDim.x + threadIdx.x;
    if (r >= RR) return;
    long long v;
    if (d_idx64) v = ((const long long*)nidx)[r];
    else         v = (long long)((const int*)nidx)[r];
    int vi = (int)v;
    vi = min(max(vi, 0), NN - 1);
    int batch = r / (NN * KK);
    d_GI[r] = batch * NN + vi;
}

// ---------------------------------------------------------------------------
// Launch 2: all weight transposes + bf16 hi/lo splits + feature split
// ---------------------------------------------------------------------------
__global__ void prep_all_kernel(const float* __restrict__ w_attn,
                                const float* __restrict__ w_s,
                                const float* __restrict__ w_o,
                                const float* __restrict__ feat)
{
    int b = blockIdx.x, t = threadIdx.x;
    if (b < 384) {                               // 128x256 transposed splits
        int i = (b & 127) * 256 + t;             // i = n*128 + k
        int n = i >> 7, k = i & 127;
        float v;
        __nv_bfloat16 *Th, *Tl;
        if (b < 128)      { v = w_attn[(size_t)k * 256 + n];         Th = d_WAh; Tl = d_WAl; }
        else if (b < 256) { v = w_s[(size_t)k * 256 + n];            Th = d_WSh; Tl = d_WSl; }
        else              { v = w_attn[(size_t)(128 + k) * 256 + n]; Th = d_Wth; Tl = d_Wtl; }
        __nv_bfloat16 hi = __float2bfloat16(v);
        Th[i] = hi;
        Tl[i] = __float2bfloat16(v - __bfloat162float(hi));
    } else if (b < 640) {                        // w_o^T 256x256
        int i = (b - 384) * 256 + t;             // i = n*256 + k
        int n = i >> 8, k = i & 255;
        float v = w_o[(size_t)k * 256 + n];
        __nv_bfloat16 hi = __float2bfloat16(v);
        d_WOh[i] = hi;
        d_WOl[i] = __float2bfloat16(v - __bfloat162float(hi));
    } else {                                     // feature split
        int i = (b - 640) * 256 + t;
        float v = feat[i];
        __nv_bfloat16 hi = __float2bfloat16(v);
        d_Fh[i] = hi;
        d_Fl[i] = __float2bfloat16(v - __bfloat162float(hi));
    }
}

// ---------------------------------------------------------------------------
// Warp-tile MMA via ldmatrix: 3-pass bf16 split over 128x128(K) tile in smem.
// smem rows: stride 272 bytes (136 bf16). Warp tile 32(M) x 64(N).
// ---------------------------------------------------------------------------
#define SA 136
__device__ __forceinline__ void mma_tile(
    uint32_t aAH, uint32_t aAL, uint32_t aWH, uint32_t aWL,
    int wm, int wn, int lane, float (&acc)[2][8][4])
{
    const int ri = lane & 7, mi = lane >> 3;
    const uint32_t aoff = (uint32_t)((wm * 32 + (mi & 1) * 8 + ri) * 272 + (mi >> 1) * 16);
    const uint32_t boff = (uint32_t)((wn * 64 + (mi >> 1) * 8 + ri) * 272 + (mi & 1) * 16);
#pragma unroll
    for (int p = 0; p < 3; p++) {               // hh, hl, lh
        const uint32_t Ab = ((p == 2) ? aAL : aAH) + aoff;
        const uint32_t Bb = ((p == 1) ? aWL : aWH) + boff;
#pragma unroll
        for (int ks = 0; ks < 8; ks++) {
            const uint32_t k2 = ks * 32;
            uint32_t a[2][4], b[8][2];
            ldsm_x4(a[0][0], a[0][1], a[0][2], a[0][3], Ab + k2);
            ldsm_x4(a[1][0], a[1][1], a[1][2], a[1][3], Ab + 16 * 272 + k2);
#pragma unroll
            for (int q = 0; q < 4; q++)
                ldsm_x4(b[2 * q][0], b[2 * q][1], b[2 * q + 1][0], b[2 * q + 1][1],
                        Bb + q * 16 * 272 + k2);
#pragma unroll
            for (int i = 0; i < 2; i++)
#pragma unroll
                for (int j = 0; j < 8; j++)
                    asm volatile(
                        "mma.sync.aligned.m16n8k16.row.col.f32.bf16.bf16.f32 "
                        "{%0,%1,%2,%3}, {%4,%5,%6,%7}, {%8,%9}, {%0,%1,%2,%3};"
                        : "+f"(acc[i][j][0]), "+f"(acc[i][j][1]),
                          "+f"(acc[i][j][2]), "+f"(acc[i][j][3])
                        : "r"(a[i][0]), "r"(a[i][1]), "r"(a[i][2]), "r"(a[i][3]),
                          "r"(b[j][0]), "r"(b[j][1]));
        }
    }
}

// ---------------------------------------------------------------------------
// Generic HMMA GEMM: C[M,256] = (Ah+Al)[M,Kd] @ (Wh+Wl)^T, W stored [256][Kd].
// mode 0: C=acc   mode 1: C=acc*s+t   mode 2: C=lrelu(addend + acc*s+t)
// ---------------------------------------------------------------------------
#define G_SMEM (4 * 128 * 272)
__global__ __launch_bounds__(256, 1)
void hmma_gemm(const __nv_bfloat16* __restrict__ Ah, const __nv_bfloat16* __restrict__ Al,
               const __nv_bfloat16* __restrict__ Wh, const __nv_bfloat16* __restrict__ Wl,
               float* __restrict__ C, int Kd, int mode,
               const float* __restrict__ sv, const float* __restrict__ tv,
               const float* __restrict__ addend)
{
    extern __shared__ __align__(16) char sm[];
    const uint32_t sb = smem_u32(sm);
    const uint32_t aWH = sb, aWL = sb + 34816, aAH = sb + 69632, aAL = sb + 104448;

    const int tid = threadIdx.x;
    const int wid = tid >> 5, lane = tid & 31;
    const int wm = wid >> 1, wn = wid & 1;
    const int g = lane >> 2, tg = lane & 3;
    const int m0 = blockIdx.x * 128;
    const int half = blockIdx.y;
    const int rowU4 = Kd >> 3;

    float acc[2][8][4];
#pragma unroll
    for (int i = 0; i < 2; i++)
#pragma unroll
        for (int j = 0; j < 8; j++)
#pragma unroll
            for (int c = 0; c < 4; c++) acc[i][j][c] = 0.f;

    for (int kt = 0; kt < (Kd >> 7); kt++) {
        if (kt > 0) __syncthreads();
        for (int lin = tid; lin < 2048; lin += 256) {
            int row = lin >> 4, ch = lin & 15;
            size_t wi = (size_t)(half * 128 + row) * rowU4 + kt * 16 + ch;
            size_t ai = (size_t)(m0 + row) * rowU4 + kt * 16 + ch;
            uint32_t so = row * 272u + ch * 16u;
            CP16(aWH + so, (const char*)Wh + wi * 16);
            CP16(aWL + so, (const char*)Wl + wi * 16);
            CP16(aAH + so, (const char*)Ah + ai * 16);
            CP16(aAL + so, (const char*)Al + ai * 16);
        }
        CP_COMMIT();
        CP_WAIT(0);
        __syncthreads();
        mma_tile(aAH, aAL, aWH, aWL, wm, wn, lane, acc);
    }

#pragma unroll
    for (int i = 0; i < 2; i++) {
        const int row0 = m0 + wm * 32 + i * 16 + g;
#pragma unroll
        for (int j = 0; j < 8; j++) {
            const int col = half * 128 + wn * 64 + j * 8 + 2 * tg;
            float2 v0 = make_float2(acc[i][j][0], acc[i][j][1]);
            float2 v1 = make_float2(acc[i][j][2], acc[i][j][3]);
            if (mode >= 1) {
                float s0 = sv[col], s1 = sv[col + 1];
                float t0 = tv[col], t1 = tv[col + 1];
                v0.x = v0.x * s0 + t0; v0.y = v0.y * s1 + t1;
                v1.x = v1.x * s0 + t0; v1.y = v1.y * s1 + t1;
                if (mode == 2) {
                    float2 a0 = *(const float2*)(addend + (size_t)row0 * 256 + col);
                    float2 a1 = *(const float2*)(addend + (size_t)(row0 + 8) * 256 + col);
                    v0.x = lrelu(a0.x + v0.x); v0.y = lrelu(a0.y + v0.y);
                    v1.x = lrelu(a1.x + v1.x); v1.y = lrelu(a1.y + v1.y);
                }
            }
            *(float2*)(C + (size_t)row0 * 256 + col) = v0;
            *(float2*)(C + (size_t)(row0 + 8) * 256 + col) = v1;
        }
    }
}

// ---------------------------------------------------------------------------
// Fused: NB compute + LB GEMM + F1 add + softmax + pooling. grid=296.
// smem: WH 0 | WL 34816 | AH 69632 | AL 104448 (Ft overlays AH for half0)
//       Ct 139264 (128x132 fp32) | raw 206848 (5120B)
// ---------------------------------------------------------------------------
#define CSA 132
#define FZ_WH  0
#define FZ_WL  34816
#define FZ_AH  69632
#define FZ_AL  104448
#define FZ_CT  139264
#define FZ_RAW 206848
#define FZ_TOT 211968

__global__ __launch_bounds__(256, 1)
void lb_fused_kernel(const float* __restrict__ feat, const float* __restrict__ raw,
                     const float* __restrict__ wn_)
{
    extern __shared__ __align__(16) char sm[];
    const uint32_t sb = smem_u32(sm);
    __nv_bfloat16* AH = (__nv_bfloat16*)(sm + FZ_AH);
    __nv_bfloat16* AL = (__nv_bfloat16*)(sm + FZ_AL);
    float* Ct = (float*)(sm + FZ_CT);
    float* Ft = (float*)(sm + FZ_AH);
    const float* raws = (const float*)(sm + FZ_RAW);

    const int tid = threadIdx.x;
    const int wid = tid >> 5, lane = tid & 31;
    const int wm = wid >> 1, wn = wid & 1;
    const int g = lane >> 2, tg = lane & 3;
    const int half = blockIdx.x & 1;

    // per-thread NB constants (column fixed per thread)
    const int cch = tid & 127;
    const int rhi = tid >> 7;
    float wcol[CG];
#pragma unroll
    for (int q = 0; q < CG; q++) wcol[q] = wn_[q * 128 + cch];
    const float sc = d_fold[0][cch], tc = d_fold[1][cch];

    // W half resident
    for (int lin = tid; lin < 2048; lin += 256) {
        int row = lin >> 4, ch = lin & 15;
        size_t wi = (size_t)(half * 128 + row) * 16 + ch;
        uint32_t so = row * 272u + ch * 16u;
        CP16(sb + FZ_WH + so, (const char*)d_Wth + wi * 16);
        CP16(sb + FZ_WL + so, (const char*)d_Wtl + wi * 16);
    }
    CP_COMMIT();
    CP_WAIT(0);
    __syncthreads();

    for (int tile = blockIdx.x >> 1; tile < NTILES; tile += 148) {
        __syncthreads();   // prev pool done before overwriting raw/Ct

        // async: raw tile (5KB), then F1 gather -> Ct
        const char* rawg = (const char*)raw + (size_t)tile * 5120;
        for (int i = tid; i < 320; i += 256)
            CP16(sb + FZ_RAW + i * 16, rawg + i * 16);
        CP_COMMIT();
        const char* F1c = (const char*)d_F1;
#pragma unroll
        for (int ii = 0; ii < 16; ii++) {
            int lin = tid + 256 * ii;
            int r = lin >> 5, c4 = lin & 31;
            int gi = d_GI[tile * 128 + r];
            CP16(sb + FZ_CT + r * 528 + c4 * 16,
                 F1c + (size_t)gi * 1024 + half * 512 + c4 * 16);
        }
        CP_COMMIT();
        CP_WAIT(1);        // raw arrived (F1 may still fly)
        __syncthreads();

        // NB compute: 128x128, each thread owns column cch, rows 2*ii+rhi
#pragma unroll 8
        for (int ii = 0; ii < 64; ii++) {
            int r = ii * 2 + rhi;
            float a = 0.f;
#pragma unroll
            for (int q = 0; q < CG; q++) a += wcol[q] * raws[r * CG + q];
            float v = lrelu(a * sc + tc);
            __nv_bfloat16 hi = __float2bfloat16(v);
            AH[r * SA + cch] = hi;
            AL[r * SA + cch] = __float2bfloat16(v - __bfloat162float(hi));
        }
        __syncthreads();

        float acc[2][8][4];
#pragma unroll
        for (int i = 0; i < 2; i++)
#pragma unroll
            for (int j = 0; j < 8; j++)
#pragma unroll
                for (int c = 0; c < 4; c++) acc[i][j][c] = 0.f;

        mma_tile(sb + FZ_AH, sb + FZ_AL, sb + FZ_WH, sb + FZ_WL, wm, wn, lane, acc);

        CP_WAIT(0);        // F1 in Ct
        __syncthreads();

        // feat gather for half 0 (into Ft, overlays AH/AL — mma done)
        if (half == 0) {
            const char* fc = (const char*)feat;
#pragma unroll
            for (int ii = 0; ii < 16; ii++) {
                int lin = tid + 256 * ii;
                int r = lin >> 5, c4 = lin & 31;
                int gi = d_GI[tile * 128 + r];
                CP16(sb + FZ_AH + r * 528 + c4 * 16, fc + (size_t)gi * 512 + c4 * 16);
            }
            CP_COMMIT();
        }

        // epilogue: Ct += acc (Ct holds F1 rows)
#pragma unroll
        for (int i = 0; i < 2; i++) {
            const int r0 = wm * 32 + i * 16 + g;
#pragma unroll
            for (int j = 0; j < 8; j++) {
                const int c = wn * 64 + j * 8 + 2 * tg;
                float2* p0 = (float2*)(Ct + r0 * CSA + c);
                float2* p1 = (float2*)(Ct + (r0 + 8) * CSA + c);
                float2 v0 = *p0, v1 = *p1;
                v0.x += acc[i][j][0]; v0.y += acc[i][j][1];
                v1.x += acc[i][j][2]; v1.y += acc[i][j][3];
                *p0 = v0; *p1 = v1;
            }
        }
        if (half == 0) CP_WAIT(0);
        __syncthreads();

        // softmax over K per channel + pool
        const int pt = tid >> 5, lt = tid & 31;
        const float* ctp = Ct + pt * 16 * CSA;
#pragma unroll
        for (int c = 0; c < 4; c++) {
            const int ch = lt + 32 * c;
            float l[KK];
#pragma unroll
            for (int k = 0; k < KK; k++) l[k] = ctp[k * CSA + ch];
            float m = l[0];
#pragma unroll
            for (int k = 1; k < KK; k++) m = fmaxf(m, l[k]);
            float s = 0.f;
#pragma unroll
            for (int k = 0; k < KK; k++) { l[k] = __expf(l[k] - m); s += l[k]; }
            float inv = __frcp_rn(s);

            float pooled = 0.f;
            if (half == 0) {
                const float* fp = Ft + pt * 16 * CSA + ch;
#pragma unroll
                for (int k = 0; k < KK; k++) pooled += l[k] * fp[k * CSA];
            } else {
                const __nv_bfloat16* ah = AH + (pt * 16) * SA + ch;
                const __nv_bfloat16* al = AL + (pt * 16) * SA + ch;
#pragma unroll
                for (int k = 0; k < KK; k++)
                    pooled += l[k] * (__bfloat162float(ah[k * SA]) +
                                      __bfloat162float(al[k * SA]));
            }
            pooled *= inv;
            size_t o = (size_t)(tile * 8 + pt) * 256 + half * 128 + ch;
            __nv_bfloat16 hi = __float2bfloat16(pooled);
            d_PLh[o] = hi;
            d_PLl[o] = __float2bfloat16(pooled - __bfloat162float(hi));
        }
    }
}

// ---------------------------------------------------------------------------
// Launch (order matters: lb_fused must be launch index 5 for ncu -s 5 -c 1)
// ---------------------------------------------------------------------------
extern "C" void kernel_launch(void* const* d_in, const int* in_sizes, int n_in,
                              void* d_out, int out_size)
{
    const float* feature = (const float*)d_in[0];
    const float* raw     = (const float*)d_in[1];
    const void*  nidx    = d_in[2];
    const float* w_n     = (const float*)d_in[3];
    const float* b_n     = (const float*)d_in[4];
    const float* g_n     = (const float*)d_in[5];
    const float* beta_n  = (const float*)d_in[6];
    const float* rm_n    = (const float*)d_in[7];
    const float* rv_n    = (const float*)d_in[8];
    const float* w_attn  = (const float*)d_in[9];
    const float* w_o     = (const float*)d_in[10];
    const float* b_o     = (const float*)d_in[11];
    const float* g_o     = (const float*)d_in[12];
    const float* beta_o  = (const float*)d_in[13];
    const float* rm_o    = (const float*)d_in[14];
    const float* rv_o    = (const float*)d_in[15];
    const float* w_s     = (const float*)d_in[16];
    const float* b_s     = (const float*)d_in[17];
    const float* g_s     = (const float*)d_in[18];
    const float* beta_s  = (const float*)d_in[19];
    const float* rm_s    = (const float*)d_in[20];
    const float* rv_s    = (const float*)d_in[21];
    float* out = (float*)d_out;

    float *pF1, *pFS, *pFold;
    __nv_bfloat16 *pWAh, *pWAl, *pWSh, *pWSl, *pWOh, *pWOl, *pFh, *pFl, *pPLh, *pPLl;
    cudaGetSymbolAddress((void**)&pF1, d_F1);
    cudaGetSymbolAddress((void**)&pFS, d_FS);
    cudaGetSymbolAddress((void**)&pFold, d_fold);
    cudaGetSymbolAddress((void**)&pWAh, d_WAh);
    cudaGetSymbolAddress((void**)&pWAl, d_WAl);
    cudaGetSymbolAddress((void**)&pWSh, d_WSh);
    cudaGetSymbolAddress((void**)&pWSl, d_WSl);
    cudaGetSymbolAddress((void**)&pWOh, d_WOh);
    cudaGetSymbolAddress((void**)&pWOl, d_WOl);
    cudaGetSymbolAddress((void**)&pFh, d_Fh);
    cudaGetSymbolAddress((void**)&pFl, d_Fl);
    cudaGetSymbolAddress((void**)&pPLh, d_PLh);
    cudaGetSymbolAddress((void**)&pPLl, d_PLl);

    cudaFuncSetAttribute(hmma_gemm, cudaFuncAttributeMaxDynamicSharedMemorySize, G_SMEM);
    cudaFuncSetAttribute(lb_fused_kernel, cudaFuncAttributeMaxDynamicSharedMemorySize, FZ_TOT);

    // 0
    foldetect_kernel<<<2, 256>>>(b_n, g_n, beta_n, rm_n, rv_n,
                                 b_o, g_o, beta_o, rm_o, rv_o,
                                 b_s, g_s, beta_s, rm_s, rv_s, (const int*)nidx);
    // 1
    convert_idx_kernel<<<(RR + 255) / 256, 256>>>(nidx);
    // 2
    prep_all_kernel<<<640 + (PP * CIN) / 256, 256>>>(w_attn, w_s, w_o, feature);
    // 3: F1 = feature @ w_attn_top
    hmma_gemm<<<dim3(PP / 128, 2), 256, G_SMEM>>>(pFh, pFl, pWAh, pWAl, pF1,
                                                  128, 0, nullptr, nullptr, nullptr);
    // 4: FS = BN_s(feature @ w_s)
    hmma_gemm<<<dim3(PP / 128, 2), 256, G_SMEM>>>(pFh, pFl, pWSh, pWSl, pFS,
                                                  128, 1, pFold + 4 * 256, pFold + 5 * 256, nullptr);
    // 5: fused NB + LB GEMM + gather + softmax + pool -> PL
    lb_fused_kernel<<<296, 256, FZ_TOT>>>(feature, raw, w_n);
    // 6: out = lrelu(FS + BN_o(PL @ w_o))
    hmma_gemm<<<dim3(PP / 128, 2), 256, G_SMEM>>>(pPLh, pPLl, pWOh, pWOl, out,
                                                  256, 2, pFold + 2 * 256, pFold + 3 * 256, pFS);
}

// round 8
// speedup vs baseline: 1.8522x; 1.0640x over previous
#include <cuda_runtime.h>
#include <cuda_bf16.h>
#include <cstdint>

// Problem constants (fixed instance)
#define BB   4
#define NN   8192
#define KK   16
#define CG   10
#define PP   32768
#define RR   524288
#define NTILES 4096

// ---------------------------------------------------------------------------
// Scratch
// ---------------------------------------------------------------------------
__device__ float d_F1[(size_t)PP * 256];                       // feat @ w_attn_top
__device__ __nv_bfloat16 d_CATh[(size_t)PP * 384];             // [feat | PL] hi
__device__ __nv_bfloat16 d_CATl[(size_t)PP * 384];             // [feat | PL] lo
__device__ __nv_bfloat16 d_WAh[256 * 128], d_WAl[256 * 128];   // w_attn_top^T
__device__ __nv_bfloat16 d_Wth[256 * 128], d_Wtl[256 * 128];   // w_attn_bot^T
__device__ __nv_bfloat16 d_WSOh[256 * 384], d_WSOl[256 * 384]; // [w_s*s_s ; w_o*s_o]^T
__device__ int   d_GI[RR];
__device__ int   d_idx64;
__device__ float d_fold[3][256];   // 0=s_n 1=t_n 2=t_so

__device__ __forceinline__ float lrelu(float x) { return fmaxf(x, 0.2f * x); }

__device__ __forceinline__ uint32_t smem_u32(const void* p) {
    uint32_t a;
    asm("{ .reg .u64 t; cvta.to.shared.u64 t, %1; cvt.u32.u64 %0, t; }" : "=r"(a) : "l"(p));
    return a;
}
__device__ __forceinline__ void ldsm_x4(uint32_t& r0, uint32_t& r1, uint32_t& r2,
                                        uint32_t& r3, uint32_t addr) {
    asm volatile("ldmatrix.sync.aligned.m8n8.x4.shared.b16 {%0,%1,%2,%3}, [%4];"
                 : "=r"(r0), "=r"(r1), "=r"(r2), "=r"(r3) : "r"(addr));
}
#define CP16(dst, src)  asm volatile("cp.async.cg.shared.global [%0], [%1], 16;" :: "r"(dst), "l"(src))
#define CP_COMMIT()     asm volatile("cp.async.commit_group;" ::: "memory")
#define CP_WAIT(n)      asm volatile("cp.async.wait_group %0;" :: "n"(n) : "memory")
#define MMA16816(acc, a, b)                                                   \
    asm volatile("mma.sync.aligned.m16n8k16.row.col.f32.bf16.bf16.f32 "       \
                 "{%0,%1,%2,%3}, {%4,%5,%6,%7}, {%8,%9}, {%0,%1,%2,%3};"      \
                 : "+f"((acc)[0]), "+f"((acc)[1]), "+f"((acc)[2]), "+f"((acc)[3]) \
                 : "r"((a)[0]), "r"((a)[1]), "r"((a)[2]), "r"((a)[3]),        \
                   "r"((b)[0]), "r"((b)[1]))

// ---------------------------------------------------------------------------
// Launch 0: mega prep. b0: fold, b1: idx-detect, b2..: weight/feature splits
// ---------------------------------------------------------------------------
__global__ void prep_mega_kernel(
    const float* __restrict__ w_attn, const float* __restrict__ w_s,
    const float* __restrict__ w_o, const float* __restrict__ feat,
    const float* __restrict__ bn_, const float* __restrict__ gn,
    const float* __restrict__ betan, const float* __restrict__ rmn, const float* __restrict__ rvn,
    const float* __restrict__ bo, const float* __restrict__ go,
    const float* __restrict__ betao, const float* __restrict__ rmo, const float* __restrict__ rvo,
    const float* __restrict__ bs, const float* __restrict__ gs,
    const float* __restrict__ betas, const float* __restrict__ rms, const float* __restrict__ rvs,
    const int* __restrict__ widx)
{
    const int b = blockIdx.x, t = threadIdx.x;
    if (b == 0) {
        int i = t;
        if (i < 128) {
            float s = gn[i] * rsqrtf(rvn[i] + 1e-5f);
            d_fold[0][i] = s;
            d_fold[1][i] = (bn_[i] - rmn[i]) * s + betan[i];
        }
        if (i < 256) {
            float so = go[i] * rsqrtf(rvo[i] + 1e-5f);
            float ss = gs[i] * rsqrtf(rvs[i] + 1e-5f);
            d_fold[2][i] = (bo[i] - rmo[i]) * so + betao[i]
                         + (bs[i] - rms[i]) * ss + betas[i];
        }
        return;
    }
    if (b == 1) {
        __shared__ int ok;
        if (t == 0) ok = 1;
        __syncthreads();
        for (int i = t; i < 2048; i += blockDim.x)
            if (widx[2 * i + 1] != 0) ok = 0;
        __syncthreads();
        if (t == 0) d_idx64 = ok;
        return;
    }
    if (b < 130) {               // WA^T: w_attn rows 0-127
        int i = (b - 2) * 256 + t;
        int n = i >> 7, k = i & 127;
        float v = w_attn[(size_t)k * 256 + n];
        __nv_bfloat16 hi = __float2bfloat16(v);
        d_WAh[i] = hi;
        d_WAl[i] = __float2bfloat16(v - __bfloat162float(hi));
        return;
    }
    if (b < 258) {               // Wt^T: w_attn rows 128-255
        int i = (b - 130) * 256 + t;
        int n = i >> 7, k = i & 127;
        float v = w_attn[(size_t)(128 + k) * 256 + n];
        __nv_bfloat16 hi = __float2bfloat16(v);
        d_Wth[i] = hi;
        d_Wtl[i] = __float2bfloat16(v - __bfloat162float(hi));
        return;
    }
    if (b < 642) {               // WSO^T [256][384], BN scale folded
        int i = (b - 258) * 256 + t;
        int n = i / 384, k = i % 384;
        float v;
        if (k < 128) v = w_s[(size_t)k * 256 + n] * (gs[n] * rsqrtf(rvs[n] + 1e-5f));
        else         v = w_o[(size_t)(k - 128) * 256 + n] * (go[n] * rsqrtf(rvo[n] + 1e-5f));
        __nv_bfloat16 hi = __float2bfloat16(v);
        d_WSOh[i] = hi;
        d_WSOl[i] = __float2bfloat16(v - __bfloat162float(hi));
        return;
    }
    {                            // feature split into CAT cols 0-127
        int i = (b - 642) * 256 + t;          // i = m*128 + k
        int m = i >> 7, k = i & 127;
        float v = feat[i];
        __nv_bfloat16 hi = __float2bfloat16(v);
        size_t o = (size_t)m * 384 + k;
        d_CATh[o] = hi;
        d_CATl[o] = __float2bfloat16(v - __bfloat162float(hi));
    }
}

// Launch 1: index conversion
__global__ void convert_idx_kernel(const void* __restrict__ nidx)
{
    int r = blockIdx.x * blockDim.x + threadIdx.x;
    if (r >= RR) return;
    long long v;
    if (d_idx64) v = ((const long long*)nidx)[r];
    else         v = (long long)((const int*)nidx)[r];
    int vi = (int)v;
    vi = min(max(vi, 0), NN - 1);
    int batch = r / (NN * KK);
    d_GI[r] = batch * NN + vi;
}

// ---------------------------------------------------------------------------
// Generic HMMA GEMM: C[M,256] = (Ah+Al)[M,Kd] @ (Wh+Wl)^T
// A row stride = sA u4, W row stride = sW u4. K chunked by 128.
// mode 0: C = acc     mode 3: C = lrelu(acc + tv[col])
// ---------------------------------------------------------------------------
#define G_SMEM (4 * 128 * 272)
__global__ __launch_bounds__(256, 1)
void hmma_gemm(const __nv_bfloat16* __restrict__ Ah, const __nv_bfloat16* __restrict__ Al,
               int sA,
               const __nv_bfloat16* __restrict__ Wh, const __nv_bfloat16* __restrict__ Wl,
               int sW,
               float* __restrict__ C, int Kd, int mode, const float* __restrict__ tv)
{
    extern __shared__ __align__(16) char sm[];
    const uint32_t sb = smem_u32(sm);
    const uint32_t aWH = sb, aWL = sb + 34816, aAH = sb + 69632, aAL = sb + 104448;

    const int tid = threadIdx.x;
    const int wid = tid >> 5, lane = tid & 31;
    const int wm = wid >> 1, wn = wid & 1;
    const int g = lane >> 2, tg = lane & 3;
    const int ri = lane & 7, mi = lane >> 3;
    const int m0 = blockIdx.x * 128;
    const int half = blockIdx.y;

    float acc[2][8][4];
#pragma unroll
    for (int i = 0; i < 2; i++)
#pragma unroll
        for (int j = 0; j < 8; j++)
#pragma unroll
            for (int c = 0; c < 4; c++) acc[i][j][c] = 0.f;

    const uint32_t aoff = (uint32_t)((wm * 32 + (mi & 1) * 8 + ri) * 272 + (mi >> 1) * 16);
    const uint32_t boff = (uint32_t)((wn * 64 + (mi >> 1) * 8 + ri) * 272 + (mi & 1) * 16);

    for (int kt = 0; kt < (Kd >> 7); kt++) {
        if (kt > 0) __syncthreads();
        for (int lin = tid; lin < 2048; lin += 256) {
            int row = lin >> 4, ch = lin & 15;
            size_t wi = (size_t)(half * 128 + row) * sW + kt * 16 + ch;
            size_t ai = (size_t)(m0 + row) * sA + kt * 16 + ch;
            uint32_t so = row * 272u + ch * 16u;
            CP16(aWH + so, (const char*)Wh + wi * 16);
            CP16(aWL + so, (const char*)Wl + wi * 16);
            CP16(aAH + so, (const char*)Ah + ai * 16);
            CP16(aAL + so, (const char*)Al + ai * 16);
        }
        CP_COMMIT();
        CP_WAIT(0);
        __syncthreads();
#pragma unroll
        for (int p = 0; p < 3; p++) {
            const uint32_t Ab = ((p == 2) ? aAL : aAH) + aoff;
            const uint32_t Bb = ((p == 1) ? aWL : aWH) + boff;
#pragma unroll
            for (int ks = 0; ks < 8; ks++) {
                const uint32_t k2 = ks * 32;
                uint32_t a[2][4], b[8][2];
                ldsm_x4(a[0][0], a[0][1], a[0][2], a[0][3], Ab + k2);
                ldsm_x4(a[1][0], a[1][1], a[1][2], a[1][3], Ab + 16 * 272 + k2);
#pragma unroll
                for (int q = 0; q < 4; q++)
                    ldsm_x4(b[2 * q][0], b[2 * q][1], b[2 * q + 1][0], b[2 * q + 1][1],
                            Bb + q * 16 * 272 + k2);
#pragma unroll
                for (int i = 0; i < 2; i++)
#pragma unroll
                    for (int j = 0; j < 8; j++)
                        MMA16816(acc[i][j], a[i], b[j]);
            }
        }
    }

#pragma unroll
    for (int i = 0; i < 2; i++) {
        const int row0 = m0 + wm * 32 + i * 16 + g;
#pragma unroll
        for (int j = 0; j < 8; j++) {
            const int col = half * 128 + wn * 64 + j * 8 + 2 * tg;
            float2 v0 = make_float2(acc[i][j][0], acc[i][j][1]);
            float2 v1 = make_float2(acc[i][j][2], acc[i][j][3]);
            if (mode == 3) {
                float t0 = tv[col], t1 = tv[col + 1];
                v0.x = lrelu(v0.x + t0); v0.y = lrelu(v0.y + t1);
                v1.x = lrelu(v1.x + t0); v1.y = lrelu(v1.y + t1);
            }
            *(float2*)(C + (size_t)row0 * 256 + col) = v0;
            *(float2*)(C + (size_t)(row0 + 8) * 256 + col) = v1;
        }
    }
}

// ---------------------------------------------------------------------------
// Fused LB GEMM + softmax + pooling, N-quartered for 2 CTAs/SM.
// grid = 592 (148 tile-strides x 4 N-quarters), 256 threads.
// smem (112128 B): WH 0 | WL 17408 | AH 34816 | AL 53248 | Ct 71680 |
//                  raw 106496 | sgi 111616
// A processed as two 64-channel NB chunks (order so pool's chunk stays last).
// ---------------------------------------------------------------------------
#define LQ_WH  0
#define LQ_WL  17408
#define LQ_AH  34816
#define LQ_AL  53248
#define LQ_CT  71680
#define LQ_RAW 106496
#define LQ_GI  111616
#define LQ_TOT 112128

__global__ __launch_bounds__(256, 2)
void lb_fused_kernel(const float* __restrict__ feat, const float* __restrict__ raw,
                     const float* __restrict__ wn_)
{
    extern __shared__ __align__(16) char sm[];
    const uint32_t sb = smem_u32(sm);
    __nv_bfloat16* AH = (__nv_bfloat16*)(sm + LQ_AH);
    __nv_bfloat16* AL = (__nv_bfloat16*)(sm + LQ_AL);
    float* Ct = (float*)(sm + LQ_CT);
    float* Ft = (float*)(sm + LQ_AH);          // overlays A (q<2 pool only)
    const float* raws = (const float*)(sm + LQ_RAW);
    int* sgi = (int*)(sm + LQ_GI);

    const int tid = threadIdx.x;
    const int wid = tid >> 5, lane = tid & 31;
    const int wm = wid >> 1, wn = wid & 1;
    const int g = lane >> 2, tg = lane & 3;
    const int ri = lane & 7, mi = lane >> 3;
    const int q = blockIdx.x & 3;

    // NB thread mapping: one channel per thread per chunk
    const int chl = tid & 63, rgrp = tid >> 6;

    // W quarter resident (64 N-rows x 128 K)
    for (int lin = tid; lin < 1024; lin += 256) {
        int row = lin >> 4, ch = lin & 15;
        size_t wi = (size_t)(q * 64 + row) * 16 + ch;
        uint32_t so = row * 272u + ch * 16u;
        CP16(sb + LQ_WH + so, (const char*)d_Wth + wi * 16);
        CP16(sb + LQ_WL + so, (const char*)d_Wtl + wi * 16);
    }
    CP_COMMIT();
    CP_WAIT(0);
    __syncthreads();

    const int cFirst = (q == 2) ? 64 : 0;       // pool needs the LAST chunk resident
    const int cSecond = 64 - cFirst;

    const uint32_t aoff = (uint32_t)((wm * 32 + (mi & 1) * 8 + ri) * 144 + (mi >> 1) * 16);
    const uint32_t boffBase = (uint32_t)((wn * 32 + (mi >> 1) * 8 + ri) * 272 + (mi & 1) * 16);

    for (int tile = blockIdx.x >> 2; tile < NTILES; tile += 148) {
        __syncthreads();                         // prev pool done (Ct/A/raw free)

        // raw tile async
        const char* rawg = (const char*)raw + (size_t)tile * 5120;
        for (int i = tid; i < 320; i += 256)
            CP16(sb + LQ_RAW + i * 16, rawg + i * 16);
        CP_COMMIT();                             // group: raw
        if (tid < 128) sgi[tid] = d_GI[tile * 128 + tid];
        __syncthreads();                         // sgi visible

        // F1 quarter gather -> Ct (async)
        const char* F1c = (const char*)d_F1;
#pragma unroll
        for (int ii = 0; ii < 8; ii++) {
            int lin = tid + 256 * ii;            // 0..2047
            int r = lin >> 4, c4 = lin & 15;
            int gi = sgi[r];
            CP16(sb + LQ_CT + r * 272 + c4 * 16,
                 F1c + (size_t)gi * 1024 + q * 256 + c4 * 16);
        }
        CP_COMMIT();                             // group: F1
        CP_WAIT(1);                              // raw arrived
        __syncthreads();

        float acc[2][4][4];
#pragma unroll
        for (int i = 0; i < 2; i++)
#pragma unroll
            for (int j = 0; j < 4; j++)
#pragma unroll
                for (int c = 0; c < 4; c++) acc[i][j][c] = 0.f;

#pragma unroll
        for (int cc = 0; cc < 2; cc++) {
            const int c0 = cc ? cSecond : cFirst;
            // NB compute chunk: ch = c0 + chl, rows rgrp + 4*ii
            {
                const int chg = c0 + chl;
                float wcol[CG];
#pragma unroll
                for (int u = 0; u < CG; u++) wcol[u] = wn_[u * 128 + chg];
                const float sc = d_fold[0][chg], tc = d_fold[1][chg];
#pragma unroll 4
                for (int ii = 0; ii < 32; ii++) {
                    int r = ii * 4 + rgrp;
                    float a = 0.f;
#pragma unroll
                    for (int u = 0; u < CG; u++) a += wcol[u] * raws[r * CG + u];
                    float v = lrelu(a * sc + tc);
                    __nv_bfloat16 hi = __float2bfloat16(v);
                    AH[r * 72 + chl] = hi;
                    AL[r * 72 + chl] = __float2bfloat16(v - __bfloat162float(hi));
                }
            }
            __syncthreads();
            // mma over this chunk: W k-bytes offset = c0*2
            const uint32_t boff = boffBase + (uint32_t)(c0 * 2);
#pragma unroll
            for (int p = 0; p < 3; p++) {
                const uint32_t Ab = ((p == 2) ? (sb + LQ_AL) : (sb + LQ_AH)) + aoff;
                const uint32_t Bb = ((p == 1) ? (sb + LQ_WL) : (sb + LQ_WH)) + boff;
#pragma unroll
                for (int ks = 0; ks < 4; ks++) {
                    const uint32_t k2 = ks * 32;
                    uint32_t a[2][4], b[4][2];
                    ldsm_x4(a[0][0], a[0][1], a[0][2], a[0][3], Ab + k2);
                    ldsm_x4(a[1][0], a[1][1], a[1][2], a[1][3], Ab + 16 * 144 + k2);
                    ldsm_x4(b[0][0], b[0][1], b[1][0], b[1][1], Bb + k2);
                    ldsm_x4(b[2][0], b[2][1], b[3][0], b[3][1], Bb + 16 * 272 + k2);
#pragma unroll
                    for (int i = 0; i < 2; i++)
#pragma unroll
                        for (int j = 0; j < 4; j++)
                            MMA16816(acc[i][j], a[i], b[j]);
                }
            }
            __syncthreads();                     // all warps done with A chunk
        }

        CP_WAIT(0);                              // F1 in Ct
        // feat gather for q<2 into Ft (A region free now)
        if (q < 2) {
            const char* fc = (const char*)feat;
#pragma unroll
            for (int ii = 0; ii < 8; ii++) {
                int lin = tid + 256 * ii;
                int r = lin >> 4, c4 = lin & 15;
                int gi = sgi[r];
                CP16(sb + LQ_AH + r * 272 + c4 * 16,
                     fc + (size_t)gi * 512 + q * 256 + c4 * 16);
            }
            CP_COMMIT();
        }

        // epilogue: Ct += acc   (rows wm*32+i*16+g(+8), cols wn*32+j*8+2tg)
#pragma unroll
        for (int i = 0; i < 2; i++) {
            const int r0 = wm * 32 + i * 16 + g;
#pragma unroll
            for (int j = 0; j < 4; j++) {
                const int c = wn * 32 + j * 8 + 2 * tg;
                float2* p0 = (float2*)(Ct + r0 * 68 + c);
                float2* p1 = (float2*)(Ct + (r0 + 8) * 68 + c);
                float2 v0 = *p0, v1 = *p1;
                v0.x += acc[i][j][0]; v0.y += acc[i][j][1];
                v1.x += acc[i][j][2]; v1.y += acc[i][j][3];
                *p0 = v0; *p1 = v1;
            }
        }
        if (q < 2) CP_WAIT(0);
        __syncthreads();

        // softmax over K per (point, col) + pool; 512 pairs, 2 per thread
#pragma unroll
        for (int s = 0; s < 2; s++) {
            const int pid = tid + 256 * s;
            const int pt = pid >> 6, lc = pid & 63;
            const float* ctp = Ct + pt * 16 * 68 + lc;
            float l[KK];
#pragma unroll
            for (int k = 0; k < KK; k++) l[k] = ctp[k * 68];
            float m = l[0];
#pragma unroll
            for (int k = 1; k < KK; k++) m = fmaxf(m, l[k]);
            float sum = 0.f;
#pragma unroll
            for (int k = 0; k < KK; k++) { l[k] = __expf(l[k] - m); sum += l[k]; }
            float inv = __frcp_rn(sum);

            float pooled = 0.f;
            if (q < 2) {
                const float* fp = Ft + pt * 16 * 68 + lc;
#pragma unroll
                for (int k = 0; k < KK; k++) pooled += l[k] * fp[k * 68];
            } else {
                const __nv_bfloat16* ah = AH + pt * 16 * 72 + lc;
                const __nv_bfloat16* al = AL + pt * 16 * 72 + lc;
#pragma unroll
                for (int k = 0; k < KK; k++)
                    pooled += l[k] * (__bfloat162float(ah[k * 72]) +
                                      __bfloat162float(al[k * 72]));
            }
            pooled *= inv;
            size_t o = (size_t)(tile * 8 + pt) * 384 + 128 + q * 64 + lc;
            __nv_bfloat16 hi = __float2bfloat16(pooled);
            d_CATh[o] = hi;
            d_CATl[o] = __float2bfloat16(pooled - __bfloat162float(hi));
        }
    }
}

// ---------------------------------------------------------------------------
// Launch
// ---------------------------------------------------------------------------
extern "C" void kernel_launch(void* const* d_in, const int* in_sizes, int n_in,
                              void* d_out, int out_size)
{
    const float* feature = (const float*)d_in[0];
    const float* raw     = (const float*)d_in[1];
    const void*  nidx    = d_in[2];
    const float* w_n     = (const float*)d_in[3];
    const float* b_n     = (const float*)d_in[4];
    const float* g_n     = (const float*)d_in[5];
    const float* beta_n  = (const float*)d_in[6];
    const float* rm_n    = (const float*)d_in[7];
    const float* rv_n    = (const float*)d_in[8];
    const float* w_attn  = (const float*)d_in[9];
    const float* w_o     = (const float*)d_in[10];
    const float* b_o     = (const float*)d_in[11];
    const float* g_o     = (const float*)d_in[12];
    const float* beta_o  = (const float*)d_in[13];
    const float* rm_o    = (const float*)d_in[14];
    const float* rv_o    = (const float*)d_in[15];
    const float* w_s     = (const float*)d_in[16];
    const float* b_s     = (const float*)d_in[17];
    const float* g_s     = (const float*)d_in[18];
    const float* beta_s  = (const float*)d_in[19];
    const float* rm_s    = (const float*)d_in[20];
    const float* rv_s    = (const float*)d_in[21];
    float* out = (float*)d_out;

    float *pF1, *pFold;
    __nv_bfloat16 *pCATh, *pCATl, *pWAh, *pWAl, *pWSOh, *pWSOl;
    cudaGetSymbolAddress((void**)&pF1, d_F1);
    cudaGetSymbolAddress((void**)&pFold, d_fold);
    cudaGetSymbolAddress((void**)&pCATh, d_CATh);
    cudaGetSymbolAddress((void**)&pCATl, d_CATl);
    cudaGetSymbolAddress((void**)&pWAh, d_WAh);
    cudaGetSymbolAddress((void**)&pWAl, d_WAl);
    cudaGetSymbolAddress((void**)&pWSOh, d_WSOh);
    cudaGetSymbolAddress((void**)&pWSOl, d_WSOl);

    cudaFuncSetAttribute(hmma_gemm, cudaFuncAttributeMaxDynamicSharedMemorySize, G_SMEM);
    cudaFuncSetAttribute(lb_fused_kernel, cudaFuncAttributeMaxDynamicSharedMemorySize, LQ_TOT);

    // 0: prep (fold + detect + all splits)
    prep_mega_kernel<<<642 + (PP * 128) / 256, 256>>>(
        w_attn, w_s, w_o, feature,
        b_n, g_n, beta_n, rm_n, rv_n,
        b_o, g_o, beta_o, rm_o, rv_o,
        b_s, g_s, beta_s, rm_s, rv_s, (const int*)nidx);
    // 1: index conversion
    convert_idx_kernel<<<(RR + 255) / 256, 256>>>(nidx);
    // 2: F1 = feat @ w_attn_top
    hmma_gemm<<<dim3(PP / 128, 2), 256, G_SMEM>>>(pCATh, pCATl, 48, pWAh, pWAl, 16,
                                                  pF1, 128, 0, nullptr);
    // 3: fused NB + LB GEMM + gather + softmax + pool -> CAT[128:384]  (ncu target)
    lb_fused_kernel<<<592, 256, LQ_TOT>>>(feature, raw, w_n);
    // 4: out = lrelu([feat|PL] @ WSO + t_so)
    hmma_gemm<<<dim3(PP / 128, 2), 256, G_SMEM>>>(pCATh, pCATl, 48, pWSOh, pWSOl, 48,
                                                  out, 384, 3, pFold + 2 * 256);
}

// round 9
// speedup vs baseline: 1.9760x; 1.0668x over previous
#include <cuda_runtime.h>
#include <cuda_bf16.h>
#include <cstdint>

// Problem constants (fixed instance)
#define BB   4
#define NN   8192
#define KK   16
#define CG   10
#define PP   32768
#define RR   524288
#define NTILES 4096

// ---------------------------------------------------------------------------
// Scratch
// ---------------------------------------------------------------------------
__device__ float d_F1[(size_t)PP * 256];                       // feat @ w_attn_top
__device__ __nv_bfloat16 d_NBh[(size_t)RR * 128];              // neigh hi
__device__ __nv_bfloat16 d_NBl[(size_t)RR * 128];              // neigh lo
__device__ __nv_bfloat16 d_CATh[(size_t)PP * 384];             // [feat | PL] hi
__device__ __nv_bfloat16 d_CATl[(size_t)PP * 384];             // [feat | PL] lo
__device__ __nv_bfloat16 d_WAh[256 * 128], d_WAl[256 * 128];   // w_attn_top^T
__device__ __nv_bfloat16 d_Wth[256 * 128], d_Wtl[256 * 128];   // w_attn_bot^T
__device__ __nv_bfloat16 d_WSOh[256 * 384], d_WSOl[256 * 384]; // [w_s*s_s ; w_o*s_o]^T
__device__ int   d_GI[RR];
__device__ int   d_idx64;
__device__ float d_fold[3][256];   // 0=s_n 1=t_n 2=t_so

__device__ __forceinline__ float lrelu(float x) { return fmaxf(x, 0.2f * x); }

__device__ __forceinline__ uint32_t smem_u32(const void* p) {
    uint32_t a;
    asm("{ .reg .u64 t; cvta.to.shared.u64 t, %1; cvt.u32.u64 %0, t; }" : "=r"(a) : "l"(p));
    return a;
}
__device__ __forceinline__ void ldsm_x4(uint32_t& r0, uint32_t& r1, uint32_t& r2,
                                        uint32_t& r3, uint32_t addr) {
    asm volatile("ldmatrix.sync.aligned.m8n8.x4.shared.b16 {%0,%1,%2,%3}, [%4];"
                 : "=r"(r0), "=r"(r1), "=r"(r2), "=r"(r3) : "r"(addr));
}
#define CP16(dst, src)  asm volatile("cp.async.cg.shared.global [%0], [%1], 16;" :: "r"(dst), "l"(src))
#define CP_COMMIT()     asm volatile("cp.async.commit_group;" ::: "memory")
#define CP_WAIT(n)      asm volatile("cp.async.wait_group %0;" :: "n"(n) : "memory")
#define MMA16816(acc, a, b)                                                   \
    asm volatile("mma.sync.aligned.m16n8k16.row.col.f32.bf16.bf16.f32 "       \
                 "{%0,%1,%2,%3}, {%4,%5,%6,%7}, {%8,%9}, {%0,%1,%2,%3};"      \
                 : "+f"((acc)[0]), "+f"((acc)[1]), "+f"((acc)[2]), "+f"((acc)[3]) \
                 : "r"((a)[0]), "r"((a)[1]), "r"((a)[2]), "r"((a)[3]),        \
                   "r"((b)[0]), "r"((b)[1]))

// ---------------------------------------------------------------------------
// Launch 0: mega prep. b0: fold, b1: idx-detect, b2..: weight/feature splits
// ---------------------------------------------------------------------------
__global__ void prep_mega_kernel(
    const float* __restrict__ w_attn, const float* __restrict__ w_s,
    const float* __restrict__ w_o, const float* __restrict__ feat,
    const float* __restrict__ bn_, const float* __restrict__ gn,
    const float* __restrict__ betan, const float* __restrict__ rmn, const float* __restrict__ rvn,
    const float* __restrict__ bo, const float* __restrict__ go,
    const float* __restrict__ betao, const float* __restrict__ rmo, const float* __restrict__ rvo,
    const float* __restrict__ bs, const float* __restrict__ gs,
    const float* __restrict__ betas, const float* __restrict__ rms, const float* __restrict__ rvs,
    const int* __restrict__ widx)
{
    const int b = blockIdx.x, t = threadIdx.x;
    if (b == 0) {
        int i = t;
        if (i < 128) {
            float s = gn[i] * rsqrtf(rvn[i] + 1e-5f);
            d_fold[0][i] = s;
            d_fold[1][i] = (bn_[i] - rmn[i]) * s + betan[i];
        }
        if (i < 256) {
            float so = go[i] * rsqrtf(rvo[i] + 1e-5f);
            float ss = gs[i] * rsqrtf(rvs[i] + 1e-5f);
            d_fold[2][i] = (bo[i] - rmo[i]) * so + betao[i]
                         + (bs[i] - rms[i]) * ss + betas[i];
        }
        return;
    }
    if (b == 1) {
        __shared__ int ok;
        if (t == 0) ok = 1;
        __syncthreads();
        for (int i = t; i < 2048; i += blockDim.x)
            if (widx[2 * i + 1] != 0) ok = 0;
        __syncthreads();
        if (t == 0) d_idx64 = ok;
        return;
    }
    if (b < 130) {               // WA^T: w_attn rows 0-127
        int i = (b - 2) * 256 + t;
        int n = i >> 7, k = i & 127;
        float v = w_attn[(size_t)k * 256 + n];
        __nv_bfloat16 hi = __float2bfloat16(v);
        d_WAh[i] = hi;
        d_WAl[i] = __float2bfloat16(v - __bfloat162float(hi));
        return;
    }
    if (b < 258) {               // Wt^T: w_attn rows 128-255
        int i = (b - 130) * 256 + t;
        int n = i >> 7, k = i & 127;
        float v = w_attn[(size_t)(128 + k) * 256 + n];
        __nv_bfloat16 hi = __float2bfloat16(v);
        d_Wth[i] = hi;
        d_Wtl[i] = __float2bfloat16(v - __bfloat162float(hi));
        return;
    }
    if (b < 642) {               // WSO^T [256][384], BN scale folded
        int i = (b - 258) * 256 + t;
        int n = i / 384, k = i % 384;
        float v;
        if (k < 128) v = w_s[(size_t)k * 256 + n] * (gs[n] * rsqrtf(rvs[n] + 1e-5f));
        else         v = w_o[(size_t)(k - 128) * 256 + n] * (go[n] * rsqrtf(rvo[n] + 1e-5f));
        __nv_bfloat16 hi = __float2bfloat16(v);
        d_WSOh[i] = hi;
        d_WSOl[i] = __float2bfloat16(v - __bfloat162float(hi));
        return;
    }
    {                            // feature split into CAT cols 0-127
        int i = (b - 642) * 256 + t;          // i = m*128 + k
        int m = i >> 7, k = i & 127;
        float v = feat[i];
        __nv_bfloat16 hi = __float2bfloat16(v);
        size_t o = (size_t)m * 384 + k;
        d_CATh[o] = hi;
        d_CATl[o] = __float2bfloat16(v - __bfloat162float(hi));
    }
}

// ---------------------------------------------------------------------------
// Launch 1: idx conversion (blocks 0..2047) + NB compute (rest)
// NB = lrelu(BN(raw @ w_n)) -> bf16 hi/lo gmem, 2 rows per 256-thread block
// ---------------------------------------------------------------------------
__global__ void neighconv_kernel(const void* __restrict__ nidx,
                                 const float* __restrict__ raw,
                                 const float* __restrict__ wn_)
{
    const int b = blockIdx.x, t = threadIdx.x;
    if (b < 2048) {
        int r = b * 256 + t;
        long long v;
        if (d_idx64) v = ((const long long*)nidx)[r];
        else         v = (long long)((const int*)nidx)[r];
        int vi = (int)v;
        vi = min(max(vi, 0), NN - 1);
        int batch = r / (NN * KK);
        d_GI[r] = batch * NN + vi;
        return;
    }
    int r = (b - 2048) * 2 + (t >> 7);
    int c = t & 127;
    const float* rr = raw + (size_t)r * CG;
    float acc = 0.f;
#pragma unroll
    for (int g = 0; g < CG; g++) acc += rr[g] * wn_[g * 128 + c];
    float v = lrelu(acc * d_fold[0][c] + d_fold[1][c]);
    __nv_bfloat16 hi = __float2bfloat16(v);
    size_t o = (size_t)r * 128 + c;
    d_NBh[o] = hi;
    d_NBl[o] = __float2bfloat16(v - __bfloat162float(hi));
}

// ---------------------------------------------------------------------------
// Generic HMMA GEMM: C[M,256] = (Ah+Al)[M,Kd] @ (Wh+Wl)^T
// A row stride = sA u4, W row stride = sW u4. K chunked by 128.
// mode 0: C = acc     mode 3: C = lrelu(acc + tv[col])
// ---------------------------------------------------------------------------
#define G_SMEM (4 * 128 * 272)
__global__ __launch_bounds__(256, 1)
void hmma_gemm(const __nv_bfloat16* __restrict__ Ah, const __nv_bfloat16* __restrict__ Al,
               int sA,
               const __nv_bfloat16* __restrict__ Wh, const __nv_bfloat16* __restrict__ Wl,
               int sW,
               float* __restrict__ C, int Kd, int mode, const float* __restrict__ tv)
{
    extern __shared__ __align__(16) char sm[];
    const uint32_t sb = smem_u32(sm);
    const uint32_t aWH = sb, aWL = sb + 34816, aAH = sb + 69632, aAL = sb + 104448;

    const int tid = threadIdx.x;
    const int wid = tid >> 5, lane = tid & 31;
    const int wm = wid >> 1, wn = wid & 1;
    const int g = lane >> 2, tg = lane & 3;
    const int ri = lane & 7, mi = lane >> 3;
    const int m0 = blockIdx.x * 128;
    const int half = blockIdx.y;

    float acc[2][8][4];
#pragma unroll
    for (int i = 0; i < 2; i++)
#pragma unroll
        for (int j = 0; j < 8; j++)
#pragma unroll
            for (int c = 0; c < 4; c++) acc[i][j][c] = 0.f;

    const uint32_t aoff = (uint32_t)((wm * 32 + (mi & 1) * 8 + ri) * 272 + (mi >> 1) * 16);
    const uint32_t boff = (uint32_t)((wn * 64 + (mi >> 1) * 8 + ri) * 272 + (mi & 1) * 16);

    for (int kt = 0; kt < (Kd >> 7); kt++) {
        if (kt > 0) __syncthreads();
        for (int lin = tid; lin < 2048; lin += 256) {
            int row = lin >> 4, ch = lin & 15;
            size_t wi = (size_t)(half * 128 + row) * sW + kt * 16 + ch;
            size_t ai = (size_t)(m0 + row) * sA + kt * 16 + ch;
            uint32_t so = row * 272u + ch * 16u;
            CP16(aWH + so, (const char*)Wh + wi * 16);
            CP16(aWL + so, (const char*)Wl + wi * 16);
            CP16(aAH + so, (const char*)Ah + ai * 16);
            CP16(aAL + so, (const char*)Al + ai * 16);
        }
        CP_COMMIT();
        CP_WAIT(0);
        __syncthreads();
#pragma unroll
        for (int p = 0; p < 3; p++) {
            const uint32_t Ab = ((p == 2) ? aAL : aAH) + aoff;
            const uint32_t Bb = ((p == 1) ? aWL : aWH) + boff;
#pragma unroll
            for (int ks = 0; ks < 8; ks++) {
                const uint32_t k2 = ks * 32;
                uint32_t a[2][4], b[8][2];
                ldsm_x4(a[0][0], a[0][1], a[0][2], a[0][3], Ab + k2);
                ldsm_x4(a[1][0], a[1][1], a[1][2], a[1][3], Ab + 16 * 272 + k2);
#pragma unroll
                for (int q = 0; q < 4; q++)
                    ldsm_x4(b[2 * q][0], b[2 * q][1], b[2 * q + 1][0], b[2 * q + 1][1],
                            Bb + q * 16 * 272 + k2);
#pragma unroll
                for (int i = 0; i < 2; i++)
#pragma unroll
                    for (int j = 0; j < 8; j++)
                        MMA16816(acc[i][j], a[i], b[j]);
            }
        }
    }

#pragma unroll
    for (int i = 0; i < 2; i++) {
        const int row0 = m0 + wm * 32 + i * 16 + g;
#pragma unroll
        for (int j = 0; j < 8; j++) {
            const int col = half * 128 + wn * 64 + j * 8 + 2 * tg;
            float2 v0 = make_float2(acc[i][j][0], acc[i][j][1]);
            float2 v1 = make_float2(acc[i][j][2], acc[i][j][3]);
            if (mode == 3) {
                float t0 = tv[col], t1 = tv[col + 1];
                v0.x = lrelu(v0.x + t0); v0.y = lrelu(v0.y + t1);
                v1.x = lrelu(v1.x + t0); v1.y = lrelu(v1.y + t1);
            }
            *(float2*)(C + (size_t)row0 * 256 + col) = v0;
            *(float2*)(C + (size_t)(row0 + 8) * 256 + col) = v1;
        }
    }
}

// ---------------------------------------------------------------------------
// Fused LB GEMM + softmax + pooling, N-quartered, NB read from gmem.
// grid = 592 (148 tile-strides x 4 N-quarters), 256 threads, 2 CTAs/SM.
// smem (107008 B): WH 0 (17408) | WL 17408 | AH 34816 (18432) | AL 53248 |
//                  Ct 71680 (34816) | sgi 106496 (512)
// A is one 64-K-chunk buffer (row stride 144B); two chunks processed in
// sequence; pool's chunk (q's channels for q>=2) processed second.
// Ft (q<2 feat gather, 128x272B) overlays AH/AL after mma.
// ---------------------------------------------------------------------------
#define LQ_WH  0
#define LQ_WL  17408
#define LQ_AH  34816
#define LQ_AL  53248
#define LQ_CT  71680
#define LQ_GI  106496
#define LQ_TOT 107008

__global__ __launch_bounds__(256, 2)
void lb_fused_kernel(const float* __restrict__ feat)
{
    extern __shared__ __align__(16) char sm[];
    const uint32_t sb = smem_u32(sm);
    __nv_bfloat16* AH = (__nv_bfloat16*)(sm + LQ_AH);
    __nv_bfloat16* AL = (__nv_bfloat16*)(sm + LQ_AL);
    float* Ct = (float*)(sm + LQ_CT);
    float* Ft = (float*)(sm + LQ_AH);
    int* sgi = (int*)(sm + LQ_GI);

    const int tid = threadIdx.x;
    const int wid = tid >> 5, lane = tid & 31;
    const int wm = wid >> 1, wn = wid & 1;
    const int g = lane >> 2, tg = lane & 3;
    const int ri = lane & 7, mi = lane >> 3;
    const int q = blockIdx.x & 3;

    // W quarter resident (64 N-rows x 128 K)
    for (int lin = tid; lin < 1024; lin += 256) {
        int row = lin >> 4, ch = lin & 15;
        size_t wi = (size_t)(q * 64 + row) * 16 + ch;
        uint32_t so = row * 272u + ch * 16u;
        CP16(sb + LQ_WH + so, (const char*)d_Wth + wi * 16);
        CP16(sb + LQ_WL + so, (const char*)d_Wtl + wi * 16);
    }
    CP_COMMIT();
    CP_WAIT(0);
    __syncthreads();

    const int cFirst = (q == 2) ? 64 : 0;   // pool's chunk must be SECOND
    const int cSecond = 64 - cFirst;

    const uint32_t aoff = (uint32_t)((wm * 32 + (mi & 1) * 8 + ri) * 144 + (mi >> 1) * 16);
    const uint32_t boffBase = (uint32_t)((wn * 32 + (mi >> 1) * 8 + ri) * 272 + (mi & 1) * 16);

    for (int tile = blockIdx.x >> 2; tile < NTILES; tile += 148) {
        __syncthreads();                     // prev pool done (Ct/A free)

        if (tid < 128) sgi[tid] = d_GI[tile * 128 + tid];

        // A chunk 1 (hi+lo): 128 rows x 64 ch bf16 = 1024 u4 each
        const char* nbh = (const char*)d_NBh + ((size_t)tile * 128 * 128 + cFirst) * 2;
        const char* nbl = (const char*)d_NBl + ((size_t)tile * 128 * 128 + cFirst) * 2;
#pragma unroll
        for (int ii = 0; ii < 4; ii++) {
            int lin = tid + 256 * ii;        // 0..1023
            int row = lin >> 3, cc = lin & 7;
            uint32_t so = row * 144u + cc * 16u;
            size_t goff = (size_t)row * 256 + cc * 16;
            CP16(sb + LQ_AH + so, nbh + goff);
            CP16(sb + LQ_AL + so, nbl + goff);
        }
        CP_COMMIT();                         // group A1
        __syncthreads();                     // sgi visible

        // F1 quarter gather -> Ct
        const char* F1c = (const char*)d_F1;
#pragma unroll
        for (int ii = 0; ii < 8; ii++) {
            int lin = tid + 256 * ii;        // 0..2047
            int r = lin >> 4, c4 = lin & 15;
            int gi = sgi[r];
            CP16(sb + LQ_CT + r * 272 + c4 * 16,
                 F1c + (size_t)gi * 1024 + q * 256 + c4 * 16);
        }
        CP_COMMIT();                         // group F1

        float acc[2][4][4];
#pragma unroll
        for (int i = 0; i < 2; i++)
#pragma unroll
            for (int j = 0; j < 4; j++)
#pragma unroll
                for (int c = 0; c < 4; c++) acc[i][j][c] = 0.f;

        CP_WAIT(1);                          // A1 arrived
        __syncthreads();

        // mma chunk 1
        {
            const uint32_t boff = boffBase + (uint32_t)(cFirst * 2);
#pragma unroll
            for (int p = 0; p < 3; p++) {
                const uint32_t Ab = ((p == 2) ? (sb + LQ_AL) : (sb + LQ_AH)) + aoff;
                const uint32_t Bb = ((p == 1) ? (sb + LQ_WL) : (sb + LQ_WH)) + boff;
#pragma unroll
                for (int ks = 0; ks < 4; ks++) {
                    const uint32_t k2 = ks * 32;
                    uint32_t a[2][4], b[4][2];
                    ldsm_x4(a[0][0], a[0][1], a[0][2], a[0][3], Ab + k2);
                    ldsm_x4(a[1][0], a[1][1], a[1][2], a[1][3], Ab + 16 * 144 + k2);
                    ldsm_x4(b[0][0], b[0][1], b[1][0], b[1][1], Bb + k2);
                    ldsm_x4(b[2][0], b[2][1], b[3][0], b[3][1], Bb + 16 * 272 + k2);
#pragma unroll
                    for (int i = 0; i < 2; i++)
#pragma unroll
                        for (int j = 0; j < 4; j++)
                            MMA16816(acc[i][j], a[i], b[j]);
                }
            }
        }
        __syncthreads();                     // chunk-1 reads done

        // A chunk 2 into the same buffer
        const char* nbh2 = (const char*)d_NBh + ((size_t)tile * 128 * 128 + cSecond) * 2;
        const char* nbl2 = (const char*)d_NBl + ((size_t)tile * 128 * 128 + cSecond) * 2;
#pragma unroll
        for (int ii = 0; ii < 4; ii++) {
            int lin = tid + 256 * ii;
            int row = lin >> 3, cc = lin & 7;
            uint32_t so = row * 144u + cc * 16u;
            size_t goff = (size_t)row * 256 + cc * 16;
            CP16(sb + LQ_AH + so, nbh2 + goff);
            CP16(sb + LQ_AL + so, nbl2 + goff);
        }
        CP_COMMIT();                         // group A2
        CP_WAIT(0);                          // A2 + F1 arrived
        __syncthreads();

        // mma chunk 2
        {
            const uint32_t boff = boffBase + (uint32_t)(cSecond * 2);
#pragma unroll
            for (int p = 0; p < 3; p++) {
                const uint32_t Ab = ((p == 2) ? (sb + LQ_AL) : (sb + LQ_AH)) + aoff;
                const uint32_t Bb = ((p == 1) ? (sb + LQ_WL) : (sb + LQ_WH)) + boff;
#pragma unroll
                for (int ks = 0; ks < 4; ks++) {
                    const uint32_t k2 = ks * 32;
                    uint32_t a[2][4], b[4][2];
                    ldsm_x4(a[0][0], a[0][1], a[0][2], a[0][3], Ab + k2);
                    ldsm_x4(a[1][0], a[1][1], a[1][2], a[1][3], Ab + 16 * 144 + k2);
                    ldsm_x4(b[0][0], b[0][1], b[1][0], b[1][1], Bb + k2);
                    ldsm_x4(b[2][0], b[2][1], b[3][0], b[3][1], Bb + 16 * 272 + k2);
#pragma unroll
                    for (int i = 0; i < 2; i++)
#pragma unroll
                        for (int j = 0; j < 4; j++)
                            MMA16816(acc[i][j], a[i], b[j]);
                }
            }
        }
        __syncthreads();                     // chunk-2 reads done (A free for Ft)

        // feat gather for q<2 into Ft (overlays A buffer)
        if (q < 2) {
            const char* fc = (const char*)feat;
#pragma unroll
            for (int ii = 0; ii < 8; ii++) {
                int lin = tid + 256 * ii;
                int r = lin >> 4, c4 = lin & 15;
                int gi = sgi[r];
                CP16(sb + LQ_AH + r * 272 + c4 * 16,
                     fc + (size_t)gi * 512 + q * 256 + c4 * 16);
            }
            CP_COMMIT();
        }

        // epilogue: Ct += acc
#pragma unroll
        for (int i = 0; i < 2; i++) {
            const int r0 = wm * 32 + i * 16 + g;
#pragma unroll
            for (int j = 0; j < 4; j++) {
                const int c = wn * 32 + j * 8 + 2 * tg;
                float2* p0 = (float2*)(Ct + r0 * 68 + c);
                float2* p1 = (float2*)(Ct + (r0 + 8) * 68 + c);
                float2 v0 = *p0, v1 = *p1;
                v0.x += acc[i][j][0]; v0.y += acc[i][j][1];
                v1.x += acc[i][j][2]; v1.y += acc[i][j][3];
                *p0 = v0; *p1 = v1;
            }
        }
        if (q < 2) CP_WAIT(0);
        __syncthreads();

        // softmax over K per (point, col) + pool; 512 pairs, 2 per thread
#pragma unroll
        for (int s = 0; s < 2; s++) {
            const int pid = tid + 256 * s;
            const int pt = pid >> 6, lc = pid & 63;
            const float* ctp = Ct + pt * 16 * 68 + lc;
            float l[KK];
#pragma unroll
            for (int k = 0; k < KK; k++) l[k] = ctp[k * 68];
            float m = l[0];
#pragma unroll
            for (int k = 1; k < KK; k++) m = fmaxf(m, l[k]);
            float sum = 0.f;
#pragma unroll
            for (int k = 0; k < KK; k++) { l[k] = __expf(l[k] - m); sum += l[k]; }
            float inv = __frcp_rn(sum);

            float pooled = 0.f;
            if (q < 2) {
                const float* fp = Ft + pt * 16 * 68 + lc;
#pragma unroll
                for (int k = 0; k < KK; k++) pooled += l[k] * fp[k * 68];
            } else {
                const __nv_bfloat16* ah = AH + pt * 16 * 72 + lc;
                const __nv_bfloat16* al = AL + pt * 16 * 72 + lc;
#pragma unroll
                for (int k = 0; k < KK; k++)
                    pooled += l[k] * (__bfloat162float(ah[k * 72]) +
                                      __bfloat162float(al[k * 72]));
            }
            pooled *= inv;
            size_t o = (size_t)(tile * 8 + pt) * 384 + 128 + q * 64 + lc;
            __nv_bfloat16 hi = __float2bfloat16(pooled);
            d_CATh[o] = hi;
            d_CATl[o] = __float2bfloat16(pooled - __bfloat162float(hi));
        }
    }
}

// ---------------------------------------------------------------------------
// Launch
// ---------------------------------------------------------------------------
extern "C" void kernel_launch(void* const* d_in, const int* in_sizes, int n_in,
                              void* d_out, int out_size)
{
    const float* feature = (const float*)d_in[0];
    const float* raw     = (const float*)d_in[1];
    const void*  nidx    = d_in[2];
    const float* w_n     = (const float*)d_in[3];
    const float* b_n     = (const float*)d_in[4];
    const float* g_n     = (const float*)d_in[5];
    const float* beta_n  = (const float*)d_in[6];
    const float* rm_n    = (const float*)d_in[7];
    const float* rv_n    = (const float*)d_in[8];
    const float* w_attn  = (const float*)d_in[9];
    const float* w_o     = (const float*)d_in[10];
    const float* b_o     = (const float*)d_in[11];
    const float* g_o     = (const float*)d_in[12];
    const float* beta_o  = (const float*)d_in[13];
    const float* rm_o    = (const float*)d_in[14];
    const float* rv_o    = (const float*)d_in[15];
    const float* w_s     = (const float*)d_in[16];
    const float* b_s     = (const float*)d_in[17];
    const float* g_s     = (const float*)d_in[18];
    const float* beta_s  = (const float*)d_in[19];
    const float* rm_s    = (const float*)d_in[20];
    const float* rv_s    = (const float*)d_in[21];
    float* out = (float*)d_out;

    float *pF1, *pFold;
    __nv_bfloat16 *pCATh, *pCATl, *pWAh, *pWAl, *pWSOh, *pWSOl;
    cudaGetSymbolAddress((void**)&pF1, d_F1);
    cudaGetSymbolAddress((void**)&pFold, d_fold);
    cudaGetSymbolAddress((void**)&pCATh, d_CATh);
    cudaGetSymbolAddress((void**)&pCATl, d_CATl);
    cudaGetSymbolAddress((void**)&pWAh, d_WAh);
    cudaGetSymbolAddress((void**)&pWAl, d_WAl);
    cudaGetSymbolAddress((void**)&pWSOh, d_WSOh);
    cudaGetSymbolAddress((void**)&pWSOl, d_WSOl);

    cudaFuncSetAttribute(hmma_gemm, cudaFuncAttributeMaxDynamicSharedMemorySize, G_SMEM);
    cudaFuncSetAttribute(lb_fused_kernel, cudaFuncAttributeMaxDynamicSharedMemorySize, LQ_TOT);

    // 0: prep (fold + detect + all splits)
    prep_mega_kernel<<<642 + (PP * 128) / 256, 256>>>(
        w_attn, w_s, w_o, feature,
        b_n, g_n, beta_n, rm_n, rv_n,
        b_o, g_o, beta_o, rm_o, rv_o,
        b_s, g_s, beta_s, rm_s, rv_s, (const int*)nidx);
    // 1: idx conversion + NB -> gmem (bf16 hi/lo)
    neighconv_kernel<<<2048 + RR / 2, 256>>>(nidx, raw, w_n);
    // 2: F1 = feat @ w_attn_top
    hmma_gemm<<<dim3(PP / 128, 2), 256, G_SMEM>>>(pCATh, pCATl, 48, pWAh, pWAl, 16,
                                                  pF1, 128, 0, nullptr);
    // 3: fused LB GEMM + gather + softmax + pool -> CAT[128:384]  (ncu target)
    lb_fused_kernel<<<592, 256, LQ_TOT>>>(feature);
    // 4: out = lrelu([feat|PL] @ WSO + t_so)
    hmma_gemm<<<dim3(PP / 128, 2), 256, G_SMEM>>>(pCATh, pCATl, 48, pWSOh, pWSOl, 48,
                                                  out, 384, 3, pFold + 2 * 256);
}

// round 10
// speedup vs baseline: 1.9887x; 1.0064x over previous
#include <cuda_runtime.h>
#include <cuda_bf16.h>
#include <cstdint>

// Problem constants (fixed instance)
#define BB   4
#define NN   8192
#define KK   16
#define CG   10
#define PP   32768
#define RR   524288
#define NTILES 4096

// ---------------------------------------------------------------------------
// Scratch
// ---------------------------------------------------------------------------
__device__ float d_F1[(size_t)PP * 256];                       // feat @ w_attn_top
__device__ __nv_bfloat16 d_NBh[(size_t)RR * 128];              // neigh hi
__device__ __nv_bfloat16 d_NBl[(size_t)RR * 128];              // neigh lo
__device__ __nv_bfloat16 d_CATh[(size_t)PP * 384];             // [feat | PL] hi
__device__ __nv_bfloat16 d_CATl[(size_t)PP * 384];             // [feat | PL] lo
__device__ __nv_bfloat16 d_WAh[256 * 128], d_WAl[256 * 128];   // w_attn_top^T
__device__ __nv_bfloat16 d_Wth[256 * 128], d_Wtl[256 * 128];   // w_attn_bot^T
__device__ __nv_bfloat16 d_WSOh[256 * 384], d_WSOl[256 * 384]; // [w_s*s_s ; w_o*s_o]^T
__device__ int   d_GI[RR];
__device__ int   d_idx64;
__device__ float d_fold[3][256];   // 0=s_n 1=t_n 2=t_so

__device__ __forceinline__ float lrelu(float x) { return fmaxf(x, 0.2f * x); }

__device__ __forceinline__ uint32_t smem_u32(const void* p) {
    uint32_t a;
    asm("{ .reg .u64 t; cvta.to.shared.u64 t, %1; cvt.u32.u64 %0, t; }" : "=r"(a) : "l"(p));
    return a;
}
__device__ __forceinline__ void ldsm_x4(uint32_t& r0, uint32_t& r1, uint32_t& r2,
                                        uint32_t& r3, uint32_t addr) {
    asm volatile("ldmatrix.sync.aligned.m8n8.x4.shared.b16 {%0,%1,%2,%3}, [%4];"
                 : "=r"(r0), "=r"(r1), "=r"(r2), "=r"(r3) : "r"(addr));
}
#define CP16(dst, src)  asm volatile("cp.async.cg.shared.global [%0], [%1], 16;" :: "r"(dst), "l"(src))
#define CP_COMMIT()     asm volatile("cp.async.commit_group;" ::: "memory")
#define CP_WAIT(n)      asm volatile("cp.async.wait_group %0;" :: "n"(n) : "memory")
#define MMA16816(acc, a, b)                                                   \
    asm volatile("mma.sync.aligned.m16n8k16.row.col.f32.bf16.bf16.f32 "       \
                 "{%0,%1,%2,%3}, {%4,%5,%6,%7}, {%8,%9}, {%0,%1,%2,%3};"      \
                 : "+f"((acc)[0]), "+f"((acc)[1]), "+f"((acc)[2]), "+f"((acc)[3]) \
                 : "r"((a)[0]), "r"((a)[1]), "r"((a)[2]), "r"((a)[3]),        \
                   "r"((b)[0]), "r"((b)[1]))

// ---------------------------------------------------------------------------
// Launch 0: mega prep. b0: fold, b1: idx-detect, b2..: weight/feature splits
// ---------------------------------------------------------------------------
__global__ void prep_mega_kernel(
    const float* __restrict__ w_attn, const float* __restrict__ w_s,
    const float* __restrict__ w_o, const float* __restrict__ feat,
    const float* __restrict__ bn_, const float* __restrict__ gn,
    const float* __restrict__ betan, const float* __restrict__ rmn, const float* __restrict__ rvn,
    const float* __restrict__ bo, const float* __restrict__ go,
    const float* __restrict__ betao, const float* __restrict__ rmo, const float* __restrict__ rvo,
    const float* __restrict__ bs, const float* __restrict__ gs,
    const float* __restrict__ betas, const float* __restrict__ rms, const float* __restrict__ rvs,
    const int* __restrict__ widx)
{
    const int b = blockIdx.x, t = threadIdx.x;
    if (b == 0) {
        int i = t;
        if (i < 128) {
            float s = gn[i] * rsqrtf(rvn[i] + 1e-5f);
            d_fold[0][i] = s;
            d_fold[1][i] = (bn_[i] - rmn[i]) * s + betan[i];
        }
        if (i < 256) {
            float so = go[i] * rsqrtf(rvo[i] + 1e-5f);
            float ss = gs[i] * rsqrtf(rvs[i] + 1e-5f);
            d_fold[2][i] = (bo[i] - rmo[i]) * so + betao[i]
                         + (bs[i] - rms[i]) * ss + betas[i];
        }
        return;
    }
    if (b == 1) {
        __shared__ int ok;
        if (t == 0) ok = 1;
        __syncthreads();
        for (int i = t; i < 2048; i += blockDim.x)
            if (widx[2 * i + 1] != 0) ok = 0;
        __syncthreads();
        if (t == 0) d_idx64 = ok;
        return;
    }
    if (b < 130) {               // WA^T: w_attn rows 0-127
        int i = (b - 2) * 256 + t;
        int n = i >> 7, k = i & 127;
        float v = w_attn[(size_t)k * 256 + n];
        __nv_bfloat16 hi = __float2bfloat16(v);
        d_WAh[i] = hi;
        d_WAl[i] = __float2bfloat16(v - __bfloat162float(hi));
        return;
    }
    if (b < 258) {               // Wt^T: w_attn rows 128-255
        int i = (b - 130) * 256 + t;
        int n = i >> 7, k = i & 127;
        float v = w_attn[(size_t)(128 + k) * 256 + n];
        __nv_bfloat16 hi = __float2bfloat16(v);
        d_Wth[i] = hi;
        d_Wtl[i] = __float2bfloat16(v - __bfloat162float(hi));
        return;
    }
    if (b < 642) {               // WSO^T [256][384], BN scale folded
        int i = (b - 258) * 256 + t;
        int n = i / 384, k = i % 384;
        float v;
        if (k < 128) v = w_s[(size_t)k * 256 + n] * (gs[n] * rsqrtf(rvs[n] + 1e-5f));
        else         v = w_o[(size_t)(k - 128) * 256 + n] * (go[n] * rsqrtf(rvo[n] + 1e-5f));
        __nv_bfloat16 hi = __float2bfloat16(v);
        d_WSOh[i] = hi;
        d_WSOl[i] = __float2bfloat16(v - __bfloat162float(hi));
        return;
    }
    {                            // feature split into CAT cols 0-127
        int i = (b - 642) * 256 + t;          // i = m*128 + k
        int m = i >> 7, k = i & 127;
        float v = feat[i];
        __nv_bfloat16 hi = __float2bfloat16(v);
        size_t o = (size_t)m * 384 + k;
        d_CATh[o] = hi;
        d_CATl[o] = __float2bfloat16(v - __bfloat162float(hi));
    }
}

// ---------------------------------------------------------------------------
// Launch 1: idx conversion (blocks 0..2047) + NB compute (rest)
// ---------------------------------------------------------------------------
__global__ void neighconv_kernel(const void* __restrict__ nidx,
                                 const float* __restrict__ raw,
                                 const float* __restrict__ wn_)
{
    const int b = blockIdx.x, t = threadIdx.x;
    if (b < 2048) {
        int r = b * 256 + t;
        long long v;
        if (d_idx64) v = ((const long long*)nidx)[r];
        else         v = (long long)((const int*)nidx)[r];
        int vi = (int)v;
        vi = min(max(vi, 0), NN - 1);
        int batch = r / (NN * KK);
        d_GI[r] = batch * NN + vi;
        return;
    }
    int r = (b - 2048) * 2 + (t >> 7);
    int c = t & 127;
    const float* rr = raw + (size_t)r * CG;
    float acc = 0.f;
#pragma unroll
    for (int g = 0; g < CG; g++) acc += rr[g] * wn_[g * 128 + c];
    float v = lrelu(acc * d_fold[0][c] + d_fold[1][c]);
    __nv_bfloat16 hi = __float2bfloat16(v);
    size_t o = (size_t)r * 128 + c;
    d_NBh[o] = hi;
    d_NBl[o] = __float2bfloat16(v - __bfloat162float(hi));
}

// ---------------------------------------------------------------------------
// Generic HMMA GEMM (unchanged from R9)
// ---------------------------------------------------------------------------
#define G_SMEM (4 * 128 * 272)
__global__ __launch_bounds__(256, 1)
void hmma_gemm(const __nv_bfloat16* __restrict__ Ah, const __nv_bfloat16* __restrict__ Al,
               int sA,
               const __nv_bfloat16* __restrict__ Wh, const __nv_bfloat16* __restrict__ Wl,
               int sW,
               float* __restrict__ C, int Kd, int mode, const float* __restrict__ tv)
{
    extern __shared__ __align__(16) char sm[];
    const uint32_t sb = smem_u32(sm);
    const uint32_t aWH = sb, aWL = sb + 34816, aAH = sb + 69632, aAL = sb + 104448;

    const int tid = threadIdx.x;
    const int wid = tid >> 5, lane = tid & 31;
    const int wm = wid >> 1, wn = wid & 1;
    const int g = lane >> 2, tg = lane & 3;
    const int ri = lane & 7, mi = lane >> 3;
    const int m0 = blockIdx.x * 128;
    const int half = blockIdx.y;

    float acc[2][8][4];
#pragma unroll
    for (int i = 0; i < 2; i++)
#pragma unroll
        for (int j = 0; j < 8; j++)
#pragma unroll
            for (int c = 0; c < 4; c++) acc[i][j][c] = 0.f;

    const uint32_t aoff = (uint32_t)((wm * 32 + (mi & 1) * 8 + ri) * 272 + (mi >> 1) * 16);
    const uint32_t boff = (uint32_t)((wn * 64 + (mi >> 1) * 8 + ri) * 272 + (mi & 1) * 16);

    for (int kt = 0; kt < (Kd >> 7); kt++) {
        if (kt > 0) __syncthreads();
        for (int lin = tid; lin < 2048; lin += 256) {
            int row = lin >> 4, ch = lin & 15;
            size_t wi = (size_t)(half * 128 + row) * sW + kt * 16 + ch;
            size_t ai = (size_t)(m0 + row) * sA + kt * 16 + ch;
            uint32_t so = row * 272u + ch * 16u;
            CP16(aWH + so, (const char*)Wh + wi * 16);
            CP16(aWL + so, (const char*)Wl + wi * 16);
            CP16(aAH + so, (const char*)Ah + ai * 16);
            CP16(aAL + so, (const char*)Al + ai * 16);
        }
        CP_COMMIT();
        CP_WAIT(0);
        __syncthreads();
#pragma unroll
        for (int p = 0; p < 3; p++) {
            const uint32_t Ab = ((p == 2) ? aAL : aAH) + aoff;
            const uint32_t Bb = ((p == 1) ? aWL : aWH) + boff;
#pragma unroll
            for (int ks = 0; ks < 8; ks++) {
                const uint32_t k2 = ks * 32;
                uint32_t a[2][4], b[8][2];
                ldsm_x4(a[0][0], a[0][1], a[0][2], a[0][3], Ab + k2);
                ldsm_x4(a[1][0], a[1][1], a[1][2], a[1][3], Ab + 16 * 272 + k2);
#pragma unroll
                for (int q = 0; q < 4; q++)
                    ldsm_x4(b[2 * q][0], b[2 * q][1], b[2 * q + 1][0], b[2 * q + 1][1],
                            Bb + q * 16 * 272 + k2);
#pragma unroll
                for (int i = 0; i < 2; i++)
#pragma unroll
                    for (int j = 0; j < 8; j++)
                        MMA16816(acc[i][j], a[i], b[j]);
            }
        }
    }

#pragma unroll
    for (int i = 0; i < 2; i++) {
        const int row0 = m0 + wm * 32 + i * 16 + g;
#pragma unroll
        for (int j = 0; j < 8; j++) {
            const int col = half * 128 + wn * 64 + j * 8 + 2 * tg;
            float2 v0 = make_float2(acc[i][j][0], acc[i][j][1]);
            float2 v1 = make_float2(acc[i][j][2], acc[i][j][3]);
            if (mode == 3) {
                float t0 = tv[col], t1 = tv[col + 1];
                v0.x = lrelu(v0.x + t0); v0.y = lrelu(v0.y + t1);
                v1.x = lrelu(v1.x + t0); v1.y = lrelu(v1.y + t1);
            }
            *(float2*)(C + (size_t)row0 * 256 + col) = v0;
            *(float2*)(C + (size_t)(row0 + 8) * 256 + col) = v1;
        }
    }
}

// ---------------------------------------------------------------------------
// Fused LB GEMM + softmax + pooling, N-quartered, pipelined 32-K A chunks.
// grid = 592, 256 threads, 2 CTAs/SM.
// smem (111104 B): WH 0 (17408) | WL 17408 | A 34816 (4 x 10240:
//   AH0, AL0, AH1, AL1) | Ct 75776 (128x68 f32) | sgi 110592 (512)
// A chunk row stride 80B (32 bf16 + pad); W/Ct/Ft row stride 272B.
// Chunk order per quarter puts pool's NB channels in the final two buffers.
// ---------------------------------------------------------------------------
#define LQ_WH  0
#define LQ_WL  17408
#define LQ_A   34816
#define LQ_CT  75776
#define LQ_GI  110592
#define LQ_TOT 111104

__device__ __forceinline__ void load_a_chunk(uint32_t sb, int tile, int chunk,
                                             int buf, int tid)
{
    const char* nbh = (const char*)d_NBh + (size_t)tile * 32768 + chunk * 64;
    const char* nbl = (const char*)d_NBl + (size_t)tile * 32768 + chunk * 64;
    const uint32_t Ab = sb + LQ_A + buf * 20480u;
#pragma unroll
    for (int ii = 0; ii < 2; ii++) {
        int lin = tid + 256 * ii;
        int row = lin >> 2, c4 = lin & 3;
        uint32_t so = row * 80u + c4 * 16u;
        size_t go = (size_t)row * 256 + c4 * 16;
        CP16(Ab + so, nbh + go);
        CP16(Ab + 10240u + so, nbl + go);
    }
    CP_COMMIT();
}

__global__ __launch_bounds__(256, 2)
void lb_fused_kernel(const float* __restrict__ feat)
{
    extern __shared__ __align__(16) char sm[];
    const uint32_t sb = smem_u32(sm);
    float* Ct = (float*)(sm + LQ_CT);
    float* Ft = (float*)(sm + LQ_A);
    int* sgi = (int*)(sm + LQ_GI);

    const int tid = threadIdx.x;
    const int wid = tid >> 5, lane = tid & 31;
    const int wm = wid >> 1, wn = wid & 1;
    const int g = lane >> 2, tg = lane & 3;
    const int ri = lane & 7, mi = lane >> 3;
    const int q = blockIdx.x & 3;

    // W quarter resident (64 N-rows x 128 K, hi+lo)
    for (int lin = tid; lin < 1024; lin += 256) {
        int row = lin >> 4, ch = lin & 15;
        size_t wi = (size_t)(q * 64 + row) * 16 + ch;
        uint32_t so = row * 272u + ch * 16u;
        CP16(sb + LQ_WH + so, (const char*)d_Wth + wi * 16);
        CP16(sb + LQ_WL + so, (const char*)d_Wtl + wi * 16);
    }
    CP_COMMIT();
    CP_WAIT(0);
    __syncthreads();

    const uint32_t aoff = (uint32_t)((wm * 32 + (mi & 1) * 8 + ri) * 80 + (mi >> 1) * 16);
    const uint32_t boffB = (uint32_t)((wn * 32 + (mi >> 1) * 8 + ri) * 272 + (mi & 1) * 16);

    for (int tile = blockIdx.x >> 2; tile < NTILES; tile += 148) {
        __syncthreads();                      // prev pool done (bufs/Ct free)

        if (tid < 128) sgi[tid] = d_GI[tile * 128 + tid];

        const int id0 = (q == 2) ? 2 : 0;
        load_a_chunk(sb, tile, id0, 0, tid);  // chunk ids[0] -> buf0

        float acc[2][4][4];
#pragma unroll
        for (int i = 0; i < 2; i++)
#pragma unroll
            for (int j = 0; j < 4; j++)
#pragma unroll
                for (int c = 0; c < 4; c++) acc[i][j][c] = 0.f;

#pragma unroll
        for (int cc = 0; cc < 4; cc++) {
            const int chunk = (q == 2) ? ((cc + 2) & 3) : cc;
            // wait for chunk cc's data (FIFO: groups are A0 | A1,F1 | A2 | A3)
            if (cc == 1) CP_WAIT(1);
            else         CP_WAIT(0);
            __syncthreads();

            if (cc == 0) {
                const int id1 = (q == 2) ? 3 : 1;
                load_a_chunk(sb, tile, id1, 1, tid);
                // F1 quarter gather -> Ct (own group, after A1's)
                const char* F1c = (const char*)d_F1;
#pragma unroll
                for (int ii = 0; ii < 8; ii++) {
                    int lin = tid + 256 * ii;
                    int r = lin >> 4, c4 = lin & 15;
                    int gi = sgi[r];
                    CP16(sb + LQ_CT + r * 272 + c4 * 16,
                         F1c + (size_t)gi * 1024 + q * 256 + c4 * 16);
                }
                CP_COMMIT();
            } else if (cc < 3) {
                const int idn = (q == 2) ? ((cc + 3) & 3) : (cc + 1);
                load_a_chunk(sb, tile, idn, (cc + 1) & 1, tid);
            }

            // mma chunk cc from buf[cc&1]
            const uint32_t Abase = sb + LQ_A + (cc & 1) * 20480u;
            const uint32_t boff = boffB + (uint32_t)(chunk * 64);
#pragma unroll
            for (int ks = 0; ks < 2; ks++) {
                uint32_t ah[2][4], al[2][4], bh[4][2], bl[4][2];
                const uint32_t Aa = Abase + aoff + ks * 32;
                ldsm_x4(ah[0][0], ah[0][1], ah[0][2], ah[0][3], Aa);
                ldsm_x4(ah[1][0], ah[1][1], ah[1][2], ah[1][3], Aa + 16 * 80);
                ldsm_x4(al[0][0], al[0][1], al[0][2], al[0][3], Aa + 10240);
                ldsm_x4(al[1][0], al[1][1], al[1][2], al[1][3], Aa + 10240 + 16 * 80);
                const uint32_t Bh = sb + LQ_WH + boff + ks * 32;
                const uint32_t Bl = sb + LQ_WL + boff + ks * 32;
                ldsm_x4(bh[0][0], bh[0][1], bh[1][0], bh[1][1], Bh);
                ldsm_x4(bh[2][0], bh[2][1], bh[3][0], bh[3][1], Bh + 16 * 272);
                ldsm_x4(bl[0][0], bl[0][1], bl[1][0], bl[1][1], Bl);
                ldsm_x4(bl[2][0], bl[2][1], bl[3][0], bl[3][1], Bl + 16 * 272);
#pragma unroll
                for (int i = 0; i < 2; i++)
#pragma unroll
                    for (int j = 0; j < 4; j++) {
                        MMA16816(acc[i][j], ah[i], bh[j]);
                        MMA16816(acc[i][j], ah[i], bl[j]);
                        MMA16816(acc[i][j], al[i], bh[j]);
                    }
            }
        }
        __syncthreads();                      // all mma done; F1 visible in Ct

        // feat gather for q<2 into Ft (overlays A buffers)
        if (q < 2) {
            const char* fc = (const char*)feat;
#pragma unroll
            for (int ii = 0; ii < 8; ii++) {
                int lin = tid + 256 * ii;
                int r = lin >> 4, c4 = lin & 15;
                int gi = sgi[r];
                CP16(sb + LQ_A + r * 272 + c4 * 16,
                     fc + (size_t)gi * 512 + q * 256 + c4 * 16);
            }
            CP_COMMIT();
        }

        // epilogue: Ct += acc
#pragma unroll
        for (int i = 0; i < 2; i++) {
            const int r0 = wm * 32 + i * 16 + g;
#pragma unroll
            for (int j = 0; j < 4; j++) {
                const int c = wn * 32 + j * 8 + 2 * tg;
                float2* p0 = (float2*)(Ct + r0 * 68 + c);
                float2* p1 = (float2*)(Ct + (r0 + 8) * 68 + c);
                float2 v0 = *p0, v1 = *p1;
                v0.x += acc[i][j][0]; v0.y += acc[i][j][1];
                v1.x += acc[i][j][2]; v1.y += acc[i][j][3];
                *p0 = v0; *p1 = v1;
            }
        }
        if (q < 2) CP_WAIT(0);
        __syncthreads();

        // softmax over K per (point, col) + pool; 512 pairs, 2 per thread
#pragma unroll
        for (int s = 0; s < 2; s++) {
            const int pid = tid + 256 * s;
            const int pt = pid >> 6, lc = pid & 63;
            const float* ctp = Ct + pt * 16 * 68 + lc;
            float l[KK];
#pragma unroll
            for (int k = 0; k < KK; k++) l[k] = ctp[k * 68];
            float m = l[0];
#pragma unroll
            for (int k = 1; k < KK; k++) m = fmaxf(m, l[k]);
            float sum = 0.f;
#pragma unroll
            for (int k = 0; k < KK; k++) { l[k] = __expf(l[k] - m); sum += l[k]; }
            float inv = __frcp_rn(sum);

            float pooled = 0.f;
            if (q < 2) {
                const float* fp = Ft + pt * 16 * 68 + lc;
#pragma unroll
                for (int k = 0; k < KK; k++) pooled += l[k] * fp[k * 68];
            } else {
                // pool channels live in the final two A buffers (chunk order)
                const char* base = sm + LQ_A + (lc >> 5) * 20480;
                const __nv_bfloat16* ah = (const __nv_bfloat16*)base + pt * 16 * 40 + (lc & 31);
                const __nv_bfloat16* al = (const __nv_bfloat16*)(base + 10240) + pt * 16 * 40 + (lc & 31);
#pragma unroll
                for (int k = 0; k < KK; k++)
                    pooled += l[k] * (__bfloat162float(ah[k * 40]) +
                                      __bfloat162float(al[k * 40]));
            }
            pooled *= inv;
            size_t o = (size_t)(tile * 8 + pt) * 384 + 128 + q * 64 + lc;
            __nv_bfloat16 hi = __float2bfloat16(pooled);
            d_CATh[o] = hi;
            d_CATl[o] = __float2bfloat16(pooled - __bfloat162float(hi));
        }
    }
}

// ---------------------------------------------------------------------------
// Launch
// ---------------------------------------------------------------------------
extern "C" void kernel_launch(void* const* d_in, const int* in_sizes, int n_in,
                              void* d_out, int out_size)
{
    const float* feature = (const float*)d_in[0];
    const float* raw     = (const float*)d_in[1];
    const void*  nidx    = d_in[2];
    const float* w_n     = (const float*)d_in[3];
    const float* b_n     = (const float*)d_in[4];
    const float* g_n     = (const float*)d_in[5];
    const float* beta_n  = (const float*)d_in[6];
    const float* rm_n    = (const float*)d_in[7];
    const float* rv_n    = (const float*)d_in[8];
    const float* w_attn  = (const float*)d_in[9];
    const float* w_o     = (const float*)d_in[10];
    const float* b_o     = (const float*)d_in[11];
    const float* g_o     = (const float*)d_in[12];
    const float* beta_o  = (const float*)d_in[13];
    const float* rm_o    = (const float*)d_in[14];
    const float* rv_o    = (const float*)d_in[15];
    const float* w_s     = (const float*)d_in[16];
    const float* b_s     = (const float*)d_in[17];
    const float* g_s     = (const float*)d_in[18];
    const float* beta_s  = (const float*)d_in[19];
    const float* rm_s    = (const float*)d_in[20];
    const float* rv_s    = (const float*)d_in[21];
    float* out = (float*)d_out;

    float *pF1, *pFold;
    __nv_bfloat16 *pCATh, *pCATl, *pWAh, *pWAl, *pWSOh, *pWSOl;
    cudaGetSymbolAddress((void**)&pF1, d_F1);
    cudaGetSymbolAddress((void**)&pFold, d_fold);
    cudaGetSymbolAddress((void**)&pCATh, d_CATh);
    cudaGetSymbolAddress((void**)&pCATl, d_CATl);
    cudaGetSymbolAddress((void**)&pWAh, d_WAh);
    cudaGetSymbolAddress((void**)&pWAl, d_WAl);
    cudaGetSymbolAddress((void**)&pWSOh, d_WSOh);
    cudaGetSymbolAddress((void**)&pWSOl, d_WSOl);

    cudaFuncSetAttribute(hmma_gemm, cudaFuncAttributeMaxDynamicSharedMemorySize, G_SMEM);
    cudaFuncSetAttribute(lb_fused_kernel, cudaFuncAttributeMaxDynamicSharedMemorySize, LQ_TOT);

    // 0: prep (fold + detect + all splits)
    prep_mega_kernel<<<642 + (PP * 128) / 256, 256>>>(
        w_attn, w_s, w_o, feature,
        b_n, g_n, beta_n, rm_n, rv_n,
        b_o, g_o, beta_o, rm_o, rv_o,
        b_s, g_s, beta_s, rm_s, rv_s, (const int*)nidx);
    // 1: idx conversion + NB -> gmem (bf16 hi/lo)
    neighconv_kernel<<<2048 + RR / 2, 256>>>(nidx, raw, w_n);
    // 2: F1 = feat @ w_attn_top
    hmma_gemm<<<dim3(PP / 128, 2), 256, G_SMEM>>>(pCATh, pCATl, 48, pWAh, pWAl, 16,
                                                  pF1, 128, 0, nullptr);
    // 3: fused LB GEMM + gather + softmax + pool -> CAT[128:384]  (ncu target)
    lb_fused_kernel<<<592, 256, LQ_TOT>>>(feature);
    // 4: out = lrelu([feat|PL] @ WSO + t_so)
    hmma_gemm<<<dim3(PP / 128, 2), 256, G_SMEM>>>(pCATh, pCATl, 48, pWSOh, pWSOl, 48,
                                                  out, 384, 3, pFold + 2 * 256);
}

// round 11
// speedup vs baseline: 2.0203x; 1.0159x over previous
#include <cuda_runtime.h>
#include <cuda_bf16.h>
#include <cstdint>

// Problem constants (fixed instance)
#define BB   4
#define NN   8192
#define KK   16
#define CG   10
#define PP   32768
#define RR   524288
#define NTILES 4096

// ---------------------------------------------------------------------------
// Scratch
// ---------------------------------------------------------------------------
__device__ float d_F1[(size_t)PP * 256];                       // feat @ w_attn_top
__device__ __nv_bfloat16 d_NBh[(size_t)RR * 128];              // neigh hi
__device__ __nv_bfloat16 d_NBl[(size_t)RR * 128];              // neigh lo
__device__ __nv_bfloat16 d_CATh[(size_t)PP * 384];             // [feat | PL] hi
__device__ __nv_bfloat16 d_CATl[(size_t)PP * 384];             // [feat | PL] lo
__device__ __nv_bfloat16 d_WAh[256 * 128], d_WAl[256 * 128];   // w_attn_top^T
__device__ __nv_bfloat16 d_Wth[256 * 128], d_Wtl[256 * 128];   // w_attn_bot^T
__device__ __nv_bfloat16 d_WSOh[256 * 384], d_WSOl[256 * 384]; // [w_s*s_s ; w_o*s_o]^T
__device__ int   d_GI[RR];
__device__ int   d_idx64;
__device__ float d_fold[3][256];   // 0=s_n 1=t_n 2=t_so

__device__ __forceinline__ float lrelu(float x) { return fmaxf(x, 0.2f * x); }

__device__ __forceinline__ uint32_t smem_u32(const void* p) {
    uint32_t a;
    asm("{ .reg .u64 t; cvta.to.shared.u64 t, %1; cvt.u32.u64 %0, t; }" : "=r"(a) : "l"(p));
    return a;
}
__device__ __forceinline__ void ldsm_x4(uint32_t& r0, uint32_t& r1, uint32_t& r2,
                                        uint32_t& r3, uint32_t addr) {
    asm volatile("ldmatrix.sync.aligned.m8n8.x4.shared.b16 {%0,%1,%2,%3}, [%4];"
                 : "=r"(r0), "=r"(r1), "=r"(r2), "=r"(r3) : "r"(addr));
}
#define CP16(dst, src)  asm volatile("cp.async.cg.shared.global [%0], [%1], 16;" :: "r"(dst), "l"(src))
#define CP_COMMIT()     asm volatile("cp.async.commit_group;" ::: "memory")
#define CP_WAIT(n)      asm volatile("cp.async.wait_group %0;" :: "n"(n) : "memory")
#define MMA16816(acc, a, b)                                                   \
    asm volatile("mma.sync.aligned.m16n8k16.row.col.f32.bf16.bf16.f32 "       \
                 "{%0,%1,%2,%3}, {%4,%5,%6,%7}, {%8,%9}, {%0,%1,%2,%3};"      \
                 : "+f"((acc)[0]), "+f"((acc)[1]), "+f"((acc)[2]), "+f"((acc)[3]) \
                 : "r"((a)[0]), "r"((a)[1]), "r"((a)[2]), "r"((a)[3]),        \
                   "r"((b)[0]), "r"((b)[1]))

// ---------------------------------------------------------------------------
// Launch 0: mega prep. b0: fold, b1: idx-detect, b2..: weight/feature splits
// ---------------------------------------------------------------------------
__global__ void prep_mega_kernel(
    const float* __restrict__ w_attn, const float* __restrict__ w_s,
    const float* __restrict__ w_o, const float* __restrict__ feat,
    const float* __restrict__ bn_, const float* __restrict__ gn,
    const float* __restrict__ betan, const float* __restrict__ rmn, const float* __restrict__ rvn,
    const float* __restrict__ bo, const float* __restrict__ go,
    const float* __restrict__ betao, const float* __restrict__ rmo, const float* __restrict__ rvo,
    const float* __restrict__ bs, const float* __restrict__ gs,
    const float* __restrict__ betas, const float* __restrict__ rms, const float* __restrict__ rvs,
    const int* __restrict__ widx)
{
    const int b = blockIdx.x, t = threadIdx.x;
    if (b == 0) {
        int i = t;
        if (i < 128) {
            float s = gn[i] * rsqrtf(rvn[i] + 1e-5f);
            d_fold[0][i] = s;
            d_fold[1][i] = (bn_[i] - rmn[i]) * s + betan[i];
        }
        if (i < 256) {
            float so = go[i] * rsqrtf(rvo[i] + 1e-5f);
            float ss = gs[i] * rsqrtf(rvs[i] + 1e-5f);
            d_fold[2][i] = (bo[i] - rmo[i]) * so + betao[i]
                         + (bs[i] - rms[i]) * ss + betas[i];
        }
        return;
    }
    if (b == 1) {
        __shared__ int ok;
        if (t == 0) ok = 1;
        __syncthreads();
        for (int i = t; i < 2048; i += blockDim.x)
            if (widx[2 * i + 1] != 0) ok = 0;
        __syncthreads();
        if (t == 0) d_idx64 = ok;
        return;
    }
    if (b < 130) {               // WA^T: w_attn rows 0-127
        int i = (b - 2) * 256 + t;
        int n = i >> 7, k = i & 127;
        float v = w_attn[(size_t)k * 256 + n];
        __nv_bfloat16 hi = __float2bfloat16(v);
        d_WAh[i] = hi;
        d_WAl[i] = __float2bfloat16(v - __bfloat162float(hi));
        return;
    }
    if (b < 258) {               // Wt^T: w_attn rows 128-255
        int i = (b - 130) * 256 + t;
        int n = i >> 7, k = i & 127;
        float v = w_attn[(size_t)(128 + k) * 256 + n];
        __nv_bfloat16 hi = __float2bfloat16(v);
        d_Wth[i] = hi;
        d_Wtl[i] = __float2bfloat16(v - __bfloat162float(hi));
        return;
    }
    if (b < 642) {               // WSO^T [256][384], BN scale folded
        int i = (b - 258) * 256 + t;
        int n = i / 384, k = i % 384;
        float v;
        if (k < 128) v = w_s[(size_t)k * 256 + n] * (gs[n] * rsqrtf(rvs[n] + 1e-5f));
        else         v = w_o[(size_t)(k - 128) * 256 + n] * (go[n] * rsqrtf(rvo[n] + 1e-5f));
        __nv_bfloat16 hi = __float2bfloat16(v);
        d_WSOh[i] = hi;
        d_WSOl[i] = __float2bfloat16(v - __bfloat162float(hi));
        return;
    }
    {                            // feature split into CAT cols 0-127
        int i = (b - 642) * 256 + t;          // i = m*128 + k
        int m = i >> 7, k = i & 127;
        float v = feat[i];
        __nv_bfloat16 hi = __float2bfloat16(v);
        size_t o = (size_t)m * 384 + k;
        d_CATh[o] = hi;
        d_CATl[o] = __float2bfloat16(v - __bfloat162float(hi));
    }
}

// ---------------------------------------------------------------------------
// Launch 1: idx conversion (blocks 0..2047) + NB compute (rest)
// ---------------------------------------------------------------------------
__global__ void neighconv_kernel(const void* __restrict__ nidx,
                                 const float* __restrict__ raw,
                                 const float* __restrict__ wn_)
{
    const int b = blockIdx.x, t = threadIdx.x;
    if (b < 2048) {
        int r = b * 256 + t;
        long long v;
        if (d_idx64) v = ((const long long*)nidx)[r];
        else         v = (long long)((const int*)nidx)[r];
        int vi = (int)v;
        vi = min(max(vi, 0), NN - 1);
        int batch = r / (NN * KK);
        d_GI[r] = batch * NN + vi;
        return;
    }
    int r = (b - 2048) * 2 + (t >> 7);
    int c = t & 127;
    const float* rr = raw + (size_t)r * CG;
    float acc = 0.f;
#pragma unroll
    for (int g = 0; g < CG; g++) acc += rr[g] * wn_[g * 128 + c];
    float v = lrelu(acc * d_fold[0][c] + d_fold[1][c]);
    __nv_bfloat16 hi = __float2bfloat16(v);
    size_t o = (size_t)r * 128 + c;
    d_NBh[o] = hi;
    d_NBl[o] = __float2bfloat16(v - __bfloat162float(hi));
}

// ---------------------------------------------------------------------------
// Generic HMMA GEMM, BM=64, 2 CTAs/SM: C[M,256] = (Ah+Al)[M,Kd] @ (Wh+Wl)^T
// smem: WH 0 (34816) | WL 34816 | AH 69632 (17408) | AL 87040 -> 104448 B
// warps: 2(M) x 4(N), warp tile 32x32. mode 0: C=acc  mode 3: C=lrelu(acc+tv)
// ---------------------------------------------------------------------------
#define G_SMEM 104448
__global__ __launch_bounds__(256, 2)
void hmma_gemm(const __nv_bfloat16* __restrict__ Ah, const __nv_bfloat16* __restrict__ Al,
               int sA,
               const __nv_bfloat16* __restrict__ Wh, const __nv_bfloat16* __restrict__ Wl,
               int sW,
               float* __restrict__ C, int Kd, int mode, const float* __restrict__ tv)
{
    extern __shared__ __align__(16) char sm[];
    const uint32_t sb = smem_u32(sm);
    const uint32_t aWH = sb, aWL = sb + 34816, aAH = sb + 69632, aAL = sb + 87040;

    const int tid = threadIdx.x;
    const int wid = tid >> 5, lane = tid & 31;
    const int wm = wid >> 2, wn = wid & 3;
    const int g = lane >> 2, tg = lane & 3;
    const int ri = lane & 7, mi = lane >> 3;
    const int m0 = blockIdx.x * 64;
    const int half = blockIdx.y;

    float acc[2][4][4];
#pragma unroll
    for (int i = 0; i < 2; i++)
#pragma unroll
        for (int j = 0; j < 4; j++)
#pragma unroll
            for (int c = 0; c < 4; c++) acc[i][j][c] = 0.f;

    const uint32_t aoff = (uint32_t)((wm * 32 + (mi & 1) * 8 + ri) * 272 + (mi >> 1) * 16);
    const uint32_t boff = (uint32_t)((wn * 32 + (mi >> 1) * 8 + ri) * 272 + (mi & 1) * 16);

    for (int kt = 0; kt < (Kd >> 7); kt++) {
        if (kt > 0) __syncthreads();
        for (int lin = tid; lin < 2048; lin += 256) {
            int row = lin >> 4, ch = lin & 15;
            uint32_t so = row * 272u + ch * 16u;
            size_t wi = (size_t)(half * 128 + row) * sW + kt * 16 + ch;
            CP16(aWH + so, (const char*)Wh + wi * 16);
            CP16(aWL + so, (const char*)Wl + wi * 16);
            if (lin < 1024) {
                size_t ai = (size_t)(m0 + row) * sA + kt * 16 + ch;
                CP16(aAH + so, (const char*)Ah + ai * 16);
                CP16(aAL + so, (const char*)Al + ai * 16);
            }
        }
        CP_COMMIT();
        CP_WAIT(0);
        __syncthreads();
#pragma unroll
        for (int ks = 0; ks < 8; ks++) {
            const uint32_t k2 = ks * 32;
            uint32_t ah[2][4], al[2][4], bh[4][2], bl[4][2];
            ldsm_x4(ah[0][0], ah[0][1], ah[0][2], ah[0][3], aAH + aoff + k2);
            ldsm_x4(ah[1][0], ah[1][1], ah[1][2], ah[1][3], aAH + aoff + 16 * 272 + k2);
            ldsm_x4(al[0][0], al[0][1], al[0][2], al[0][3], aAL + aoff + k2);
            ldsm_x4(al[1][0], al[1][1], al[1][2], al[1][3], aAL + aoff + 16 * 272 + k2);
            ldsm_x4(bh[0][0], bh[0][1], bh[1][0], bh[1][1], aWH + boff + k2);
            ldsm_x4(bh[2][0], bh[2][1], bh[3][0], bh[3][1], aWH + boff + 16 * 272 + k2);
            ldsm_x4(bl[0][0], bl[0][1], bl[1][0], bl[1][1], aWL + boff + k2);
            ldsm_x4(bl[2][0], bl[2][1], bl[3][0], bl[3][1], aWL + boff + 16 * 272 + k2);
#pragma unroll
            for (int i = 0; i < 2; i++)
#pragma unroll
                for (int j = 0; j < 4; j++) {
                    MMA16816(acc[i][j], ah[i], bh[j]);
                    MMA16816(acc[i][j], ah[i], bl[j]);
                    MMA16816(acc[i][j], al[i], bh[j]);
                }
        }
    }

#pragma unroll
    for (int i = 0; i < 2; i++) {
        const int row0 = m0 + wm * 32 + i * 16 + g;
#pragma unroll
        for (int j = 0; j < 4; j++) {
            const int col = half * 128 + wn * 32 + j * 8 + 2 * tg;
            float2 v0 = make_float2(acc[i][j][0], acc[i][j][1]);
            float2 v1 = make_float2(acc[i][j][2], acc[i][j][3]);
            if (mode == 3) {
                float t0 = tv[col], t1 = tv[col + 1];
                v0.x = lrelu(v0.x + t0); v0.y = lrelu(v0.y + t1);
                v1.x = lrelu(v1.x + t0); v1.y = lrelu(v1.y + t1);
            }
            *(float2*)(C + (size_t)row0 * 256 + col) = v0;
            *(float2*)(C + (size_t)(row0 + 8) * 256 + col) = v1;
        }
    }
}

// ---------------------------------------------------------------------------
// Fused LB GEMM + softmax + pooling, N-quartered, cross-tile prefetch.
// grid = 592, 256 threads, 2 CTAs/SM.
// smem (111616 B): WH 0 (17408) | WL 17408 | A 34816 (2 bufs x 20480) |
//                  Ct 75776 (128x68 f32 = 34816) | sgi 110592 (2x512)
// Pool reads sources (feat / NB) from gmem (L2-hot) => A bufs free during
// pool => next tile's chunks 0,1 prefetch under epilogue+pool.
// ---------------------------------------------------------------------------
#define LQ_WH  0
#define LQ_WL  17408
#define LQ_A   34816
#define LQ_CT  75776
#define LQ_GI  110592
#define LQ_TOT 111616

__device__ __forceinline__ void load_a_chunk(uint32_t sb, int tile, int chunk,
                                             int buf, int tid)
{
    const char* nbh = (const char*)d_NBh + (size_t)tile * 32768 + chunk * 64;
    const char* nbl = (const char*)d_NBl + (size_t)tile * 32768 + chunk * 64;
    const uint32_t Ab = sb + LQ_A + buf * 20480u;
#pragma unroll
    for (int ii = 0; ii < 2; ii++) {
        int lin = tid + 256 * ii;
        int row = lin >> 2, c4 = lin & 3;
        uint32_t so = row * 80u + c4 * 16u;
        size_t go = (size_t)row * 256 + c4 * 16;
        CP16(Ab + so, nbh + go);
        CP16(Ab + 10240u + so, nbl + go);
    }
    CP_COMMIT();
}

__device__ __forceinline__ void mma_chunk(uint32_t sb, int buf, uint32_t aoff,
                                          uint32_t boff, float (&acc)[2][4][4])
{
    const uint32_t Abase = sb + LQ_A + buf * 20480u;
#pragma unroll
    for (int ks = 0; ks < 2; ks++) {
        uint32_t ah[2][4], al[2][4], bh[4][2], bl[4][2];
        const uint32_t Aa = Abase + aoff + ks * 32;
        ldsm_x4(ah[0][0], ah[0][1], ah[0][2], ah[0][3], Aa);
        ldsm_x4(ah[1][0], ah[1][1], ah[1][2], ah[1][3], Aa + 16 * 80);
        ldsm_x4(al[0][0], al[0][1], al[0][2], al[0][3], Aa + 10240);
        ldsm_x4(al[1][0], al[1][1], al[1][2], al[1][3], Aa + 10240 + 16 * 80);
        const uint32_t Bh = sb + LQ_WH + boff + ks * 32;
        const uint32_t Bl = sb + LQ_WL + boff + ks * 32;
        ldsm_x4(bh[0][0], bh[0][1], bh[1][0], bh[1][1], Bh);
        ldsm_x4(bh[2][0], bh[2][1], bh[3][0], bh[3][1], Bh + 16 * 272);
        ldsm_x4(bl[0][0], bl[0][1], bl[1][0], bl[1][1], Bl);
        ldsm_x4(bl[2][0], bl[2][1], bl[3][0], bl[3][1], Bl + 16 * 272);
#pragma unroll
        for (int i = 0; i < 2; i++)
#pragma unroll
            for (int j = 0; j < 4; j++) {
                MMA16816(acc[i][j], ah[i], bh[j]);
                MMA16816(acc[i][j], ah[i], bl[j]);
                MMA16816(acc[i][j], al[i], bh[j]);
            }
    }
}

__global__ __launch_bounds__(256, 2)
void lb_fused_kernel(const float* __restrict__ feat)
{
    extern __shared__ __align__(16) char sm[];
    const uint32_t sb = smem_u32(sm);
    float* Ct = (float*)(sm + LQ_CT);
    int* sgi = (int*)(sm + LQ_GI);

    const int tid = threadIdx.x;
    const int wid = tid >> 5, lane = tid & 31;
    const int wm = wid >> 1, wn = wid & 1;
    const int g = lane >> 2, tg = lane & 3;
    const int ri = lane & 7, mi = lane >> 3;
    const int q = blockIdx.x & 3;
    const int tile0 = blockIdx.x >> 2;

    // W quarter resident (64 N-rows x 128 K, hi+lo)
    for (int lin = tid; lin < 1024; lin += 256) {
        int row = lin >> 4, ch = lin & 15;
        size_t wi = (size_t)(q * 64 + row) * 16 + ch;
        uint32_t so = row * 272u + ch * 16u;
        CP16(sb + LQ_WH + so, (const char*)d_Wth + wi * 16);
        CP16(sb + LQ_WL + so, (const char*)d_Wtl + wi * 16);
    }
    CP_COMMIT();
    CP_WAIT(0);
    __syncthreads();

    const uint32_t aoff = (uint32_t)((wm * 32 + (mi & 1) * 8 + ri) * 80 + (mi >> 1) * 16);
    const uint32_t boffB = (uint32_t)((wn * 32 + (mi >> 1) * 8 + ri) * 272 + (mi & 1) * 16);

    // Prologue: first tile's chunks 0,1 in flight        pending = {c0, c1}
    load_a_chunk(sb, tile0, 0, 0, tid);
    load_a_chunk(sb, tile0, 1, 1, tid);

    int it = 0;
    for (int tile = tile0; tile < NTILES; tile += 148, it++) {
        const int cur = it & 1;
        int* sg = sgi + cur * 128;                 // double-buffered indices
        if (tid < 128) sg[tid] = d_GI[tile * 128 + tid];
        __syncthreads();                           // Ct free; sg visible

        // F1 quarter gather -> Ct                 pending = {c0, c1, F1}
        const char* F1c = (const char*)d_F1;
#pragma unroll
        for (int ii = 0; ii < 8; ii++) {
            int lin = tid + 256 * ii;
            int r = lin >> 4, c4 = lin & 15;
            int gi = sg[r];
            CP16(sb + LQ_CT + r * 272 + c4 * 16,
                 F1c + (size_t)gi * 1024 + q * 256 + c4 * 16);
        }
        CP_COMMIT();

        const int nt = (tile + 148 < NTILES) ? (tile + 148) : tile0;  // dummy-safe

        float acc[2][4][4];
#pragma unroll
        for (int i = 0; i < 2; i++)
#pragma unroll
            for (int j = 0; j < 4; j++)
#pragma unroll
                for (int c = 0; c < 4; c++) acc[i][j][c] = 0.f;

        CP_WAIT(2); __syncthreads();               // c0 ready
        mma_chunk(sb, 0, aoff, boffB + 0 * 64, acc);
        __syncthreads();
        load_a_chunk(sb, tile, 2, 0, tid);         // pending {c1, F1, c2}

        CP_WAIT(2); __syncthreads();               // c1 ready
        mma_chunk(sb, 1, aoff, boffB + 1 * 64, acc);
        __syncthreads();
        load_a_chunk(sb, tile, 3, 1, tid);         // pending {F1, c2, c3}

        CP_WAIT(1); __syncthreads();               // F1 + c2 ready
        mma_chunk(sb, 0, aoff, boffB + 2 * 64, acc);
        __syncthreads();
        load_a_chunk(sb, nt, 0, 0, tid);           // pending {c3, c0'}

        CP_WAIT(1); __syncthreads();               // c3 ready
        mma_chunk(sb, 1, aoff, boffB + 3 * 64, acc);
        __syncthreads();
        load_a_chunk(sb, nt, 1, 1, tid);           // pending {c0', c1'}

        // epilogue: Ct += acc (F1 already arrived + sync'd)
#pragma unroll
        for (int i = 0; i < 2; i++) {
            const int r0 = wm * 32 + i * 16 + g;
#pragma unroll
            for (int j = 0; j < 4; j++) {
                const int c = wn * 32 + j * 8 + 2 * tg;
                float2* p0 = (float2*)(Ct + r0 * 68 + c);
                float2* p1 = (float2*)(Ct + (r0 + 8) * 68 + c);
                float2 v0 = *p0, v1 = *p1;
                v0.x += acc[i][j][0]; v0.y += acc[i][j][1];
                v1.x += acc[i][j][2]; v1.y += acc[i][j][3];
                *p0 = v0; *p1 = v1;
            }
        }
        __syncthreads();                           // Ct complete

        // softmax over K per (point, col) + pool; sources from gmem (L2-hot)
#pragma unroll
        for (int s = 0; s < 2; s++) {
            const int pid = tid + 256 * s;
            const int pt = pid >> 6, lc = pid & 63;
            const float* ctp = Ct + pt * 16 * 68 + lc;
            float l[KK];
#pragma unroll
            for (int k = 0; k < KK; k++) l[k] = ctp[k * 68];
            float m = l[0];
#pragma unroll
            for (int k = 1; k < KK; k++) m = fmaxf(m, l[k]);
            float sum = 0.f;
#pragma unroll
            for (int k = 0; k < KK; k++) { l[k] = __expf(l[k] - m); sum += l[k]; }
            float inv = __frcp_rn(sum);

            float pooled = 0.f;
            if (q < 2) {
                const int* gp = sg + pt * 16;
#pragma unroll
                for (int k = 0; k < KK; k++)
                    pooled += l[k] * __ldg(feat + (size_t)gp[k] * 128 + q * 64 + lc);
            } else {
                const size_t base = (size_t)(tile * 128 + pt * 16) * 128 + (q - 2) * 64 + lc;
#pragma unroll
                for (int k = 0; k < KK; k++)
                    pooled += l[k] * (__bfloat162float(d_NBh[base + (size_t)k * 128]) +
                                      __bfloat162float(d_NBl[base + (size_t)k * 128]));
            }
            pooled *= inv;
            size_t o = (size_t)(tile * 8 + pt) * 384 + 128 + q * 64 + lc;
            __nv_bfloat16 hi = __float2bfloat16(pooled);
            d_CATh[o] = hi;
            d_CATl[o] = __float2bfloat16(pooled - __bfloat162float(hi));
        }
        // no trailing sync: loop-top sync protects Ct / sg
    }
}

// ---------------------------------------------------------------------------
// Launch
// ---------------------------------------------------------------------------
extern "C" void kernel_launch(void* const* d_in, const int* in_sizes, int n_in,
                              void* d_out, int out_size)
{
    const float* feature = (const float*)d_in[0];
    const float* raw     = (const float*)d_in[1];
    const void*  nidx    = d_in[2];
    const float* w_n     = (const float*)d_in[3];
    const float* b_n     = (const float*)d_in[4];
    const float* g_n     = (const float*)d_in[5];
    const float* beta_n  = (const float*)d_in[6];
    const float* rm_n    = (const float*)d_in[7];
    const float* rv_n    = (const float*)d_in[8];
    const float* w_attn  = (const float*)d_in[9];
    const float* w_o     = (const float*)d_in[10];
    const float* b_o     = (const float*)d_in[11];
    const float* g_o     = (const float*)d_in[12];
    const float* beta_o  = (const float*)d_in[13];
    const float* rm_o    = (const float*)d_in[14];
    const float* rv_o    = (const float*)d_in[15];
    const float* w_s     = (const float*)d_in[16];
    const float* b_s     = (const float*)d_in[17];
    const float* g_s     = (const float*)d_in[18];
    const float* beta_s  = (const float*)d_in[19];
    const float* rm_s    = (const float*)d_in[20];
    const float* rv_s    = (const float*)d_in[21];
    float* out = (float*)d_out;

    float *pF1, *pFold;
    __nv_bfloat16 *pCATh, *pCATl, *pWAh, *pWAl, *pWSOh, *pWSOl;
    cudaGetSymbolAddress((void**)&pF1, d_F1);
    cudaGetSymbolAddress((void**)&pFold, d_fold);
    cudaGetSymbolAddress((void**)&pCATh, d_CATh);
    cudaGetSymbolAddress((void**)&pCATl, d_CATl);
    cudaGetSymbolAddress((void**)&pWAh, d_WAh);
    cudaGetSymbolAddress((void**)&pWAl, d_WAl);
    cudaGetSymbolAddress((void**)&pWSOh, d_WSOh);
    cudaGetSymbolAddress((void**)&pWSOl, d_WSOl);

    cudaFuncSetAttribute(hmma_gemm, cudaFuncAttributeMaxDynamicSharedMemorySize, G_SMEM);
    cudaFuncSetAttribute(lb_fused_kernel, cudaFuncAttributeMaxDynamicSharedMemorySize, LQ_TOT);

    // 0: prep (fold + detect + all splits)
    prep_mega_kernel<<<642 + (PP * 128) / 256, 256>>>(
        w_attn, w_s, w_o, feature,
        b_n, g_n, beta_n, rm_n, rv_n,
        b_o, g_o, beta_o, rm_o, rv_o,
        b_s, g_s, beta_s, rm_s, rv_s, (const int*)nidx);
    // 1: idx conversion + NB -> gmem (bf16 hi/lo)
    neighconv_kernel<<<2048 + RR / 2, 256>>>(nidx, raw, w_n);
    // 2: F1 = feat @ w_attn_top
    hmma_gemm<<<dim3(PP / 64, 2), 256, G_SMEM>>>(pCATh, pCATl, 48, pWAh, pWAl, 16,
                                                 pF1, 128, 0, nullptr);
    // 3: fused LB GEMM + gather + softmax + pool -> CAT[128:384]  (ncu target)
    lb_fused_kernel<<<592, 256, LQ_TOT>>>(feature);
    // 4: out = lrelu([feat|PL] @ WSO + t_so)
    hmma_gemm<<<dim3(PP / 64, 2), 256, G_SMEM>>>(pCATh, pCATl, 48, pWSOh, pWSOl, 48,
                                                 out, 384, 3, pFold + 2 * 256);
}

// round 12
// speedup vs baseline: 2.2622x; 1.1197x over previous
#include <cuda_runtime.h>
#include <cuda_bf16.h>
#include <cstdint>

// Problem constants (fixed instance)
#define BB   4
#define NN   8192
#define KK   16
#define CG   10
#define PP   32768
#define RR   524288
#define NTILES 4096

// ---------------------------------------------------------------------------
// Scratch
// ---------------------------------------------------------------------------
__device__ float d_F1[(size_t)PP * 256];                       // feat @ w_attn_top
__device__ __nv_bfloat16 d_NBh[(size_t)RR * 128];              // neigh hi
__device__ __nv_bfloat16 d_NBl[(size_t)RR * 128];              // neigh lo
__device__ __nv_bfloat16 d_CATh[(size_t)PP * 384];             // [feat | PL] hi
__device__ __nv_bfloat16 d_CATl[(size_t)PP * 384];             // [feat | PL] lo
__device__ __nv_bfloat16 d_WAh[256 * 128], d_WAl[256 * 128];   // w_attn_top^T
__device__ __nv_bfloat16 d_Wth[256 * 128], d_Wtl[256 * 128];   // w_attn_bot^T
__device__ __nv_bfloat16 d_WSOh[256 * 384], d_WSOl[256 * 384]; // [w_s*s_s ; w_o*s_o]^T
__device__ int   d_GI[RR];
__device__ int   d_idx64;
__device__ float d_fold[3][256];   // 0=s_n 1=t_n 2=t_so

__device__ __forceinline__ float lrelu(float x) { return fmaxf(x, 0.2f * x); }

__device__ __forceinline__ uint32_t smem_u32(const void* p) {
    uint32_t a;
    asm("{ .reg .u64 t; cvta.to.shared.u64 t, %1; cvt.u32.u64 %0, t; }" : "=r"(a) : "l"(p));
    return a;
}
__device__ __forceinline__ void ldsm_x4(uint32_t& r0, uint32_t& r1, uint32_t& r2,
                                        uint32_t& r3, uint32_t addr) {
    asm volatile("ldmatrix.sync.aligned.m8n8.x4.shared.b16 {%0,%1,%2,%3}, [%4];"
                 : "=r"(r0), "=r"(r1), "=r"(r2), "=r"(r3) : "r"(addr));
}
#define CP16(dst, src)  asm volatile("cp.async.cg.shared.global [%0], [%1], 16;" :: "r"(dst), "l"(src))
#define CP_COMMIT()     asm volatile("cp.async.commit_group;" ::: "memory")
#define CP_WAIT(n)      asm volatile("cp.async.wait_group %0;" :: "n"(n) : "memory")
#define MMA16816(acc, a, b)                                                   \
    asm volatile("mma.sync.aligned.m16n8k16.row.col.f32.bf16.bf16.f32 "       \
                 "{%0,%1,%2,%3}, {%4,%5,%6,%7}, {%8,%9}, {%0,%1,%2,%3};"      \
                 : "+f"((acc)[0]), "+f"((acc)[1]), "+f"((acc)[2]), "+f"((acc)[3]) \
                 : "r"((a)[0]), "r"((a)[1]), "r"((a)[2]), "r"((a)[3]),        \
                   "r"((b)[0]), "r"((b)[1]))

// ---------------------------------------------------------------------------
// Launch 0: mega prep. b0: fold, b1: idx-detect, b2..641: weight splits,
// b642..1825: feature split (grid-stride).
// ---------------------------------------------------------------------------
#define PREP_FEAT_BLKS 1184
__global__ void prep_mega_kernel(
    const float* __restrict__ w_attn, const float* __restrict__ w_s,
    const float* __restrict__ w_o, const float* __restrict__ feat,
    const float* __restrict__ bn_, const float* __restrict__ gn,
    const float* __restrict__ betan, const float* __restrict__ rmn, const float* __restrict__ rvn,
    const float* __restrict__ bo, const float* __restrict__ go,
    const float* __restrict__ betao, const float* __restrict__ rmo, const float* __restrict__ rvo,
    const float* __restrict__ bs, const float* __restrict__ gs,
    const float* __restrict__ betas, const float* __restrict__ rms, const float* __restrict__ rvs,
    const int* __restrict__ widx)
{
    const int b = blockIdx.x, t = threadIdx.x;
    if (b == 0) {
        int i = t;
        if (i < 128) {
            float s = gn[i] * rsqrtf(rvn[i] + 1e-5f);
            d_fold[0][i] = s;
            d_fold[1][i] = (bn_[i] - rmn[i]) * s + betan[i];
        }
        if (i < 256) {
            float so = go[i] * rsqrtf(rvo[i] + 1e-5f);
            float ss = gs[i] * rsqrtf(rvs[i] + 1e-5f);
            d_fold[2][i] = (bo[i] - rmo[i]) * so + betao[i]
                         + (bs[i] - rms[i]) * ss + betas[i];
        }
        return;
    }
    if (b == 1) {
        __shared__ int ok;
        if (t == 0) ok = 1;
        __syncthreads();
        for (int i = t; i < 2048; i += blockDim.x)
            if (widx[2 * i + 1] != 0) ok = 0;
        __syncthreads();
        if (t == 0) d_idx64 = ok;
        return;
    }
    if (b < 130) {               // WA^T: w_attn rows 0-127
        int i = (b - 2) * 256 + t;
        int n = i >> 7, k = i & 127;
        float v = w_attn[(size_t)k * 256 + n];
        __nv_bfloat16 hi = __float2bfloat16(v);
        d_WAh[i] = hi;
        d_WAl[i] = __float2bfloat16(v - __bfloat162float(hi));
        return;
    }
    if (b < 258) {               // Wt^T: w_attn rows 128-255
        int i = (b - 130) * 256 + t;
        int n = i >> 7, k = i & 127;
        float v = w_attn[(size_t)(128 + k) * 256 + n];
        __nv_bfloat16 hi = __float2bfloat16(v);
        d_Wth[i] = hi;
        d_Wtl[i] = __float2bfloat16(v - __bfloat162float(hi));
        return;
    }
    if (b < 642) {               // WSO^T [256][384], BN scale folded
        int i = (b - 258) * 256 + t;
        int n = i / 384, k = i % 384;
        float v;
        if (k < 128) v = w_s[(size_t)k * 256 + n] * (gs[n] * rsqrtf(rvs[n] + 1e-5f));
        else         v = w_o[(size_t)(k - 128) * 256 + n] * (go[n] * rsqrtf(rvo[n] + 1e-5f));
        __nv_bfloat16 hi = __float2bfloat16(v);
        d_WSOh[i] = hi;
        d_WSOl[i] = __float2bfloat16(v - __bfloat162float(hi));
        return;
    }
    // feature split into CAT cols 0-127: grid-stride over PP*128 elements
    for (int i = (b - 642) * 256 + t; i < PP * 128; i += PREP_FEAT_BLKS * 256) {
        int m = i >> 7, k = i & 127;
        float v = feat[i];
        __nv_bfloat16 hi = __float2bfloat16(v);
        size_t o = (size_t)m * 384 + k;
        d_CATh[o] = hi;
        d_CATl[o] = __float2bfloat16(v - __bfloat162float(hi));
    }
}

// ---------------------------------------------------------------------------
// Launch 1: idx conversion (blocks 0..2047, one shot) + NB compute
// (blocks 2048.., grid-stride over row pairs).
// ---------------------------------------------------------------------------
#define NB_BLKS 2368
__global__ void neighconv_kernel(const void* __restrict__ nidx,
                                 const float* __restrict__ raw,
                                 const float* __restrict__ wn_)
{
    const int b = blockIdx.x, t = threadIdx.x;
    if (b < 2048) {
        int r = b * 256 + t;
        long long v;
        if (d_idx64) v = ((const long long*)nidx)[r];
        else         v = (long long)((const int*)nidx)[r];
        int vi = (int)v;
        vi = min(max(vi, 0), NN - 1);
        int batch = r / (NN * KK);
        d_GI[r] = batch * NN + vi;
        return;
    }
    // NB: grid-stride; per-thread column constants hoisted
    const int c = t & 127;
    const int rh = t >> 7;
    float wcol[CG];
#pragma unroll
    for (int g = 0; g < CG; g++) wcol[g] = wn_[g * 128 + c];
    const float sc = d_fold[0][c], tc = d_fold[1][c];

    for (int rp = b - 2048; rp < RR / 2; rp += NB_BLKS) {
        int r = rp * 2 + rh;
        const float* rr = raw + (size_t)r * CG;
        float acc = 0.f;
#pragma unroll
        for (int g = 0; g < CG; g++) acc += rr[g] * wcol[g];
        float v = lrelu(acc * sc + tc);
        __nv_bfloat16 hi = __float2bfloat16(v);
        size_t o = (size_t)r * 128 + c;
        d_NBh[o] = hi;
        d_NBl[o] = __float2bfloat16(v - __bfloat162float(hi));
    }
}

// ---------------------------------------------------------------------------
// Generic HMMA GEMM, BM=64, 2 CTAs/SM (unchanged from R11)
// ---------------------------------------------------------------------------
#define G_SMEM 104448
__global__ __launch_bounds__(256, 2)
void hmma_gemm(const __nv_bfloat16* __restrict__ Ah, const __nv_bfloat16* __restrict__ Al,
               int sA,
               const __nv_bfloat16* __restrict__ Wh, const __nv_bfloat16* __restrict__ Wl,
               int sW,
               float* __restrict__ C, int Kd, int mode, const float* __restrict__ tv)
{
    extern __shared__ __align__(16) char sm[];
    const uint32_t sb = smem_u32(sm);
    const uint32_t aWH = sb, aWL = sb + 34816, aAH = sb + 69632, aAL = sb + 87040;

    const int tid = threadIdx.x;
    const int wid = tid >> 5, lane = tid & 31;
    const int wm = wid >> 2, wn = wid & 3;
    const int g = lane >> 2, tg = lane & 3;
    const int ri = lane & 7, mi = lane >> 3;
    const int m0 = blockIdx.x * 64;
    const int half = blockIdx.y;

    float acc[2][4][4];
#pragma unroll
    for (int i = 0; i < 2; i++)
#pragma unroll
        for (int j = 0; j < 4; j++)
#pragma unroll
            for (int c = 0; c < 4; c++) acc[i][j][c] = 0.f;

    const uint32_t aoff = (uint32_t)((wm * 32 + (mi & 1) * 8 + ri) * 272 + (mi >> 1) * 16);
    const uint32_t boff = (uint32_t)((wn * 32 + (mi >> 1) * 8 + ri) * 272 + (mi & 1) * 16);

    for (int kt = 0; kt < (Kd >> 7); kt++) {
        if (kt > 0) __syncthreads();
        for (int lin = tid; lin < 2048; lin += 256) {
            int row = lin >> 4, ch = lin & 15;
            uint32_t so = row * 272u + ch * 16u;
            size_t wi = (size_t)(half * 128 + row) * sW + kt * 16 + ch;
            CP16(aWH + so, (const char*)Wh + wi * 16);
            CP16(aWL + so, (const char*)Wl + wi * 16);
            if (lin < 1024) {
                size_t ai = (size_t)(m0 + row) * sA + kt * 16 + ch;
                CP16(aAH + so, (const char*)Ah + ai * 16);
                CP16(aAL + so, (const char*)Al + ai * 16);
            }
        }
        CP_COMMIT();
        CP_WAIT(0);
        __syncthreads();
#pragma unroll
        for (int ks = 0; ks < 8; ks++) {
            const uint32_t k2 = ks * 32;
            uint32_t ah[2][4], al[2][4], bh[4][2], bl[4][2];
            ldsm_x4(ah[0][0], ah[0][1], ah[0][2], ah[0][3], aAH + aoff + k2);
            ldsm_x4(ah[1][0], ah[1][1], ah[1][2], ah[1][3], aAH + aoff + 16 * 272 + k2);
            ldsm_x4(al[0][0], al[0][1], al[0][2], al[0][3], aAL + aoff + k2);
            ldsm_x4(al[1][0], al[1][1], al[1][2], al[1][3], aAL + aoff + 16 * 272 + k2);
            ldsm_x4(bh[0][0], bh[0][1], bh[1][0], bh[1][1], aWH + boff + k2);
            ldsm_x4(bh[2][0], bh[2][1], bh[3][0], bh[3][1], aWH + boff + 16 * 272 + k2);
            ldsm_x4(bl[0][0], bl[0][1], bl[1][0], bl[1][1], aWL + boff + k2);
            ldsm_x4(bl[2][0], bl[2][1], bl[3][0], bl[3][1], aWL + boff + 16 * 272 + k2);
#pragma unroll
            for (int i = 0; i < 2; i++)
#pragma unroll
                for (int j = 0; j < 4; j++) {
                    MMA16816(acc[i][j], ah[i], bh[j]);
                    MMA16816(acc[i][j], ah[i], bl[j]);
                    MMA16816(acc[i][j], al[i], bh[j]);
                }
        }
    }

#pragma unroll
    for (int i = 0; i < 2; i++) {
        const int row0 = m0 + wm * 32 + i * 16 + g;
#pragma unroll
        for (int j = 0; j < 4; j++) {
            const int col = half * 128 + wn * 32 + j * 8 + 2 * tg;
            float2 v0 = make_float2(acc[i][j][0], acc[i][j][1]);
            float2 v1 = make_float2(acc[i][j][2], acc[i][j][3]);
            if (mode == 3) {
                float t0 = tv[col], t1 = tv[col + 1];
                v0.x = lrelu(v0.x + t0); v0.y = lrelu(v0.y + t1);
                v1.x = lrelu(v1.x + t0); v1.y = lrelu(v1.y + t1);
            }
            *(float2*)(C + (size_t)row0 * 256 + col) = v0;
            *(float2*)(C + (size_t)(row0 + 8) * 256 + col) = v1;
        }
    }
}

// ---------------------------------------------------------------------------
// Fused LB GEMM + softmax + pooling (unchanged from R11)
// ---------------------------------------------------------------------------
#define LQ_WH  0
#define LQ_WL  17408
#define LQ_A   34816
#define LQ_CT  75776
#define LQ_GI  110592
#define LQ_TOT 111616

__device__ __forceinline__ void load_a_chunk(uint32_t sb, int tile, int chunk,
                                             int buf, int tid)
{
    const char* nbh = (const char*)d_NBh + (size_t)tile * 32768 + chunk * 64;
    const char* nbl = (const char*)d_NBl + (size_t)tile * 32768 + chunk * 64;
    const uint32_t Ab = sb + LQ_A + buf * 20480u;
#pragma unroll
    for (int ii = 0; ii < 2; ii++) {
        int lin = tid + 256 * ii;
        int row = lin >> 2, c4 = lin & 3;
        uint32_t so = row * 80u + c4 * 16u;
        size_t go = (size_t)row * 256 + c4 * 16;
        CP16(Ab + so, nbh + go);
        CP16(Ab + 10240u + so, nbl + go);
    }
    CP_COMMIT();
}

__device__ __forceinline__ void mma_chunk(uint32_t sb, int buf, uint32_t aoff,
                                          uint32_t boff, float (&acc)[2][4][4])
{
    const uint32_t Abase = sb + LQ_A + buf * 20480u;
#pragma unroll
    for (int ks = 0; ks < 2; ks++) {
        uint32_t ah[2][4], al[2][4], bh[4][2], bl[4][2];
        const uint32_t Aa = Abase + aoff + ks * 32;
        ldsm_x4(ah[0][0], ah[0][1], ah[0][2], ah[0][3], Aa);
        ldsm_x4(ah[1][0], ah[1][1], ah[1][2], ah[1][3], Aa + 16 * 80);
        ldsm_x4(al[0][0], al[0][1], al[0][2], al[0][3], Aa + 10240);
        ldsm_x4(al[1][0], al[1][1], al[1][2], al[1][3], Aa + 10240 + 16 * 80);
        const uint32_t Bh = sb + LQ_WH + boff + ks * 32;
        const uint32_t Bl = sb + LQ_WL + boff + ks * 32;
        ldsm_x4(bh[0][0], bh[0][1], bh[1][0], bh[1][1], Bh);
        ldsm_x4(bh[2][0], bh[2][1], bh[3][0], bh[3][1], Bh + 16 * 272);
        ldsm_x4(bl[0][0], bl[0][1], bl[1][0], bl[1][1], Bl);
        ldsm_x4(bl[2][0], bl[2][1], bl[3][0], bl[3][1], Bl + 16 * 272);
#pragma unroll
        for (int i = 0; i < 2; i++)
#pragma unroll
            for (int j = 0; j < 4; j++) {
                MMA16816(acc[i][j], ah[i], bh[j]);
                MMA16816(acc[i][j], ah[i], bl[j]);
                MMA16816(acc[i][j], al[i], bh[j]);
            }
    }
}

__global__ __launch_bounds__(256, 2)
void lb_fused_kernel(const float* __restrict__ feat)
{
    extern __shared__ __align__(16) char sm[];
    const uint32_t sb = smem_u32(sm);
    float* Ct = (float*)(sm + LQ_CT);
    int* sgi = (int*)(sm + LQ_GI);

    const int tid = threadIdx.x;
    const int wid = tid >> 5, lane = tid & 31;
    const int wm = wid >> 1, wn = wid & 1;
    const int g = lane >> 2, tg = lane & 3;
    const int ri = lane & 7, mi = lane >> 3;
    const int q = blockIdx.x & 3;
    const int tile0 = blockIdx.x >> 2;

    for (int lin = tid; lin < 1024; lin += 256) {
        int row = lin >> 4, ch = lin & 15;
        size_t wi = (size_t)(q * 64 + row) * 16 + ch;
        uint32_t so = row * 272u + ch * 16u;
        CP16(sb + LQ_WH + so, (const char*)d_Wth + wi * 16);
        CP16(sb + LQ_WL + so, (const char*)d_Wtl + wi * 16);
    }
    CP_COMMIT();
    CP_WAIT(0);
    __syncthreads();

    const uint32_t aoff = (uint32_t)((wm * 32 + (mi & 1) * 8 + ri) * 80 + (mi >> 1) * 16);
    const uint32_t boffB = (uint32_t)((wn * 32 + (mi >> 1) * 8 + ri) * 272 + (mi & 1) * 16);

    load_a_chunk(sb, tile0, 0, 0, tid);
    load_a_chunk(sb, tile0, 1, 1, tid);

    int it = 0;
    for (int tile = tile0; tile < NTILES; tile += 148, it++) {
        const int cur = it & 1;
        int* sg = sgi + cur * 128;
        if (tid < 128) sg[tid] = d_GI[tile * 128 + tid];
        __syncthreads();

        const char* F1c = (const char*)d_F1;
#pragma unroll
        for (int ii = 0; ii < 8; ii++) {
            int lin = tid + 256 * ii;
            int r = lin >> 4, c4 = lin & 15;
            int gi = sg[r];
            CP16(sb + LQ_CT + r * 272 + c4 * 16,
                 F1c + (size_t)gi * 1024 + q * 256 + c4 * 16);
        }
        CP_COMMIT();

        const int nt = (tile + 148 < NTILES) ? (tile + 148) : tile0;

        float acc[2][4][4];
#pragma unroll
        for (int i = 0; i < 2; i++)
#pragma unroll
            for (int j = 0; j < 4; j++)
#pragma unroll
                for (int c = 0; c < 4; c++) acc[i][j][c] = 0.f;

        CP_WAIT(2); __syncthreads();
        mma_chunk(sb, 0, aoff, boffB + 0 * 64, acc);
        __syncthreads();
        load_a_chunk(sb, tile, 2, 0, tid);

        CP_WAIT(2); __syncthreads();
        mma_chunk(sb, 1, aoff, boffB + 1 * 64, acc);
        __syncthreads();
        load_a_chunk(sb, tile, 3, 1, tid);

        CP_WAIT(1); __syncthreads();
        mma_chunk(sb, 0, aoff, boffB + 2 * 64, acc);
        __syncthreads();
        load_a_chunk(sb, nt, 0, 0, tid);

        CP_WAIT(1); __syncthreads();
        mma_chunk(sb, 1, aoff, boffB + 3 * 64, acc);
        __syncthreads();
        load_a_chunk(sb, nt, 1, 1, tid);

#pragma unroll
        for (int i = 0; i < 2; i++) {
            const int r0 = wm * 32 + i * 16 + g;
#pragma unroll
            for (int j = 0; j < 4; j++) {
                const int c = wn * 32 + j * 8 + 2 * tg;
                float2* p0 = (float2*)(Ct + r0 * 68 + c);
                float2* p1 = (float2*)(Ct + (r0 + 8) * 68 + c);
                float2 v0 = *p0, v1 = *p1;
                v0.x += acc[i][j][0]; v0.y += acc[i][j][1];
                v1.x += acc[i][j][2]; v1.y += acc[i][j][3];
                *p0 = v0; *p1 = v1;
            }
        }
        __syncthreads();

#pragma unroll
        for (int s = 0; s < 2; s++) {
            const int pid = tid + 256 * s;
            const int pt = pid >> 6, lc = pid & 63;
            const float* ctp = Ct + pt * 16 * 68 + lc;
            float l[KK];
#pragma unroll
            for (int k = 0; k < KK; k++) l[k] = ctp[k * 68];
            float m = l[0];
#pragma unroll
            for (int k = 1; k < KK; k++) m = fmaxf(m, l[k]);
            float sum = 0.f;
#pragma unroll
            for (int k = 0; k < KK; k++) { l[k] = __expf(l[k] - m); sum += l[k]; }
            float inv = __frcp_rn(sum);

            float pooled = 0.f;
            if (q < 2) {
                const int* gp = sg + pt * 16;
#pragma unroll
                for (int k = 0; k < KK; k++)
                    pooled += l[k] * __ldg(feat + (size_t)gp[k] * 128 + q * 64 + lc);
            } else {
                const size_t base = (size_t)(tile * 128 + pt * 16) * 128 + (q - 2) * 64 + lc;
#pragma unroll
                for (int k = 0; k < KK; k++)
                    pooled += l[k] * (__bfloat162float(d_NBh[base + (size_t)k * 128]) +
                                      __bfloat162float(d_NBl[base + (size_t)k * 128]));
            }
            pooled *= inv;
            size_t o = (size_t)(tile * 8 + pt) * 384 + 128 + q * 64 + lc;
            __nv_bfloat16 hi = __float2bfloat16(pooled);
            d_CATh[o] = hi;
            d_CATl[o] = __float2bfloat16(pooled - __bfloat162float(hi));
        }
    }
}

// ---------------------------------------------------------------------------
// Launch
// ---------------------------------------------------------------------------
extern "C" void kernel_launch(void* const* d_in, const int* in_sizes, int n_in,
                              void* d_out, int out_size)
{
    const float* feature = (const float*)d_in[0];
    const float* raw     = (const float*)d_in[1];
    const void*  nidx    = d_in[2];
    const float* w_n     = (const float*)d_in[3];
    const float* b_n     = (const float*)d_in[4];
    const float* g_n     = (const float*)d_in[5];
    const float* beta_n  = (const float*)d_in[6];
    const float* rm_n    = (const float*)d_in[7];
    const float* rv_n    = (const float*)d_in[8];
    const float* w_attn  = (const float*)d_in[9];
    const float* w_o     = (const float*)d_in[10];
    const float* b_o     = (const float*)d_in[11];
    const float* g_o     = (const float*)d_in[12];
    const float* beta_o  = (const float*)d_in[13];
    const float* rm_o    = (const float*)d_in[14];
    const float* rv_o    = (const float*)d_in[15];
    const float* w_s     = (const float*)d_in[16];
    const float* b_s     = (const float*)d_in[17];
    const float* g_s     = (const float*)d_in[18];
    const float* beta_s  = (const float*)d_in[19];
    const float* rm_s    = (const float*)d_in[20];
    const float* rv_s    = (const float*)d_in[21];
    float* out = (float*)d_out;

    float *pF1, *pFold;
    __nv_bfloat16 *pCATh, *pCATl, *pWAh, *pWAl, *pWSOh, *pWSOl;
    cudaGetSymbolAddress((void**)&pF1, d_F1);
    cudaGetSymbolAddress((void**)&pFold, d_fold);
    cudaGetSymbolAddress((void**)&pCATh, d_CATh);
    cudaGetSymbolAddress((void**)&pCATl, d_CATl);
    cudaGetSymbolAddress((void**)&pWAh, d_WAh);
    cudaGetSymbolAddress((void**)&pWAl, d_WAl);
    cudaGetSymbolAddress((void**)&pWSOh, d_WSOh);
    cudaGetSymbolAddress((void**)&pWSOl, d_WSOl);

    cudaFuncSetAttribute(hmma_gemm, cudaFuncAttributeMaxDynamicSharedMemorySize, G_SMEM);
    cudaFuncSetAttribute(lb_fused_kernel, cudaFuncAttributeMaxDynamicSharedMemorySize, LQ_TOT);

    // 0: prep (fold + detect + weight splits + grid-stride feature split)
    prep_mega_kernel<<<642 + PREP_FEAT_BLKS, 256>>>(
        w_attn, w_s, w_o, feature,
        b_n, g_n, beta_n, rm_n, rv_n,
        b_o, g_o, beta_o, rm_o, rv_o,
        b_s, g_s, beta_s, rm_s, rv_s, (const int*)nidx);
    // 1: idx conversion + NB (grid-stride) -> gmem (bf16 hi/lo)
    neighconv_kernel<<<2048 + NB_BLKS, 256>>>(nidx, raw, w_n);
    // 2: F1 = feat @ w_attn_top
    hmma_gemm<<<dim3(PP / 64, 2), 256, G_SMEM>>>(pCATh, pCATl, 48, pWAh, pWAl, 16,
                                                 pF1, 128, 0, nullptr);
    // 3: fused LB GEMM + gather + softmax + pool -> CAT[128:384]  (ncu target)
    lb_fused_kernel<<<592, 256, LQ_TOT>>>(feature);
    // 4: out = lrelu([feat|PL] @ WSO + t_so)
    hmma_gemm<<<dim3(PP / 64, 2), 256, G_SMEM>>>(pCATh, pCATl, 48, pWSOh, pWSOl, 48,
                                                 out, 384, 3, pFold + 2 * 256);
}

// round 13
// speedup vs baseline: 2.8642x; 1.2661x over previous
#include <cuda_runtime.h>
#include <cuda_fp16.h>
#include <cstdint>

// Problem constants (fixed instance)
#define BB   4
#define NN   8192
#define KK   16
#define CG   10
#define PP   32768
#define RR   524288
#define NTILES 4096

// ---------------------------------------------------------------------------
// Scratch. Activations: single fp16. Weights: fp16 hi/lo (2-pass exact-ish).
// ---------------------------------------------------------------------------
__device__ float  d_F1[(size_t)PP * 256];              // feat @ w_attn_top (fp32)
__device__ __half d_NB[(size_t)RR * 128];              // neigh (fp16)
__device__ __half d_CAT[(size_t)PP * 384];             // [feat | PL] (fp16)
__device__ __half d_WAh[256 * 128], d_WAl[256 * 128];  // w_attn_top^T hi/lo
__device__ __half d_Wth[256 * 128], d_Wtl[256 * 128];  // w_attn_bot^T hi/lo
__device__ __half d_WSOh[256 * 384], d_WSOl[256 * 384];// [w_s*s_s ; w_o*s_o]^T
__device__ int    d_GI[RR];
__device__ int    d_idx64;
__device__ float  d_fold[3][256];   // 0=s_n 1=t_n 2=t_so

__device__ __forceinline__ float lrelu(float x) { return fmaxf(x, 0.2f * x); }

__device__ __forceinline__ uint32_t smem_u32(const void* p) {
    uint32_t a;
    asm("{ .reg .u64 t; cvta.to.shared.u64 t, %1; cvt.u32.u64 %0, t; }" : "=r"(a) : "l"(p));
    return a;
}
__device__ __forceinline__ void ldsm_x4(uint32_t& r0, uint32_t& r1, uint32_t& r2,
                                        uint32_t& r3, uint32_t addr) {
    asm volatile("ldmatrix.sync.aligned.m8n8.x4.shared.b16 {%0,%1,%2,%3}, [%4];"
                 : "=r"(r0), "=r"(r1), "=r"(r2), "=r"(r3) : "r"(addr));
}
#define CP16(dst, src)  asm volatile("cp.async.cg.shared.global [%0], [%1], 16;" :: "r"(dst), "l"(src))
#define CP_COMMIT()     asm volatile("cp.async.commit_group;" ::: "memory")
#define CP_WAIT(n)      asm volatile("cp.async.wait_group %0;" :: "n"(n) : "memory")
#define MMAF16(acc, a, b)                                                     \
    asm volatile("mma.sync.aligned.m16n8k16.row.col.f32.f16.f16.f32 "         \
                 "{%0,%1,%2,%3}, {%4,%5,%6,%7}, {%8,%9}, {%0,%1,%2,%3};"      \
                 : "+f"((acc)[0]), "+f"((acc)[1]), "+f"((acc)[2]), "+f"((acc)[3]) \
                 : "r"((a)[0]), "r"((a)[1]), "r"((a)[2]), "r"((a)[3]),        \
                   "r"((b)[0]), "r"((b)[1]))

// ---------------------------------------------------------------------------
// Launch 0: mega prep. b0: fold, b1: idx-detect, b2..641: weight hi/lo splits,
// b642..: feature -> CAT cols 0-127 (fp16, grid-stride).
// ---------------------------------------------------------------------------
#define PREP_FEAT_BLKS 1184
__global__ void prep_mega_kernel(
    const float* __restrict__ w_attn, const float* __restrict__ w_s,
    const float* __restrict__ w_o, const float* __restrict__ feat,
    const float* __restrict__ bn_, const float* __restrict__ gn,
    const float* __restrict__ betan, const float* __restrict__ rmn, const float* __restrict__ rvn,
    const float* __restrict__ bo, const float* __restrict__ go,
    const float* __restrict__ betao, const float* __restrict__ rmo, const float* __restrict__ rvo,
    const float* __restrict__ bs, const float* __restrict__ gs,
    const float* __restrict__ betas, const float* __restrict__ rms, const float* __restrict__ rvs,
    const int* __restrict__ widx)
{
    const int b = blockIdx.x, t = threadIdx.x;
    if (b == 0) {
        int i = t;
        if (i < 128) {
            float s = gn[i] * rsqrtf(rvn[i] + 1e-5f);
            d_fold[0][i] = s;
            d_fold[1][i] = (bn_[i] - rmn[i]) * s + betan[i];
        }
        if (i < 256) {
            float so = go[i] * rsqrtf(rvo[i] + 1e-5f);
            float ss = gs[i] * rsqrtf(rvs[i] + 1e-5f);
            d_fold[2][i] = (bo[i] - rmo[i]) * so + betao[i]
                         + (bs[i] - rms[i]) * ss + betas[i];
        }
        return;
    }
    if (b == 1) {
        __shared__ int ok;
        if (t == 0) ok = 1;
        __syncthreads();
        for (int i = t; i < 2048; i += blockDim.x)
            if (widx[2 * i + 1] != 0) ok = 0;
        __syncthreads();
        if (t == 0) d_idx64 = ok;
        return;
    }
    if (b < 130) {               // WA^T: w_attn rows 0-127
        int i = (b - 2) * 256 + t;
        int n = i >> 7, k = i & 127;
        float v = w_attn[(size_t)k * 256 + n];
        __half hi = __float2half(v);
        d_WAh[i] = hi;
        d_WAl[i] = __float2half(v - __half2float(hi));
        return;
    }
    if (b < 258) {               // Wt^T: w_attn rows 128-255
        int i = (b - 130) * 256 + t;
        int n = i >> 7, k = i & 127;
        float v = w_attn[(size_t)(128 + k) * 256 + n];
        __half hi = __float2half(v);
        d_Wth[i] = hi;
        d_Wtl[i] = __float2half(v - __half2float(hi));
        return;
    }
    if (b < 642) {               // WSO^T [256][384], BN scale folded
        int i = (b - 258) * 256 + t;
        int n = i / 384, k = i % 384;
        float v;
        if (k < 128) v = w_s[(size_t)k * 256 + n] * (gs[n] * rsqrtf(rvs[n] + 1e-5f));
        else         v = w_o[(size_t)(k - 128) * 256 + n] * (go[n] * rsqrtf(rvo[n] + 1e-5f));
        __half hi = __float2half(v);
        d_WSOh[i] = hi;
        d_WSOl[i] = __float2half(v - __half2float(hi));
        return;
    }
    // feature -> CAT cols 0-127 (fp16), grid-stride
    for (int i = (b - 642) * 256 + t; i < PP * 128; i += PREP_FEAT_BLKS * 256) {
        int m = i >> 7, k = i & 127;
        d_CAT[(size_t)m * 384 + k] = __float2half(feat[i]);
    }
}

// ---------------------------------------------------------------------------
// Launch 1: idx conversion (blocks 0..2047) + NB (grid-stride, fp16 single)
// ---------------------------------------------------------------------------
#define NB_BLKS 2368
__global__ void neighconv_kernel(const void* __restrict__ nidx,
                                 const float* __restrict__ raw,
                                 const float* __restrict__ wn_)
{
    const int b = blockIdx.x, t = threadIdx.x;
    if (b < 2048) {
        int r = b * 256 + t;
        long long v;
        if (d_idx64) v = ((const long long*)nidx)[r];
        else         v = (long long)((const int*)nidx)[r];
        int vi = (int)v;
        vi = min(max(vi, 0), NN - 1);
        int batch = r / (NN * KK);
        d_GI[r] = batch * NN + vi;
        return;
    }
    const int c = t & 127;
    const int rh = t >> 7;
    float wcol[CG];
#pragma unroll
    for (int g = 0; g < CG; g++) wcol[g] = wn_[g * 128 + c];
    const float sc = d_fold[0][c], tc = d_fold[1][c];

    for (int rp = b - 2048; rp < RR / 2; rp += NB_BLKS) {
        int r = rp * 2 + rh;
        const float* rr = raw + (size_t)r * CG;
        float acc = 0.f;
#pragma unroll
        for (int g = 0; g < CG; g++) acc += rr[g] * wcol[g];
        float v = lrelu(acc * sc + tc);
        d_NB[(size_t)r * 128 + c] = __float2half(v);
    }
}

// ---------------------------------------------------------------------------
// Generic HMMA GEMM (fp16 2-pass), BM=64, 2 CTAs/SM:
//   C[M,256] = A[M,Kd](fp16) @ (Wh+Wl)^T, W stored [256][Kd] fp16.
// smem: WH 0 (34816) | WL 34816 | A 69632 (17408) -> 87040 B
// warps 2(M) x 4(N), warp tile 32x32. mode 0: C=acc  mode 3: C=lrelu(acc+tv)
// ---------------------------------------------------------------------------
#define G_SMEM 87040
__global__ __launch_bounds__(256, 2)
void hmma_gemm(const __half* __restrict__ A, int sA,
               const __half* __restrict__ Wh, const __half* __restrict__ Wl,
               int sW,
               float* __restrict__ C, int Kd, int mode, const float* __restrict__ tv)
{
    extern __shared__ __align__(16) char sm[];
    const uint32_t sb = smem_u32(sm);
    const uint32_t aWH = sb, aWL = sb + 34816, aA = sb + 69632;

    const int tid = threadIdx.x;
    const int wid = tid >> 5, lane = tid & 31;
    const int wm = wid >> 2, wn = wid & 3;
    const int g = lane >> 2, tg = lane & 3;
    const int ri = lane & 7, mi = lane >> 3;
    const int m0 = blockIdx.x * 64;
    const int half = blockIdx.y;

    float acc[2][4][4];
#pragma unroll
    for (int i = 0; i < 2; i++)
#pragma unroll
        for (int j = 0; j < 4; j++)
#pragma unroll
            for (int c = 0; c < 4; c++) acc[i][j][c] = 0.f;

    const uint32_t aoff = (uint32_t)((wm * 32 + (mi & 1) * 8 + ri) * 272 + (mi >> 1) * 16);
    const uint32_t boff = (uint32_t)((wn * 32 + (mi >> 1) * 8 + ri) * 272 + (mi & 1) * 16);

    for (int kt = 0; kt < (Kd >> 7); kt++) {
        if (kt > 0) __syncthreads();
        for (int lin = tid; lin < 2048; lin += 256) {
            int row = lin >> 4, ch = lin & 15;
            uint32_t so = row * 272u + ch * 16u;
            size_t wi = (size_t)(half * 128 + row) * sW + kt * 16 + ch;
            CP16(aWH + so, (const char*)Wh + wi * 16);
            CP16(aWL + so, (const char*)Wl + wi * 16);
            if (lin < 1024) {
                size_t ai = (size_t)(m0 + row) * sA + kt * 16 + ch;
                CP16(aA + so, (const char*)A + ai * 16);
            }
        }
        CP_COMMIT();
        CP_WAIT(0);
        __syncthreads();
#pragma unroll
        for (int ks = 0; ks < 8; ks++) {
            const uint32_t k2 = ks * 32;
            uint32_t a[2][4], bh[4][2], bl[4][2];
            ldsm_x4(a[0][0], a[0][1], a[0][2], a[0][3], aA + aoff + k2);
            ldsm_x4(a[1][0], a[1][1], a[1][2], a[1][3], aA + aoff + 16 * 272 + k2);
            ldsm_x4(bh[0][0], bh[0][1], bh[1][0], bh[1][1], aWH + boff + k2);
            ldsm_x4(bh[2][0], bh[2][1], bh[3][0], bh[3][1], aWH + boff + 16 * 272 + k2);
            ldsm_x4(bl[0][0], bl[0][1], bl[1][0], bl[1][1], aWL + boff + k2);
            ldsm_x4(bl[2][0], bl[2][1], bl[3][0], bl[3][1], aWL + boff + 16 * 272 + k2);
#pragma unroll
            for (int i = 0; i < 2; i++)
#pragma unroll
                for (int j = 0; j < 4; j++) {
                    MMAF16(acc[i][j], a[i], bh[j]);
                    MMAF16(acc[i][j], a[i], bl[j]);
                }
        }
    }

#pragma unroll
    for (int i = 0; i < 2; i++) {
        const int row0 = m0 + wm * 32 + i * 16 + g;
#pragma unroll
        for (int j = 0; j < 4; j++) {
            const int col = half * 128 + wn * 32 + j * 8 + 2 * tg;
            float2 v0 = make_float2(acc[i][j][0], acc[i][j][1]);
            float2 v1 = make_float2(acc[i][j][2], acc[i][j][3]);
            if (mode == 3) {
                float t0 = tv[col], t1 = tv[col + 1];
                v0.x = lrelu(v0.x + t0); v0.y = lrelu(v0.y + t1);
                v1.x = lrelu(v1.x + t0); v1.y = lrelu(v1.y + t1);
            }
            *(float2*)(C + (size_t)row0 * 256 + col) = v0;
            *(float2*)(C + (size_t)(row0 + 8) * 256 + col) = v1;
        }
    }
}

// ---------------------------------------------------------------------------
// Fused LB GEMM (fp16 2-pass) + softmax + pooling, N-quartered.
// grid = 592, 256 threads, 2 CTAs/SM.
// smem (91136 B): WH 0 (17408) | WL 17408 | A 34816 (2 bufs x 10240) |
//                 Ct 55296 (128x68 f32 = 34816) | sgi 90112 (2x512)
// ---------------------------------------------------------------------------
#define LQ_WH  0
#define LQ_WL  17408
#define LQ_A   34816
#define LQ_CT  55296
#define LQ_GI  90112
#define LQ_TOT 91136

__device__ __forceinline__ void load_a_chunk(uint32_t sb, int tile, int chunk,
                                             int buf, int tid)
{
    const char* nb = (const char*)d_NB + (size_t)tile * 32768 + chunk * 64;
    const uint32_t Ab = sb + LQ_A + buf * 10240u;
#pragma unroll
    for (int ii = 0; ii < 2; ii++) {
        int lin = tid + 256 * ii;             // 0..511
        int row = lin >> 2, c4 = lin & 3;
        CP16(Ab + row * 80u + c4 * 16u, nb + (size_t)row * 256 + c4 * 16);
    }
    CP_COMMIT();
}

__device__ __forceinline__ void mma_chunk(uint32_t sb, int buf, uint32_t aoff,
                                          uint32_t boff, float (&acc)[2][4][4])
{
    const uint32_t Abase = sb + LQ_A + buf * 10240u;
#pragma unroll
    for (int ks = 0; ks < 2; ks++) {
        uint32_t a[2][4], bh[4][2], bl[4][2];
        const uint32_t Aa = Abase + aoff + ks * 32;
        ldsm_x4(a[0][0], a[0][1], a[0][2], a[0][3], Aa);
        ldsm_x4(a[1][0], a[1][1], a[1][2], a[1][3], Aa + 16 * 80);
        const uint32_t Bh = sb + LQ_WH + boff + ks * 32;
        const uint32_t Bl = sb + LQ_WL + boff + ks * 32;
        ldsm_x4(bh[0][0], bh[0][1], bh[1][0], bh[1][1], Bh);
        ldsm_x4(bh[2][0], bh[2][1], bh[3][0], bh[3][1], Bh + 16 * 272);
        ldsm_x4(bl[0][0], bl[0][1], bl[1][0], bl[1][1], Bl);
        ldsm_x4(bl[2][0], bl[2][1], bl[3][0], bl[3][1], Bl + 16 * 272);
#pragma unroll
        for (int i = 0; i < 2; i++)
#pragma unroll
            for (int j = 0; j < 4; j++) {
                MMAF16(acc[i][j], a[i], bh[j]);
                MMAF16(acc[i][j], a[i], bl[j]);
            }
    }
}

__global__ __launch_bounds__(256, 2)
void lb_fused_kernel(const float* __restrict__ feat)
{
    extern __shared__ __align__(16) char sm[];
    const uint32_t sb = smem_u32(sm);
    float* Ct = (float*)(sm + LQ_CT);
    int* sgi = (int*)(sm + LQ_GI);

    const int tid = threadIdx.x;
    const int wid = tid >> 5, lane = tid & 31;
    const int wm = wid >> 1, wn = wid & 1;
    const int g = lane >> 2, tg = lane & 3;
    const int ri = lane & 7, mi = lane >> 3;
    const int q = blockIdx.x & 3;
    const int tile0 = blockIdx.x >> 2;

    // W quarter resident (64 N-rows x 128 K, fp16 hi/lo)
    for (int lin = tid; lin < 1024; lin += 256) {
        int row = lin >> 4, ch = lin & 15;
        size_t wi = (size_t)(q * 64 + row) * 16 + ch;
        uint32_t so = row * 272u + ch * 16u;
        CP16(sb + LQ_WH + so, (const char*)d_Wth + wi * 16);
        CP16(sb + LQ_WL + so, (const char*)d_Wtl + wi * 16);
    }
    CP_COMMIT();
    CP_WAIT(0);
    __syncthreads();

    const uint32_t aoff = (uint32_t)((wm * 32 + (mi & 1) * 8 + ri) * 80 + (mi >> 1) * 16);
    const uint32_t boffB = (uint32_t)((wn * 32 + (mi >> 1) * 8 + ri) * 272 + (mi & 1) * 16);

    load_a_chunk(sb, tile0, 0, 0, tid);
    load_a_chunk(sb, tile0, 1, 1, tid);

    int it = 0;
    for (int tile = tile0; tile < NTILES; tile += 148, it++) {
        const int cur = it & 1;
        int* sg = sgi + cur * 128;
        if (tid < 128) sg[tid] = d_GI[tile * 128 + tid];
        __syncthreads();

        const char* F1c = (const char*)d_F1;
#pragma unroll
        for (int ii = 0; ii < 8; ii++) {
            int lin = tid + 256 * ii;
            int r = lin >> 4, c4 = lin & 15;
            int gi = sg[r];
            CP16(sb + LQ_CT + r * 272 + c4 * 16,
                 F1c + (size_t)gi * 1024 + q * 256 + c4 * 16);
        }
        CP_COMMIT();

        const int nt = (tile + 148 < NTILES) ? (tile + 148) : tile0;

        float acc[2][4][4];
#pragma unroll
        for (int i = 0; i < 2; i++)
#pragma unroll
            for (int j = 0; j < 4; j++)
#pragma unroll
                for (int c = 0; c < 4; c++) acc[i][j][c] = 0.f;

        CP_WAIT(2); __syncthreads();
        mma_chunk(sb, 0, aoff, boffB + 0 * 64, acc);
        __syncthreads();
        load_a_chunk(sb, tile, 2, 0, tid);

        CP_WAIT(2); __syncthreads();
        mma_chunk(sb, 1, aoff, boffB + 1 * 64, acc);
        __syncthreads();
        load_a_chunk(sb, tile, 3, 1, tid);

        CP_WAIT(1); __syncthreads();
        mma_chunk(sb, 0, aoff, boffB + 2 * 64, acc);
        __syncthreads();
        load_a_chunk(sb, nt, 0, 0, tid);

        CP_WAIT(1); __syncthreads();
        mma_chunk(sb, 1, aoff, boffB + 3 * 64, acc);
        __syncthreads();
        load_a_chunk(sb, nt, 1, 1, tid);

        // epilogue: Ct += acc (Ct holds gathered F1)
#pragma unroll
        for (int i = 0; i < 2; i++) {
            const int r0 = wm * 32 + i * 16 + g;
#pragma unroll
            for (int j = 0; j < 4; j++) {
                const int c = wn * 32 + j * 8 + 2 * tg;
                float2* p0 = (float2*)(Ct + r0 * 68 + c);
                float2* p1 = (float2*)(Ct + (r0 + 8) * 68 + c);
                float2 v0 = *p0, v1 = *p1;
                v0.x += acc[i][j][0]; v0.y += acc[i][j][1];
                v1.x += acc[i][j][2]; v1.y += acc[i][j][3];
                *p0 = v0; *p1 = v1;
            }
        }
        __syncthreads();

        // softmax over K per (point, col) + pool; sources from gmem (L2-hot)
#pragma unroll
        for (int s = 0; s < 2; s++) {
            const int pid = tid + 256 * s;
            const int pt = pid >> 6, lc = pid & 63;
            const float* ctp = Ct + pt * 16 * 68 + lc;
            float l[KK];
#pragma unroll
            for (int k = 0; k < KK; k++) l[k] = ctp[k * 68];
            float m = l[0];
#pragma unroll
            for (int k = 1; k < KK; k++) m = fmaxf(m, l[k]);
            float sum = 0.f;
#pragma unroll
            for (int k = 0; k < KK; k++) { l[k] = __expf(l[k] - m); sum += l[k]; }
            float inv = __frcp_rn(sum);

            float pooled = 0.f;
            if (q < 2) {
                const int* gp = sg + pt * 16;
#pragma unroll
                for (int k = 0; k < KK; k++)
                    pooled += l[k] * __ldg(feat + (size_t)gp[k] * 128 + q * 64 + lc);
            } else {
                const size_t base = (size_t)(tile * 128 + pt * 16) * 128 + (q - 2) * 64 + lc;
#pragma unroll
                for (int k = 0; k < KK; k++)
                    pooled += l[k] * __half2float(d_NB[base + (size_t)k * 128]);
            }
            pooled *= inv;
            d_CAT[(size_t)(tile * 8 + pt) * 384 + 128 + q * 64 + lc] = __float2half(pooled);
        }
    }
}

// ---------------------------------------------------------------------------
// Launch
// ---------------------------------------------------------------------------
extern "C" void kernel_launch(void* const* d_in, const int* in_sizes, int n_in,
                              void* d_out, int out_size)
{
    const float* feature = (const float*)d_in[0];
    const float* raw     = (const float*)d_in[1];
    const void*  nidx    = d_in[2];
    const float* w_n     = (const float*)d_in[3];
    const float* b_n     = (const float*)d_in[4];
    const float* g_n     = (const float*)d_in[5];
    const float* beta_n  = (const float*)d_in[6];
    const float* rm_n    = (const float*)d_in[7];
    const float* rv_n    = (const float*)d_in[8];
    const float* w_attn  = (const float*)d_in[9];
    const float* w_o     = (const float*)d_in[10];
    const float* b_o     = (const float*)d_in[11];
    const float* g_o     = (const float*)d_in[12];
    const float* beta_o  = (const float*)d_in[13];
    const float* rm_o    = (const float*)d_in[14];
    const float* rv_o    = (const float*)d_in[15];
    const float* w_s     = (const float*)d_in[16];
    const float* b_s     = (const float*)d_in[17];
    const float* g_s     = (const float*)d_in[18];
    const float* beta_s  = (const float*)d_in[19];
    const float* rm_s    = (const float*)d_in[20];
    const float* rv_s    = (const float*)d_in[21];
    float* out = (float*)d_out;

    float *pF1, *pFold;
    __half *pCAT, *pWAh, *pWAl, *pWSOh, *pWSOl;
    cudaGetSymbolAddress((void**)&pF1, d_F1);
    cudaGetSymbolAddress((void**)&pFold, d_fold);
    cudaGetSymbolAddress((void**)&pCAT, d_CAT);
    cudaGetSymbolAddress((void**)&pWAh, d_WAh);
    cudaGetSymbolAddress((void**)&pWAl, d_WAl);
    cudaGetSymbolAddress((void**)&pWSOh, d_WSOh);
    cudaGetSymbolAddress((void**)&pWSOl, d_WSOl);

    cudaFuncSetAttribute(hmma_gemm, cudaFuncAttributeMaxDynamicSharedMemorySize, G_SMEM);
    cudaFuncSetAttribute(lb_fused_kernel, cudaFuncAttributeMaxDynamicSharedMemorySize, LQ_TOT);

    // 0: prep (fold + detect + weight hi/lo splits + feature -> CAT fp16)
    prep_mega_kernel<<<642 + PREP_FEAT_BLKS, 256>>>(
        w_attn, w_s, w_o, feature,
        b_n, g_n, beta_n, rm_n, rv_n,
        b_o, g_o, beta_o, rm_o, rv_o,
        b_s, g_s, beta_s, rm_s, rv_s, (const int*)nidx);
    // 1: idx conversion + NB (grid-stride, fp16)
    neighconv_kernel<<<2048 + NB_BLKS, 256>>>(nidx, raw, w_n);
    // 2: F1 = feat(fp16) @ (WAh+WAl)
    hmma_gemm<<<dim3(PP / 64, 2), 256, G_SMEM>>>(pCAT, 48, pWAh, pWAl, 16,
                                                 pF1, 128, 0, nullptr);
    // 3: fused LB GEMM + gather + softmax + pool -> CAT[128:384]  (ncu target)
    lb_fused_kernel<<<592, 256, LQ_TOT>>>(feature);
    // 4: out = lrelu(CAT @ (WSOh+WSOl) + t_so)
    hmma_gemm<<<dim3(PP / 64, 2), 256, G_SMEM>>>(pCAT, 48, pWSOh, pWSOl, 48,
                                                 out, 384, 3, pFold + 2 * 256);
}

// round 14
// speedup vs baseline: 3.2097x; 1.1206x over previous
#include <cuda_runtime.h>
#include <cuda_fp16.h>
#include <cstdint>

// Problem constants (fixed instance)
#define BB   4
#define NN   8192
#define KK   16
#define CG   10
#define PP   32768
#define RR   524288
#define NTILES 4096

// ---------------------------------------------------------------------------
// Scratch. Activations AND weights: single fp16 (1-pass mma).
// ---------------------------------------------------------------------------
__device__ float  d_F1[(size_t)PP * 256];        // feat @ w_attn_top (fp32)
__device__ __half d_NB[(size_t)RR * 128];        // neigh (fp16)
__device__ __half d_CAT[(size_t)PP * 384];       // [feat | PL] (fp16)
__device__ __half d_WA[256 * 128];               // w_attn_top^T
__device__ __half d_Wt[256 * 128];               // w_attn_bot^T
__device__ __half d_WSO[256 * 384];              // [w_s*s_s ; w_o*s_o]^T
__device__ int    d_GI[RR];
__device__ int    d_idx64;
__device__ float  d_fold[3][256];   // 0=s_n 1=t_n 2=t_so

__device__ __forceinline__ float lrelu(float x) { return fmaxf(x, 0.2f * x); }

__device__ __forceinline__ uint32_t smem_u32(const void* p) {
    uint32_t a;
    asm("{ .reg .u64 t; cvta.to.shared.u64 t, %1; cvt.u32.u64 %0, t; }" : "=r"(a) : "l"(p));
    return a;
}
__device__ __forceinline__ void ldsm_x4(uint32_t& r0, uint32_t& r1, uint32_t& r2,
                                        uint32_t& r3, uint32_t addr) {
    asm volatile("ldmatrix.sync.aligned.m8n8.x4.shared.b16 {%0,%1,%2,%3}, [%4];"
                 : "=r"(r0), "=r"(r1), "=r"(r2), "=r"(r3) : "r"(addr));
}
#define CP16(dst, src)  asm volatile("cp.async.cg.shared.global [%0], [%1], 16;" :: "r"(dst), "l"(src))
#define CP_COMMIT()     asm volatile("cp.async.commit_group;" ::: "memory")
#define CP_WAIT(n)      asm volatile("cp.async.wait_group %0;" :: "n"(n) : "memory")
#define MMAF16(acc, a, b)                                                     \
    asm volatile("mma.sync.aligned.m16n8k16.row.col.f32.f16.f16.f32 "         \
                 "{%0,%1,%2,%3}, {%4,%5,%6,%7}, {%8,%9}, {%0,%1,%2,%3};"      \
                 : "+f"((acc)[0]), "+f"((acc)[1]), "+f"((acc)[2]), "+f"((acc)[3]) \
                 : "r"((a)[0]), "r"((a)[1]), "r"((a)[2]), "r"((a)[3]),        \
                   "r"((b)[0]), "r"((b)[1]))

// ---------------------------------------------------------------------------
// Launch 0: mega prep. b0: fold, b1: idx-detect, b2..641: weight transposes,
// b642..: feature -> CAT cols 0-127 (fp16, grid-stride).
// ---------------------------------------------------------------------------
#define PREP_FEAT_BLKS 1184
__global__ void prep_mega_kernel(
    const float* __restrict__ w_attn, const float* __restrict__ w_s,
    const float* __restrict__ w_o, const float* __restrict__ feat,
    const float* __restrict__ bn_, const float* __restrict__ gn,
    const float* __restrict__ betan, const float* __restrict__ rmn, const float* __restrict__ rvn,
    const float* __restrict__ bo, const float* __restrict__ go,
    const float* __restrict__ betao, const float* __restrict__ rmo, const float* __restrict__ rvo,
    const float* __restrict__ bs, const float* __restrict__ gs,
    const float* __restrict__ betas, const float* __restrict__ rms, const float* __restrict__ rvs,
    const int* __restrict__ widx)
{
    const int b = blockIdx.x, t = threadIdx.x;
    if (b == 0) {
        int i = t;
        if (i < 128) {
            float s = gn[i] * rsqrtf(rvn[i] + 1e-5f);
            d_fold[0][i] = s;
            d_fold[1][i] = (bn_[i] - rmn[i]) * s + betan[i];
        }
        if (i < 256) {
            float so = go[i] * rsqrtf(rvo[i] + 1e-5f);
            float ss = gs[i] * rsqrtf(rvs[i] + 1e-5f);
            d_fold[2][i] = (bo[i] - rmo[i]) * so + betao[i]
                         + (bs[i] - rms[i]) * ss + betas[i];
        }
        return;
    }
    if (b == 1) {
        __shared__ int ok;
        if (t == 0) ok = 1;
        __syncthreads();
        for (int i = t; i < 2048; i += blockDim.x)
            if (widx[2 * i + 1] != 0) ok = 0;
        __syncthreads();
        if (t == 0) d_idx64 = ok;
        return;
    }
    if (b < 130) {               // WA^T: w_attn rows 0-127
        int i = (b - 2) * 256 + t;
        int n = i >> 7, k = i & 127;
        d_WA[i] = __float2half(w_attn[(size_t)k * 256 + n]);
        return;
    }
    if (b < 258) {               // Wt^T: w_attn rows 128-255
        int i = (b - 130) * 256 + t;
        int n = i >> 7, k = i & 127;
        d_Wt[i] = __float2half(w_attn[(size_t)(128 + k) * 256 + n]);
        return;
    }
    if (b < 642) {               // WSO^T [256][384], BN scale folded
        int i = (b - 258) * 256 + t;
        int n = i / 384, k = i % 384;
        float v;
        if (k < 128) v = w_s[(size_t)k * 256 + n] * (gs[n] * rsqrtf(rvs[n] + 1e-5f));
        else         v = w_o[(size_t)(k - 128) * 256 + n] * (go[n] * rsqrtf(rvo[n] + 1e-5f));
        d_WSO[i] = __float2half(v);
        return;
    }
    // feature -> CAT cols 0-127 (fp16), grid-stride
    for (int i = (b - 642) * 256 + t; i < PP * 128; i += PREP_FEAT_BLKS * 256) {
        int m = i >> 7, k = i & 127;
        d_CAT[(size_t)m * 384 + k] = __float2half(feat[i]);
    }
}

// ---------------------------------------------------------------------------
// Launch 1: idx conversion (blocks 0..2047) + NB (grid-stride, fp16)
// ---------------------------------------------------------------------------
#define NB_BLKS 2368
__global__ void neighconv_kernel(const void* __restrict__ nidx,
                                 const float* __restrict__ raw,
                                 const float* __restrict__ wn_)
{
    const int b = blockIdx.x, t = threadIdx.x;
    if (b < 2048) {
        int r = b * 256 + t;
        long long v;
        if (d_idx64) v = ((const long long*)nidx)[r];
        else         v = (long long)((const int*)nidx)[r];
        int vi = (int)v;
        vi = min(max(vi, 0), NN - 1);
        int batch = r / (NN * KK);
        d_GI[r] = batch * NN + vi;
        return;
    }
    const int c = t & 127;
    const int rh = t >> 7;
    float wcol[CG];
#pragma unroll
    for (int g = 0; g < CG; g++) wcol[g] = wn_[g * 128 + c];
    const float sc = d_fold[0][c], tc = d_fold[1][c];

    for (int rp = b - 2048; rp < RR / 2; rp += NB_BLKS) {
        int r = rp * 2 + rh;
        const float* rr = raw + (size_t)r * CG;
        float acc = 0.f;
#pragma unroll
        for (int g = 0; g < CG; g++) acc += rr[g] * wcol[g];
        float v = lrelu(acc * sc + tc);
        d_NB[(size_t)r * 128 + c] = __float2half(v);
    }
}

// ---------------------------------------------------------------------------
// Generic HMMA GEMM (fp16 1-pass), BM=64, 3 CTAs/SM:
//   C[M,256] = A[M,Kd](fp16) @ W^T, W stored [256][Kd] fp16.
// smem: W 0 (34816) | A 34816 (17408) -> 52224 B
// warps 2(M) x 4(N), warp tile 32x32. mode 0: C=acc  mode 3: C=lrelu(acc+tv)
// ---------------------------------------------------------------------------
#define G_SMEM 52224
__global__ __launch_bounds__(256, 3)
void hmma_gemm(const __half* __restrict__ A, int sA,
               const __half* __restrict__ W, int sW,
               float* __restrict__ C, int Kd, int mode, const float* __restrict__ tv)
{
    extern __shared__ __align__(16) char sm[];
    const uint32_t sb = smem_u32(sm);
    const uint32_t aW = sb, aA = sb + 34816;

    const int tid = threadIdx.x;
    const int wid = tid >> 5, lane = tid & 31;
    const int wm = wid >> 2, wn = wid & 3;
    const int g = lane >> 2, tg = lane & 3;
    const int ri = lane & 7, mi = lane >> 3;
    const int m0 = blockIdx.x * 64;
    const int half = blockIdx.y;

    float acc[2][4][4];
#pragma unroll
    for (int i = 0; i < 2; i++)
#pragma unroll
        for (int j = 0; j < 4; j++)
#pragma unroll
            for (int c = 0; c < 4; c++) acc[i][j][c] = 0.f;

    const uint32_t aoff = (uint32_t)((wm * 32 + (mi & 1) * 8 + ri) * 272 + (mi >> 1) * 16);
    const uint32_t boff = (uint32_t)((wn * 32 + (mi >> 1) * 8 + ri) * 272 + (mi & 1) * 16);

    for (int kt = 0; kt < (Kd >> 7); kt++) {
        if (kt > 0) __syncthreads();
        for (int lin = tid; lin < 2048; lin += 256) {
            int row = lin >> 4, ch = lin & 15;
            uint32_t so = row * 272u + ch * 16u;
            size_t wi = (size_t)(half * 128 + row) * sW + kt * 16 + ch;
            CP16(aW + so, (const char*)W + wi * 16);
            if (lin < 1024) {
                size_t ai = (size_t)(m0 + row) * sA + kt * 16 + ch;
                CP16(aA + so, (const char*)A + ai * 16);
            }
        }
        CP_COMMIT();
        CP_WAIT(0);
        __syncthreads();
#pragma unroll
        for (int ks = 0; ks < 8; ks++) {
            const uint32_t k2 = ks * 32;
            uint32_t a[2][4], b[4][2];
            ldsm_x4(a[0][0], a[0][1], a[0][2], a[0][3], aA + aoff + k2);
            ldsm_x4(a[1][0], a[1][1], a[1][2], a[1][3], aA + aoff + 16 * 272 + k2);
            ldsm_x4(b[0][0], b[0][1], b[1][0], b[1][1], aW + boff + k2);
            ldsm_x4(b[2][0], b[2][1], b[3][0], b[3][1], aW + boff + 16 * 272 + k2);
#pragma unroll
            for (int i = 0; i < 2; i++)
#pragma unroll
                for (int j = 0; j < 4; j++)
                    MMAF16(acc[i][j], a[i], b[j]);
        }
    }

#pragma unroll
    for (int i = 0; i < 2; i++) {
        const int row0 = m0 + wm * 32 + i * 16 + g;
#pragma unroll
        for (int j = 0; j < 4; j++) {
            const int col = half * 128 + wn * 32 + j * 8 + 2 * tg;
            float2 v0 = make_float2(acc[i][j][0], acc[i][j][1]);
            float2 v1 = make_float2(acc[i][j][2], acc[i][j][3]);
            if (mode == 3) {
                float t0 = tv[col], t1 = tv[col + 1];
                v0.x = lrelu(v0.x + t0); v0.y = lrelu(v0.y + t1);
                v1.x = lrelu(v1.x + t0); v1.y = lrelu(v1.y + t1);
            }
            *(float2*)(C + (size_t)row0 * 256 + col) = v0;
            *(float2*)(C + (size_t)(row0 + 8) * 256 + col) = v1;
        }
    }
}

// ---------------------------------------------------------------------------
// Fused LB GEMM (fp16 1-pass, B in REGISTERS) + softmax + pooling.
// grid = 592 (148 x 4 N-quarters), 256 threads, 2 CTAs/SM.
// smem (73728 B): W 0 (17408, startup only) | A 17408 (2 x 10240) |
//                 Ct 37888 (128x68 f32 = 34816) | sgi 72704 (2x512)
// Each warp holds its entire B slice (32 N x 128 K) in 64 regs.
// ---------------------------------------------------------------------------
#define LQ_W   0
#define LQ_A   17408
#define LQ_CT  37888
#define LQ_GI  72704
#define LQ_TOT 73728

__device__ __forceinline__ void load_a_chunk(uint32_t sb, int tile, int chunk,
                                             int buf, int tid)
{
    const char* nb = (const char*)d_NB + (size_t)tile * 32768 + chunk * 64;
    const uint32_t Ab = sb + LQ_A + buf * 10240u;
#pragma unroll
    for (int ii = 0; ii < 2; ii++) {
        int lin = tid + 256 * ii;             // 0..511
        int row = lin >> 2, c4 = lin & 3;
        CP16(Ab + row * 80u + c4 * 16u, nb + (size_t)row * 256 + c4 * 16);
    }
    CP_COMMIT();
}

__device__ __forceinline__ void mma_chunk(uint32_t sb, int buf, int chunk,
                                          uint32_t aoff, const uint32_t (&bfr)[8][4][2],
                                          float (&acc)[2][4][4])
{
    const uint32_t Abase = sb + LQ_A + buf * 10240u;
#pragma unroll
    for (int ks = 0; ks < 2; ks++) {
        const int kstep = chunk * 2 + ks;
        uint32_t a[2][4];
        const uint32_t Aa = Abase + aoff + ks * 32;
        ldsm_x4(a[0][0], a[0][1], a[0][2], a[0][3], Aa);
        ldsm_x4(a[1][0], a[1][1], a[1][2], a[1][3], Aa + 16 * 80);
#pragma unroll
        for (int i = 0; i < 2; i++)
#pragma unroll
            for (int j = 0; j < 4; j++)
                MMAF16(acc[i][j], a[i], bfr[kstep][j]);
    }
}

__global__ __launch_bounds__(256, 2)
void lb_fused_kernel(const float* __restrict__ feat)
{
    extern __shared__ __align__(16) char sm[];
    const uint32_t sb = smem_u32(sm);
    float* Ct = (float*)(sm + LQ_CT);
    int* sgi = (int*)(sm + LQ_GI);

    const int tid = threadIdx.x;
    const int wid = tid >> 5, lane = tid & 31;
    const int wm = wid >> 1, wn = wid & 1;
    const int g = lane >> 2, tg = lane & 3;
    const int ri = lane & 7, mi = lane >> 3;
    const int q = blockIdx.x & 3;
    const int tile0 = blockIdx.x >> 2;

    // W quarter -> smem (startup), then into per-warp registers
    for (int lin = tid; lin < 1024; lin += 256) {
        int row = lin >> 4, ch = lin & 15;
        CP16(sb + LQ_W + row * 272u + ch * 16u,
             (const char*)d_Wt + ((size_t)(q * 64 + row) * 16 + ch) * 16);
    }
    CP_COMMIT();
    CP_WAIT(0);
    __syncthreads();

    uint32_t bfr[8][4][2];
    {
        const uint32_t boffB = (uint32_t)((wn * 32 + (mi >> 1) * 8 + ri) * 272 + (mi & 1) * 16);
#pragma unroll
        for (int ks = 0; ks < 8; ks++) {
            ldsm_x4(bfr[ks][0][0], bfr[ks][0][1], bfr[ks][1][0], bfr[ks][1][1],
                    sb + LQ_W + boffB + ks * 32);
            ldsm_x4(bfr[ks][2][0], bfr[ks][2][1], bfr[ks][3][0], bfr[ks][3][1],
                    sb + LQ_W + boffB + 16 * 272 + ks * 32);
        }
    }

    const uint32_t aoff = (uint32_t)((wm * 32 + (mi & 1) * 8 + ri) * 80 + (mi >> 1) * 16);

    load_a_chunk(sb, tile0, 0, 0, tid);
    load_a_chunk(sb, tile0, 1, 1, tid);

    int it = 0;
    for (int tile = tile0; tile < NTILES; tile += 148, it++) {
        const int cur = it & 1;
        int* sg = sgi + cur * 128;
        if (tid < 128) sg[tid] = d_GI[tile * 128 + tid];
        __syncthreads();

        const char* F1c = (const char*)d_F1;
#pragma unroll
        for (int ii = 0; ii < 8; ii++) {
            int lin = tid + 256 * ii;
            int r = lin >> 4, c4 = lin & 15;
            int gi = sg[r];
            CP16(sb + LQ_CT + r * 272 + c4 * 16,
                 F1c + (size_t)gi * 1024 + q * 256 + c4 * 16);
        }
        CP_COMMIT();

        const int nt = (tile + 148 < NTILES) ? (tile + 148) : tile0;

        float acc[2][4][4];
#pragma unroll
        for (int i = 0; i < 2; i++)
#pragma unroll
            for (int j = 0; j < 4; j++)
#pragma unroll
                for (int c = 0; c < 4; c++) acc[i][j][c] = 0.f;

        CP_WAIT(2); __syncthreads();
        mma_chunk(sb, 0, 0, aoff, bfr, acc);
        __syncthreads();
        load_a_chunk(sb, tile, 2, 0, tid);

        CP_WAIT(2); __syncthreads();
        mma_chunk(sb, 1, 1, aoff, bfr, acc);
        __syncthreads();
        load_a_chunk(sb, tile, 3, 1, tid);

        CP_WAIT(1); __syncthreads();
        mma_chunk(sb, 0, 2, aoff, bfr, acc);
        __syncthreads();
        load_a_chunk(sb, nt, 0, 0, tid);

        CP_WAIT(1); __syncthreads();
        mma_chunk(sb, 1, 3, aoff, bfr, acc);
        __syncthreads();
        load_a_chunk(sb, nt, 1, 1, tid);

        // epilogue: Ct += acc (Ct holds gathered F1)
#pragma unroll
        for (int i = 0; i < 2; i++) {
            const int r0 = wm * 32 + i * 16 + g;
#pragma unroll
            for (int j = 0; j < 4; j++) {
                const int c = wn * 32 + j * 8 + 2 * tg;
                float2* p0 = (float2*)(Ct + r0 * 68 + c);
                float2* p1 = (float2*)(Ct + (r0 + 8) * 68 + c);
                float2 v0 = *p0, v1 = *p1;
                v0.x += acc[i][j][0]; v0.y += acc[i][j][1];
                v1.x += acc[i][j][2]; v1.y += acc[i][j][3];
                *p0 = v0; *p1 = v1;
            }
        }
        __syncthreads();

        // softmax over K per (point, col) + pool; sources from gmem (L2-hot)
#pragma unroll
        for (int s = 0; s < 2; s++) {
            const int pid = tid + 256 * s;
            const int pt = pid >> 6, lc = pid & 63;
            const float* ctp = Ct + pt * 16 * 68 + lc;
            float l[KK];
#pragma unroll
            for (int k = 0; k < KK; k++) l[k] = ctp[k * 68];
            float m = l[0];
#pragma unroll
            for (int k = 1; k < KK; k++) m = fmaxf(m, l[k]);
            float sum = 0.f;
#pragma unroll
            for (int k = 0; k < KK; k++) { l[k] = __expf(l[k] - m); sum += l[k]; }
            float inv = __frcp_rn(sum);

            float pooled = 0.f;
            if (q < 2) {
                const int* gp = sg + pt * 16;
#pragma unroll
                for (int k = 0; k < KK; k++)
                    pooled += l[k] * __ldg(feat + (size_t)gp[k] * 128 + q * 64 + lc);
            } else {
                const size_t base = (size_t)(tile * 128 + pt * 16) * 128 + (q - 2) * 64 + lc;
#pragma unroll
                for (int k = 0; k < KK; k++)
                    pooled += l[k] * __half2float(d_NB[base + (size_t)k * 128]);
            }
            pooled *= inv;
            d_CAT[(size_t)(tile * 8 + pt) * 384 + 128 + q * 64 + lc] = __float2half(pooled);
        }
    }
}

// ---------------------------------------------------------------------------
// Launch
// ---------------------------------------------------------------------------
extern "C" void kernel_launch(void* const* d_in, const int* in_sizes, int n_in,
                              void* d_out, int out_size)
{
    const float* feature = (const float*)d_in[0];
    const float* raw     = (const float*)d_in[1];
    const void*  nidx    = d_in[2];
    const float* w_n     = (const float*)d_in[3];
    const float* b_n     = (const float*)d_in[4];
    const float* g_n     = (const float*)d_in[5];
    const float* beta_n  = (const float*)d_in[6];
    const float* rm_n    = (const float*)d_in[7];
    const float* rv_n    = (const float*)d_in[8];
    const float* w_attn  = (const float*)d_in[9];
    const float* w_o     = (const float*)d_in[10];
    const float* b_o     = (const float*)d_in[11];
    const float* g_o     = (const float*)d_in[12];
    const float* beta_o  = (const float*)d_in[13];
    const float* rm_o    = (const float*)d_in[14];
    const float* rv_o    = (const float*)d_in[15];
    const float* w_s     = (const float*)d_in[16];
    const float* b_s     = (const float*)d_in[17];
    const float* g_s     = (const float*)d_in[18];
    const float* beta_s  = (const float*)d_in[19];
    const float* rm_s    = (const float*)d_in[20];
    const float* rv_s    = (const float*)d_in[21];
    float* out = (float*)d_out;

    float *pF1, *pFold;
    __half *pCAT, *pWA, *pWSO;
    cudaGetSymbolAddress((void**)&pF1, d_F1);
    cudaGetSymbolAddress((void**)&pFold, d_fold);
    cudaGetSymbolAddress((void**)&pCAT, d_CAT);
    cudaGetSymbolAddress((void**)&pWA, d_WA);
    cudaGetSymbolAddress((void**)&pWSO, d_WSO);

    cudaFuncSetAttribute(hmma_gemm, cudaFuncAttributeMaxDynamicSharedMemorySize, G_SMEM);
    cudaFuncSetAttribute(lb_fused_kernel, cudaFuncAttributeMaxDynamicSharedMemorySize, LQ_TOT);

    // 0: prep (fold + detect + weight transposes + feature -> CAT fp16)
    prep_mega_kernel<<<642 + PREP_FEAT_BLKS, 256>>>(
        w_attn, w_s, w_o, feature,
        b_n, g_n, beta_n, rm_n, rv_n,
        b_o, g_o, beta_o, rm_o, rv_o,
        b_s, g_s, beta_s, rm_s, rv_s, (const int*)nidx);
    // 1: idx conversion + NB (grid-stride, fp16)
    neighconv_kernel<<<2048 + NB_BLKS, 256>>>(nidx, raw, w_n);
    // 2: F1 = feat(fp16) @ WA
    hmma_gemm<<<dim3(PP / 64, 2), 256, G_SMEM>>>(pCAT, 48, pWA, 16,
                                                 pF1, 128, 0, nullptr);
    // 3: fused LB GEMM + gather + softmax + pool -> CAT[128:384]  (ncu target)
    lb_fused_kernel<<<592, 256, LQ_TOT>>>(feature);
    // 4: out = lrelu(CAT @ WSO + t_so)
    hmma_gemm<<<dim3(PP / 64, 2), 256, G_SMEM>>>(pCAT, 48, pWSO, 48,
                                                 out, 384, 3, pFold + 2 * 256);
}

// round 15
// speedup vs baseline: 3.3117x; 1.0318x over previous
#include <cuda_runtime.h>
#include <cuda_fp16.h>
#include <cstdint>

// Problem constants (fixed instance)
#define BB   4
#define NN   8192
#define KK   16
#define CG   10
#define PP   32768
#define RR   524288
#define NTILES 4096

// ---------------------------------------------------------------------------
// Scratch. Activations AND weights: single fp16 (1-pass mma).
// ---------------------------------------------------------------------------
__device__ float  d_F1[(size_t)PP * 256];        // feat @ w_attn_top (fp32)
__device__ __half d_NB[(size_t)RR * 128];        // neigh (fp16)
__device__ __half d_CAT[(size_t)PP * 384];       // [feat | PL] (fp16)
__device__ __half d_WA[256 * 128];               // w_attn_top^T
__device__ __half d_Wt[256 * 128];               // w_attn_bot^T
__device__ __half d_WSO[256 * 384];              // [w_s*s_s ; w_o*s_o]^T
__device__ int    d_GI[RR];
__device__ int    d_idx64;
__device__ float  d_fold[3][256];   // 0=s_n 1=t_n 2=t_so

__device__ __forceinline__ float lrelu(float x) { return fmaxf(x, 0.2f * x); }

__device__ __forceinline__ uint32_t smem_u32(const void* p) {
    uint32_t a;
    asm("{ .reg .u64 t; cvta.to.shared.u64 t, %1; cvt.u32.u64 %0, t; }" : "=r"(a) : "l"(p));
    return a;
}
__device__ __forceinline__ void ldsm_x4(uint32_t& r0, uint32_t& r1, uint32_t& r2,
                                        uint32_t& r3, uint32_t addr) {
    asm volatile("ldmatrix.sync.aligned.m8n8.x4.shared.b16 {%0,%1,%2,%3}, [%4];"
                 : "=r"(r0), "=r"(r1), "=r"(r2), "=r"(r3) : "r"(addr));
}
#define CP16(dst, src)  asm volatile("cp.async.cg.shared.global [%0], [%1], 16;" :: "r"(dst), "l"(src))
#define CP_COMMIT()     asm volatile("cp.async.commit_group;" ::: "memory")
#define CP_WAIT(n)      asm volatile("cp.async.wait_group %0;" :: "n"(n) : "memory")
#define MMAF16(acc, a, b)                                                     \
    asm volatile("mma.sync.aligned.m16n8k16.row.col.f32.f16.f16.f32 "         \
                 "{%0,%1,%2,%3}, {%4,%5,%6,%7}, {%8,%9}, {%0,%1,%2,%3};"      \
                 : "+f"((acc)[0]), "+f"((acc)[1]), "+f"((acc)[2]), "+f"((acc)[3]) \
                 : "r"((a)[0]), "r"((a)[1]), "r"((a)[2]), "r"((a)[3]),        \
                   "r"((b)[0]), "r"((b)[1]))

// ---------------------------------------------------------------------------
// Launch 0: mega prep. b0: fold, b1: idx-detect, b2..641: weight transposes,
// b642..: feature -> CAT cols 0-127 (fp16, grid-stride).
// ---------------------------------------------------------------------------
#define PREP_FEAT_BLKS 1184
__global__ void prep_mega_kernel(
    const float* __restrict__ w_attn, const float* __restrict__ w_s,
    const float* __restrict__ w_o, const float* __restrict__ feat,
    const float* __restrict__ bn_, const float* __restrict__ gn,
    const float* __restrict__ betan, const float* __restrict__ rmn, const float* __restrict__ rvn,
    const float* __restrict__ bo, const float* __restrict__ go,
    const float* __restrict__ betao, const float* __restrict__ rmo, const float* __restrict__ rvo,
    const float* __restrict__ bs, const float* __restrict__ gs,
    const float* __restrict__ betas, const float* __restrict__ rms, const float* __restrict__ rvs,
    const int* __restrict__ widx)
{
    const int b = blockIdx.x, t = threadIdx.x;
    if (b == 0) {
        int i = t;
        if (i < 128) {
            float s = gn[i] * rsqrtf(rvn[i] + 1e-5f);
            d_fold[0][i] = s;
            d_fold[1][i] = (bn_[i] - rmn[i]) * s + betan[i];
        }
        if (i < 256) {
            float so = go[i] * rsqrtf(rvo[i] + 1e-5f);
            float ss = gs[i] * rsqrtf(rvs[i] + 1e-5f);
            d_fold[2][i] = (bo[i] - rmo[i]) * so + betao[i]
                         + (bs[i] - rms[i]) * ss + betas[i];
        }
        return;
    }
    if (b == 1) {
        __shared__ int ok;
        if (t == 0) ok = 1;
        __syncthreads();
        for (int i = t; i < 2048; i += blockDim.x)
            if (widx[2 * i + 1] != 0) ok = 0;
        __syncthreads();
        if (t == 0) d_idx64 = ok;
        return;
    }
    if (b < 130) {               // WA^T: w_attn rows 0-127
        int i = (b - 2) * 256 + t;
        int n = i >> 7, k = i & 127;
        d_WA[i] = __float2half(w_attn[(size_t)k * 256 + n]);
        return;
    }
    if (b < 258) {               // Wt^T: w_attn rows 128-255
        int i = (b - 130) * 256 + t;
        int n = i >> 7, k = i & 127;
        d_Wt[i] = __float2half(w_attn[(size_t)(128 + k) * 256 + n]);
        return;
    }
    if (b < 642) {               // WSO^T [256][384], BN scale folded
        int i = (b - 258) * 256 + t;
        int n = i / 384, k = i % 384;
        float v;
        if (k < 128) v = w_s[(size_t)k * 256 + n] * (gs[n] * rsqrtf(rvs[n] + 1e-5f));
        else         v = w_o[(size_t)(k - 128) * 256 + n] * (go[n] * rsqrtf(rvo[n] + 1e-5f));
        d_WSO[i] = __float2half(v);
        return;
    }
    // feature -> CAT cols 0-127 (fp16), grid-stride
    for (int i = (b - 642) * 256 + t; i < PP * 128; i += PREP_FEAT_BLKS * 256) {
        int m = i >> 7, k = i & 127;
        d_CAT[(size_t)m * 384 + k] = __float2half(feat[i]);
    }
}

// ---------------------------------------------------------------------------
// Launch 1: idx conversion (blocks 0..2047) + NB (grid-stride, fp16)
// ---------------------------------------------------------------------------
#define NB_BLKS 2368
__global__ void neighconv_kernel(const void* __restrict__ nidx,
                                 const float* __restrict__ raw,
                                 const float* __restrict__ wn_)
{
    const int b = blockIdx.x, t = threadIdx.x;
    if (b < 2048) {
        int r = b * 256 + t;
        long long v;
        if (d_idx64) v = ((const long long*)nidx)[r];
        else         v = (long long)((const int*)nidx)[r];
        int vi = (int)v;
        vi = min(max(vi, 0), NN - 1);
        int batch = r / (NN * KK);
        d_GI[r] = batch * NN + vi;
        return;
    }
    const int c = t & 127;
    const int rh = t >> 7;
    float wcol[CG];
#pragma unroll
    for (int g = 0; g < CG; g++) wcol[g] = wn_[g * 128 + c];
    const float sc = d_fold[0][c], tc = d_fold[1][c];

    for (int rp = b - 2048; rp < RR / 2; rp += NB_BLKS) {
        int r = rp * 2 + rh;
        const float* rr = raw + (size_t)r * CG;
        float acc = 0.f;
#pragma unroll
        for (int g = 0; g < CG; g++) acc += rr[g] * wcol[g];
        float v = lrelu(acc * sc + tc);
        d_NB[(size_t)r * 128 + c] = __float2half(v);
    }
}

// ---------------------------------------------------------------------------
// Generic HMMA GEMM (fp16 1-pass), BM=64, 3 CTAs/SM (unchanged from R14)
// ---------------------------------------------------------------------------
#define G_SMEM 52224
__global__ __launch_bounds__(256, 3)
void hmma_gemm(const __half* __restrict__ A, int sA,
               const __half* __restrict__ W, int sW,
               float* __restrict__ C, int Kd, int mode, const float* __restrict__ tv)
{
    extern __shared__ __align__(16) char sm[];
    const uint32_t sb = smem_u32(sm);
    const uint32_t aW = sb, aA = sb + 34816;

    const int tid = threadIdx.x;
    const int wid = tid >> 5, lane = tid & 31;
    const int wm = wid >> 2, wn = wid & 3;
    const int g = lane >> 2, tg = lane & 3;
    const int ri = lane & 7, mi = lane >> 3;
    const int m0 = blockIdx.x * 64;
    const int half = blockIdx.y;

    float acc[2][4][4];
#pragma unroll
    for (int i = 0; i < 2; i++)
#pragma unroll
        for (int j = 0; j < 4; j++)
#pragma unroll
            for (int c = 0; c < 4; c++) acc[i][j][c] = 0.f;

    const uint32_t aoff = (uint32_t)((wm * 32 + (mi & 1) * 8 + ri) * 272 + (mi >> 1) * 16);
    const uint32_t boff = (uint32_t)((wn * 32 + (mi >> 1) * 8 + ri) * 272 + (mi & 1) * 16);

    for (int kt = 0; kt < (Kd >> 7); kt++) {
        if (kt > 0) __syncthreads();
        for (int lin = tid; lin < 2048; lin += 256) {
            int row = lin >> 4, ch = lin & 15;
            uint32_t so = row * 272u + ch * 16u;
            size_t wi = (size_t)(half * 128 + row) * sW + kt * 16 + ch;
            CP16(aW + so, (const char*)W + wi * 16);
            if (lin < 1024) {
                size_t ai = (size_t)(m0 + row) * sA + kt * 16 + ch;
                CP16(aA + so, (const char*)A + ai * 16);
            }
        }
        CP_COMMIT();
        CP_WAIT(0);
        __syncthreads();
#pragma unroll
        for (int ks = 0; ks < 8; ks++) {
            const uint32_t k2 = ks * 32;
            uint32_t a[2][4], b[4][2];
            ldsm_x4(a[0][0], a[0][1], a[0][2], a[0][3], aA + aoff + k2);
            ldsm_x4(a[1][0], a[1][1], a[1][2], a[1][3], aA + aoff + 16 * 272 + k2);
            ldsm_x4(b[0][0], b[0][1], b[1][0], b[1][1], aW + boff + k2);
            ldsm_x4(b[2][0], b[2][1], b[3][0], b[3][1], aW + boff + 16 * 272 + k2);
#pragma unroll
            for (int i = 0; i < 2; i++)
#pragma unroll
                for (int j = 0; j < 4; j++)
                    MMAF16(acc[i][j], a[i], b[j]);
        }
    }

#pragma unroll
    for (int i = 0; i < 2; i++) {
        const int row0 = m0 + wm * 32 + i * 16 + g;
#pragma unroll
        for (int j = 0; j < 4; j++) {
            const int col = half * 128 + wn * 32 + j * 8 + 2 * tg;
            float2 v0 = make_float2(acc[i][j][0], acc[i][j][1]);
            float2 v1 = make_float2(acc[i][j][2], acc[i][j][3]);
            if (mode == 3) {
                float t0 = tv[col], t1 = tv[col + 1];
                v0.x = lrelu(v0.x + t0); v0.y = lrelu(v0.y + t1);
                v1.x = lrelu(v1.x + t0); v1.y = lrelu(v1.y + t1);
            }
            *(float2*)(C + (size_t)row0 * 256 + col) = v0;
            *(float2*)(C + (size_t)(row0 + 8) * 256 + col) = v1;
        }
    }
}

// ---------------------------------------------------------------------------
// Fused LB GEMM (fp16 1-pass, B in registers, whole-tile double-buffered A)
// + softmax + pooling. grid = 592 (148 x 4 N-quarters), 256 thr, 2 CTAs/SM.
// smem (105472 B): Ct 0 (34816; W staged here at startup, 17408) |
//                  A 34816 (2 x 34816, stride 272) | sgi 104448 (2x512)
// Per tile: ONE A cp group + ONE F1 group; 4 syncs; pool reads NB from the
// current A buffer (prefetch goes to the other buffer).
// ---------------------------------------------------------------------------
#define LQ_CT  0
#define LQ_A   34816
#define LQ_GI  104448
#define LQ_TOT 105472

__device__ __forceinline__ void load_a_full(uint32_t sb, int tile, int buf, int tid)
{
    const char* nb = (const char*)d_NB + (size_t)tile * 32768;
    const uint32_t Ab = sb + LQ_A + buf * 34816u;
#pragma unroll
    for (int ii = 0; ii < 8; ii++) {
        int lin = tid + 256 * ii;             // 0..2047
        int row = lin >> 4, ch = lin & 15;
        CP16(Ab + row * 272u + ch * 16u, nb + (size_t)row * 256 + ch * 16);
    }
    CP_COMMIT();
}

__global__ __launch_bounds__(256, 2)
void lb_fused_kernel(const float* __restrict__ feat)
{
    extern __shared__ __align__(16) char sm[];
    const uint32_t sb = smem_u32(sm);
    float* Ct = (float*)(sm + LQ_CT);
    int* sgi = (int*)(sm + LQ_GI);

    const int tid = threadIdx.x;
    const int wid = tid >> 5, lane = tid & 31;
    const int wm = wid >> 1, wn = wid & 1;
    const int g = lane >> 2, tg = lane & 3;
    const int ri = lane & 7, mi = lane >> 3;
    const int q = blockIdx.x & 3;
    const int tile0 = blockIdx.x >> 2;

    // W quarter -> Ct region (staging), then into per-warp registers
    for (int lin = tid; lin < 1024; lin += 256) {
        int row = lin >> 4, ch = lin & 15;
        CP16(sb + LQ_CT + row * 272u + ch * 16u,
             (const char*)d_Wt + ((size_t)(q * 64 + row) * 16 + ch) * 16);
    }
    CP_COMMIT();
    CP_WAIT(0);
    __syncthreads();

    uint32_t bfr[8][4][2];
    {
        const uint32_t boffB = (uint32_t)((wn * 32 + (mi >> 1) * 8 + ri) * 272 + (mi & 1) * 16);
#pragma unroll
        for (int ks = 0; ks < 8; ks++) {
            ldsm_x4(bfr[ks][0][0], bfr[ks][0][1], bfr[ks][1][0], bfr[ks][1][1],
                    sb + LQ_CT + boffB + ks * 32);
            ldsm_x4(bfr[ks][2][0], bfr[ks][2][1], bfr[ks][3][0], bfr[ks][3][1],
                    sb + LQ_CT + boffB + 16 * 272 + ks * 32);
        }
    }
    __syncthreads();   // W staging reads done before Ct reuse

    const uint32_t aoff = (uint32_t)((wm * 32 + (mi & 1) * 8 + ri) * 272 + (mi >> 1) * 16);

    load_a_full(sb, tile0, 0, tid);            // pending: {A0}

    int it = 0;
    for (int tile = tile0; tile < NTILES; tile += 148, it++) {
        const int cur = it & 1;
        int* sg = sgi + cur * 128;
        if (tid < 128) sg[tid] = d_GI[tile * 128 + tid];
        __syncthreads();                       // sg visible; prev pool done

        // F1 quarter gather -> Ct             pending: {A_cur, F1}
        const char* F1c = (const char*)d_F1;
#pragma unroll
        for (int ii = 0; ii < 8; ii++) {
            int lin = tid + 256 * ii;
            int r = lin >> 4, c4 = lin & 15;
            int gi = sg[r];
            CP16(sb + LQ_CT + r * 272 + c4 * 16,
                 F1c + (size_t)gi * 1024 + q * 256 + c4 * 16);
        }
        CP_COMMIT();

        // next tile's A into the other buffer pending: {A_cur, F1, A_next}
        const int nt = (tile + 148 < NTILES) ? (tile + 148) : tile0;
        load_a_full(sb, nt, cur ^ 1, tid);

        CP_WAIT(2);                            // A_cur done
        __syncthreads();

        // mma: all 8 k-steps from A buffer cur; B in registers
        float acc[2][4][4];
#pragma unroll
        for (int i = 0; i < 2; i++)
#pragma unroll
            for (int j = 0; j < 4; j++)
#pragma unroll
                for (int c = 0; c < 4; c++) acc[i][j][c] = 0.f;

        const uint32_t Abase = sb + LQ_A + cur * 34816u + aoff;
#pragma unroll
        for (int ks = 0; ks < 8; ks++) {
            uint32_t a[2][4];
            ldsm_x4(a[0][0], a[0][1], a[0][2], a[0][3], Abase + ks * 32);
            ldsm_x4(a[1][0], a[1][1], a[1][2], a[1][3], Abase + 16 * 272 + ks * 32);
#pragma unroll
            for (int i = 0; i < 2; i++)
#pragma unroll
                for (int j = 0; j < 4; j++)
                    MMAF16(acc[i][j], a[i], bfr[ks][j]);
        }

        CP_WAIT(1);                            // F1 done (A_next still flying)
        __syncthreads();

        // epilogue: Ct += acc (Ct holds gathered F1)
#pragma unroll
        for (int i = 0; i < 2; i++) {
            const int r0 = wm * 32 + i * 16 + g;
#pragma unroll
            for (int j = 0; j < 4; j++) {
                const int c = wn * 32 + j * 8 + 2 * tg;
                float2* p0 = (float2*)(Ct + r0 * 68 + c);
                float2* p1 = (float2*)(Ct + (r0 + 8) * 68 + c);
                float2 v0 = *p0, v1 = *p1;
                v0.x += acc[i][j][0]; v0.y += acc[i][j][1];
                v1.x += acc[i][j][2]; v1.y += acc[i][j][3];
                *p0 = v0; *p1 = v1;
            }
        }
        __syncthreads();                       // Ct complete

        // softmax over K per (point, col) + pool
        const __half* Acur = (const __half*)(sm + LQ_A + cur * 34816u);
#pragma unroll
        for (int s = 0; s < 2; s++) {
            const int pid = tid + 256 * s;
            const int pt = pid >> 6, lc = pid & 63;
            const float* ctp = Ct + pt * 16 * 68 + lc;
            float l[KK];
#pragma unroll
            for (int k = 0; k < KK; k++) l[k] = ctp[k * 68];
            float m = l[0];
#pragma unroll
            for (int k = 1; k < KK; k++) m = fmaxf(m, l[k]);
            float sum = 0.f;
#pragma unroll
            for (int k = 0; k < KK; k++) { l[k] = __expf(l[k] - m); sum += l[k]; }
            float inv = __frcp_rn(sum);

            float pooled = 0.f;
            if (q < 2) {
                const int* gp = sg + pt * 16;
#pragma unroll
                for (int k = 0; k < KK; k++)
                    pooled += l[k] * __ldg(feat + (size_t)gp[k] * 128 + q * 64 + lc);
            } else {
                // NB channels live in the current A buffer (stride 136 halves)
                const __half* ap = Acur + (size_t)(pt * 16) * 136 + (q - 2) * 64 + lc;
#pragma unroll
                for (int k = 0; k < KK; k++)
                    pooled += l[k] * __half2float(ap[k * 136]);
            }
            pooled *= inv;
            d_CAT[(size_t)(tile * 8 + pt) * 384 + 128 + q * 64 + lc] = __float2half(pooled);
        }
        // loop-top sync protects Ct / sg / A buffers
    }
}

// ---------------------------------------------------------------------------
// Launch
// ---------------------------------------------------------------------------
extern "C" void kernel_launch(void* const* d_in, const int* in_sizes, int n_in,
                              void* d_out, int out_size)
{
    const float* feature = (const float*)d_in[0];
    const float* raw     = (const float*)d_in[1];
    const void*  nidx    = d_in[2];
    const float* w_n     = (const float*)d_in[3];
    const float* b_n     = (const float*)d_in[4];
    const float* g_n     = (const float*)d_in[5];
    const float* beta_n  = (const float*)d_in[6];
    const float* rm_n    = (const float*)d_in[7];
    const float* rv_n    = (const float*)d_in[8];
    const float* w_attn  = (const float*)d_in[9];
    const float* w_o     = (const float*)d_in[10];
    const float* b_o     = (const float*)d_in[11];
    const float* g_o     = (const float*)d_in[12];
    const float* beta_o  = (const float*)d_in[13];
    const float* rm_o    = (const float*)d_in[14];
    const float* rv_o    = (const float*)d_in[15];
    const float* w_s     = (const float*)d_in[16];
    const float* b_s     = (const float*)d_in[17];
    const float* g_s     = (const float*)d_in[18];
    const float* beta_s  = (const float*)d_in[19];
    const float* rm_s    = (const float*)d_in[20];
    const float* rv_s    = (const float*)d_in[21];
    float* out = (float*)d_out;

    float *pF1, *pFold;
    __half *pCAT, *pWA, *pWSO;
    cudaGetSymbolAddress((void**)&pF1, d_F1);
    cudaGetSymbolAddress((void**)&pFold, d_fold);
    cudaGetSymbolAddress((void**)&pCAT, d_CAT);
    cudaGetSymbolAddress((void**)&pWA, d_WA);
    cudaGetSymbolAddress((void**)&pWSO, d_WSO);

    cudaFuncSetAttribute(hmma_gemm, cudaFuncAttributeMaxDynamicSharedMemorySize, G_SMEM);
    cudaFuncSetAttribute(lb_fused_kernel, cudaFuncAttributeMaxDynamicSharedMemorySize, LQ_TOT);

    // 0: prep (fold + detect + weight transposes + feature -> CAT fp16)
    prep_mega_kernel<<<642 + PREP_FEAT_BLKS, 256>>>(
        w_attn, w_s, w_o, feature,
        b_n, g_n, beta_n, rm_n, rv_n,
        b_o, g_o, beta_o, rm_o, rv_o,
        b_s, g_s, beta_s, rm_s, rv_s, (const int*)nidx);
    // 1: idx conversion + NB (grid-stride, fp16)
    neighconv_kernel<<<2048 + NB_BLKS, 256>>>(nidx, raw, w_n);
    // 2: F1 = feat(fp16) @ WA
    hmma_gemm<<<dim3(PP / 64, 2), 256, G_SMEM>>>(pCAT, 48, pWA, 16,
                                                 pF1, 128, 0, nullptr);
    // 3: fused LB GEMM + gather + softmax + pool -> CAT[128:384]  (ncu target)
    lb_fused_kernel<<<592, 256, LQ_TOT>>>(feature);
    // 4: out = lrelu(CAT @ WSO + t_so)
    hmma_gemm<<<dim3(PP / 64, 2), 256, G_SMEM>>>(pCAT, 48, pWSO, 48,
                                                 out, 384, 3, pFold + 2 * 256);
}